// round 1
// baseline (speedup 1.0000x reference)
#include <cuda_runtime.h>
#include <cuda_bf16.h>

// Problem constants
#define B_SZ   2
#define L_SZ   4096
#define DMODEL 1024
#define DINT   64
#define KW     32
#define SUBH   5
#define HEADS  14
#define ML     (B_SZ * L_SZ)          // 8192 rows
#define NQK    (SUBH * DINT)          // 320
#define NV     (HEADS * DINT)         // 896

// ---------------- scratch (static device globals; no allocation) -------------
__device__ float g_qp[ML * NQK];      // [b,l,s,i]   8192 x 320
__device__ float g_kp[ML * NQK];      // [b,l,s,i]
__device__ float g_vp[ML * NV];       // [b,l,h,i]   8192 x 896
__device__ float g_ao[ML * NV];       // attention output [b,l,h,i]

// ---------------- SGEMM: C[M,N] = A[M,K] * W + bias[N] ----------------------
// wseg == 1: W is stored as per-64-column segments, each [K,64] row-major
//            (matches Wq/Wk/Wv layout [head, K, 64])
// wseg == 0: W is plain row-major [K, N]
#define BM 128
#define BN 128
#define BK 8
#define TM 8
#define TN 8

__global__ __launch_bounds__(256)
void sgemm_bias(const float* __restrict__ A, const float* __restrict__ W,
                const float* __restrict__ bias, float* __restrict__ C,
                int M, int N, int K, int wseg)
{
    __shared__ float As[BK][BM];
    __shared__ float Bs[BK][BN];

    const int bm = blockIdx.y * BM;
    const int bn = blockIdx.x * BN;
    const int tid = threadIdx.x;

    // A tile loader: 128 rows x 8 cols, one float4 per thread
    const int arow  = tid >> 1;          // 0..127
    const int acol4 = (tid & 1) * 4;     // 0 or 4
    // B tile loader: 8 rows x 128 cols, one float4 per thread
    const int brow = tid >> 5;           // 0..7
    const int bcol = (tid & 31) * 4;     // 0..124

    const int tx = tid & 15;             // 0..15  (col group)
    const int ty = tid >> 4;             // 0..15  (row group)

    float acc[TM][TN];
    #pragma unroll
    for (int i = 0; i < TM; i++)
        #pragma unroll
        for (int j = 0; j < TN; j++) acc[i][j] = 0.f;

    float areg[TM], breg[TN];

    for (int k0 = 0; k0 < K; k0 += BK) {
        // ---- load A tile (M rows always in-bounds: M % 128 == 0) ----
        float4 av = *(const float4*)(A + (long)(bm + arow) * K + k0 + acol4);
        As[acol4 + 0][arow] = av.x;
        As[acol4 + 1][arow] = av.y;
        As[acol4 + 2][arow] = av.z;
        As[acol4 + 3][arow] = av.w;

        // ---- load B tile ----
        int gn = bn + bcol;
        float4 bv;
        if (gn < N) {
            const float* bp;
            if (wseg) bp = W + (long)(gn >> 6) * ((long)K * 64) + (long)(k0 + brow) * 64 + (gn & 63);
            else      bp = W + (long)(k0 + brow) * N + gn;
            bv = *(const float4*)bp;
        } else {
            bv = make_float4(0.f, 0.f, 0.f, 0.f);
        }
        *(float4*)(&Bs[brow][bcol]) = bv;

        __syncthreads();

        #pragma unroll
        for (int kk = 0; kk < BK; kk++) {
            #pragma unroll
            for (int i = 0; i < TM; i += 4) {
                float4 t = *(const float4*)(&As[kk][ty * TM + i]);
                areg[i + 0] = t.x; areg[i + 1] = t.y; areg[i + 2] = t.z; areg[i + 3] = t.w;
            }
            #pragma unroll
            for (int j = 0; j < TN; j += 4) {
                float4 t = *(const float4*)(&Bs[kk][tx * TN + j]);
                breg[j + 0] = t.x; breg[j + 1] = t.y; breg[j + 2] = t.z; breg[j + 3] = t.w;
            }
            #pragma unroll
            for (int i = 0; i < TM; i++)
                #pragma unroll
                for (int j = 0; j < TN; j++)
                    acc[i][j] += areg[i] * breg[j];
        }
        __syncthreads();
    }

    // ---- epilogue ----
    #pragma unroll
    for (int i = 0; i < TM; i++) {
        int row = bm + ty * TM + i;
        #pragma unroll
        for (int j = 0; j < TN; j++) {
            int col = bn + tx * TN + j;
            if (col < N)
                C[(long)row * N + col] = acc[i][j] + bias[col];
        }
    }
}

// ---------------- fused banded attention ------------------------------------
// grid: (L, B, H), block: 128 threads. One (h,b,l) per CTA.
__global__ __launch_bounds__(128)
void attn_kernel(const float* __restrict__ qp, const float* __restrict__ kp,
                 const float* __restrict__ vp, const float* __restrict__ Ws,
                 const float* __restrict__ bs, float* __restrict__ ao)
{
    const int l = blockIdx.x;
    const int b = blockIdx.y;
    const int h = blockIdx.z;

    int s, d;
    if (h < 5)       { s = 0; d = 1; }
    else if (h < 10) { s = 1; d = 1; }
    else if (h < 12) { s = 2; d = 2; }
    else if (h == 12){ s = 3; d = 4; }
    else             { s = 4; d = 8; }

    const int tid = threadIdx.x;
    __shared__ float qrow[64];
    __shared__ float sc[KW];
    __shared__ float attn[KW];
    __shared__ float red[128];

    const long base = (long)b * L_SZ + l;

    if (tid < 64) qrow[tid] = qp[base * NQK + s * 64 + tid];
    __syncthreads();

    // ---- banded scores: 4 threads per window position k ----
    {
        int k = tid >> 2;
        int part = tid & 3;
        int idx = l + (k - KW / 2) * d;
        idx = idx < 0 ? 0 : (idx > L_SZ - 1 ? L_SZ - 1 : idx);
        const float4* kr = (const float4*)(kp + ((long)b * L_SZ + idx) * NQK + s * 64 + part * 16);
        const float4* qr = (const float4*)(qrow + part * 16);
        float sum = 0.f;
        #pragma unroll
        for (int u = 0; u < 4; u++) {
            float4 kv = kr[u];
            float4 qv = qr[u];
            sum += qv.x * kv.x + qv.y * kv.y + qv.z * kv.z + qv.w * kv.w;
        }
        sum += __shfl_xor_sync(0xffffffffu, sum, 1);
        sum += __shfl_xor_sync(0xffffffffu, sum, 2);
        if (part == 0) sc[k] = sum * 0.125f;   // 1/sqrt(64)
    }
    __syncthreads();

    // ---- positional supersampling (Ws) + softmax: warp 0 ----
    if (tid < 32) {
        const int m = tid;
        float acc = bs[h * KW + m];
        const float* wsrow = Ws + (long)h * KW * KW + m;
        #pragma unroll 8
        for (int k = 0; k < KW; k++)
            acc += sc[k] * wsrow[k * KW];
        float mx = acc;
        #pragma unroll
        for (int o = 16; o; o >>= 1) mx = fmaxf(mx, __shfl_xor_sync(0xffffffffu, mx, o));
        float e = __expf(acc - mx);
        float ss = e;
        #pragma unroll
        for (int o = 16; o; o >>= 1) ss += __shfl_xor_sync(0xffffffffu, ss, o);
        attn[m] = e / ss;
    }
    __syncthreads();

    // ---- attn . V windows: 2 threads per output dim i ----
    {
        const int i = tid & 63;
        const int half = tid >> 6;
        float acc = 0.f;
        #pragma unroll 4
        for (int kk = 0; kk < 16; kk++) {
            int k = half * 16 + kk;
            int idx = l + (k - KW / 2) * d;
            idx = idx < 0 ? 0 : (idx > L_SZ - 1 ? L_SZ - 1 : idx);
            acc += attn[k] * vp[((long)b * L_SZ + idx) * NV + h * 64 + i];
        }
        red[tid] = acc;
    }
    __syncthreads();
    if (tid < 64)
        ao[base * NV + h * 64 + tid] = red[tid] + red[tid + 64];
}

// ---------------- launcher ---------------------------------------------------
extern "C" void kernel_launch(void* const* d_in, const int* in_sizes, int n_in,
                              void* d_out, int out_size)
{
    const float* query = (const float*)d_in[0];
    const float* key   = (const float*)d_in[1];
    const float* value = (const float*)d_in[2];
    const float* Wq    = (const float*)d_in[3];
    const float* bq    = (const float*)d_in[4];
    const float* Wk    = (const float*)d_in[5];
    const float* bk    = (const float*)d_in[6];
    const float* Wv    = (const float*)d_in[7];
    const float* bv    = (const float*)d_in[8];
    const float* Ws    = (const float*)d_in[9];
    const float* bs    = (const float*)d_in[10];
    const float* Wc    = (const float*)d_in[11];
    const float* bc    = (const float*)d_in[12];
    float* out = (float*)d_out;

    float *qp, *kp, *vp, *ao;
    cudaGetSymbolAddress((void**)&qp, g_qp);
    cudaGetSymbolAddress((void**)&kp, g_kp);
    cudaGetSymbolAddress((void**)&vp, g_vp);
    cudaGetSymbolAddress((void**)&ao, g_ao);

    const int mtiles = ML / BM;                 // 64

    // Q / K / V projections (segmented weights [head, K, 64])
    sgemm_bias<<<dim3((NQK + BN - 1) / BN, mtiles), 256>>>(query, Wq, bq, qp, ML, NQK, DMODEL, 1);
    sgemm_bias<<<dim3((NQK + BN - 1) / BN, mtiles), 256>>>(key,   Wk, bk, kp, ML, NQK, DMODEL, 1);
    sgemm_bias<<<dim3((NV  + BN - 1) / BN, mtiles), 256>>>(value, Wv, bv, vp, ML, NV,  DMODEL, 1);

    // fused banded attention
    attn_kernel<<<dim3(L_SZ, B_SZ, HEADS), 128>>>(qp, kp, vp, Ws, bs, ao);

    // output projection (plain row-major Wc [896,1024])
    sgemm_bias<<<dim3((DMODEL + BN - 1) / BN, mtiles), 256>>>(ao, Wc, bc, out, ML, DMODEL, NV, 0);
}

// round 3
// speedup vs baseline: 2.3273x; 2.3273x over previous
#include <cuda_runtime.h>
#include <cuda_bf16.h>
#include <cstdint>

// Problem constants
#define B_SZ   2
#define L_SZ   4096
#define DMODEL 1024
#define DINT   64
#define KW     32
#define SUBH   5
#define HEADS  14
#define ML     (B_SZ * L_SZ)          // 8192 rows
#define NQK    (SUBH * DINT)          // 320
#define NV     (HEADS * DINT)         // 896

// ---------------- scratch (static device globals; no allocation) -------------
__device__ float g_qp[ML * NQK];
__device__ float g_kp[ML * NQK];
__device__ float g_vp[ML * NV];
__device__ float g_ao[ML * NV];
__device__ __nv_bfloat16 g_ahi[ML * DMODEL];     // activation hi
__device__ __nv_bfloat16 g_alo[ML * DMODEL];     // activation lo
__device__ __nv_bfloat16 g_whi[DMODEL * DMODEL]; // weight (transposed [N,K]) hi
__device__ __nv_bfloat16 g_wlo[DMODEL * DMODEL]; // weight lo

// ---------------- helpers ------------------------------------------------
__device__ __forceinline__ uint32_t smem_u32(const void* p) {
    uint32_t a;
    asm("{ .reg .u64 t; cvta.to.shared.u64 t, %1; cvt.u32.u64 %0, t; }" : "=r"(a) : "l"(p));
    return a;
}
__device__ __forceinline__ void cpa16(uint32_t s, const void* g) {
    asm volatile("cp.async.cg.shared.global [%0], [%1], 16;" :: "r"(s), "l"(g));
}
#define CPA_COMMIT() asm volatile("cp.async.commit_group;" ::: "memory")
#define CPA_WAIT(n)  asm volatile("cp.async.wait_group %0;" :: "n"(n) : "memory")

#define LDSM4(r0, r1, r2, r3, a) \
    asm volatile("ldmatrix.sync.aligned.m8n8.x4.shared.b16 {%0,%1,%2,%3}, [%4];" \
        : "=r"(r0), "=r"(r1), "=r"(r2), "=r"(r3) : "r"(a))

#define MMA16816(c, a, b0, b1) \
    asm volatile("mma.sync.aligned.m16n8k16.row.col.f32.bf16.bf16.f32 " \
        "{%0,%1,%2,%3},{%4,%5,%6,%7},{%8,%9},{%0,%1,%2,%3};" \
        : "+f"((c)[0]), "+f"((c)[1]), "+f"((c)[2]), "+f"((c)[3]) \
        : "r"((a)[0]), "r"((a)[1]), "r"((a)[2]), "r"((a)[3]), "r"(b0), "r"(b1))

// ---------------- conversion kernels -----------------------------------------
__global__ __launch_bounds__(256)
void conv_act(const float4* __restrict__ in, uint2* __restrict__ hi, uint2* __restrict__ lo, int n4)
{
    int i = blockIdx.x * 256 + threadIdx.x;
    if (i >= n4) return;
    float4 v = in[i];
    __nv_bfloat16 hx = __float2bfloat16_rn(v.x);
    __nv_bfloat16 hy = __float2bfloat16_rn(v.y);
    __nv_bfloat16 hz = __float2bfloat16_rn(v.z);
    __nv_bfloat16 hw = __float2bfloat16_rn(v.w);
    __nv_bfloat16 lx = __float2bfloat16_rn(v.x - __bfloat162float(hx));
    __nv_bfloat16 ly = __float2bfloat16_rn(v.y - __bfloat162float(hy));
    __nv_bfloat16 lz = __float2bfloat16_rn(v.z - __bfloat162float(hz));
    __nv_bfloat16 lw = __float2bfloat16_rn(v.w - __bfloat162float(hw));
    __nv_bfloat162 h01, h23, l01, l23;
    h01.x = hx; h01.y = hy; h23.x = hz; h23.y = hw;
    l01.x = lx; l01.y = ly; l23.x = lz; l23.y = lw;
    uint2 ho, loo;
    ho.x = *(uint32_t*)&h01; ho.y = *(uint32_t*)&h23;
    loo.x = *(uint32_t*)&l01; loo.y = *(uint32_t*)&l23;
    hi[i] = ho; lo[i] = loo;
}

// W [heads, K, 64] -> Bt [N, K] bf16 hi/lo
__global__ __launch_bounds__(256)
void conv_w_seg(const float* __restrict__ W, __nv_bfloat16* __restrict__ bhi,
                __nv_bfloat16* __restrict__ blo, int K)
{
    int n = blockIdx.x;
    int head = n >> 6, i = n & 63;
    for (int k = threadIdx.x; k < K; k += 256) {
        float x = W[((size_t)head * K + k) * 64 + i];
        __nv_bfloat16 h = __float2bfloat16_rn(x);
        __nv_bfloat16 l = __float2bfloat16_rn(x - __bfloat162float(h));
        bhi[(size_t)n * K + k] = h;
        blo[(size_t)n * K + k] = l;
    }
}

// Wc [K, N] -> Bt [N, K] bf16 hi/lo (transpose)
__global__ __launch_bounds__(256)
void conv_w_t(const float* __restrict__ W, __nv_bfloat16* __restrict__ bhi,
              __nv_bfloat16* __restrict__ blo, int K, int Ntot)
{
    int n = blockIdx.x;
    for (int k = threadIdx.x; k < K; k += 256) {
        float x = W[(size_t)k * Ntot + n];
        __nv_bfloat16 h = __float2bfloat16_rn(x);
        __nv_bfloat16 l = __float2bfloat16_rn(x - __bfloat162float(h));
        bhi[(size_t)n * K + k] = h;
        blo[(size_t)n * K + k] = l;
    }
}

// ---------------- split-bf16 HMMA GEMM ---------------------------------------
// C[M,N] = (Ahi+Alo)(Bhi+Blo)^T + bias, dropping lo*lo.
// CTA tile 128x64, 8 warps of 32x32, K chunks of 32, cp.async double buffer.
#define APAD 40                 // smem row stride in bf16 elems (80B)
#define ST_ELEMS 15360          // elems per stage
#define AHI_OFF 0
#define ALO_OFF 5120
#define BHI_OFF 10240
#define BLO_OFF 12800
#define GEMM_SMEM (2 * ST_ELEMS * 2)  // 61440 bytes

__global__ __launch_bounds__(256)
void gemm_hmma(const __nv_bfloat16* __restrict__ Ahi, const __nv_bfloat16* __restrict__ Alo,
               const __nv_bfloat16* __restrict__ Bhi, const __nv_bfloat16* __restrict__ Blo,
               const float* __restrict__ bias, float* __restrict__ C, int N, int K)
{
    extern __shared__ __nv_bfloat16 sm[];
    const int tid = threadIdx.x, lane = tid & 31, wid = tid >> 5;
    const int wm = wid >> 1, wn = wid & 1;          // warp grid 4 x 2
    const int m0 = blockIdx.y * 128, n0 = blockIdx.x * 64;
    const uint32_t sb = smem_u32(sm);

    float c[2][4][4];
    #pragma unroll
    for (int i = 0; i < 2; i++)
        #pragma unroll
        for (int j = 0; j < 4; j++)
            #pragma unroll
            for (int q = 0; q < 4; q++) c[i][j][q] = 0.f;

    // loader indices
    const int a_row0 = tid >> 2;                    // + i*64
    const int a_col  = (tid & 3) * 8;
    const int b_row  = tid >> 2;                    // 0..63
    const int b_col  = (tid & 3) * 8;

    const int nit = K >> 5;

    // ---- prologue: stage 0 ----
    {
        uint32_t base = sb;
        #pragma unroll
        for (int i = 0; i < 2; i++) {
            int row = a_row0 + i * 64;
            uint32_t so = base + (uint32_t)(row * APAD + a_col) * 2;
            size_t go = (size_t)(m0 + row) * K + a_col;
            cpa16(so + AHI_OFF * 2, Ahi + go);
            cpa16(so + ALO_OFF * 2, Alo + go);
        }
        {
            uint32_t so = base + (uint32_t)(b_row * APAD + b_col) * 2;
            size_t go = (size_t)(n0 + b_row) * K + b_col;
            cpa16(so + BHI_OFF * 2, Bhi + go);
            cpa16(so + BLO_OFF * 2, Blo + go);
        }
        CPA_COMMIT();
    }

    const int r = lane & 7, g = lane >> 3;
    // ldmatrix lane-relative element offsets
    const int a_ld_row = (g & 1) * 8 + r;           // within 16-row tile
    const int a_ld_k   = (g >> 1) * 8;
    const int b_ld_row = (g >> 1) * 8 + r;
    const int b_ld_k   = (g & 1) * 8;

    for (int it = 0; it < nit; ++it) {
        if (it + 1 < nit) {
            uint32_t base = sb + (uint32_t)(((it + 1) & 1) * ST_ELEMS) * 2;
            int k0 = (it + 1) << 5;
            #pragma unroll
            for (int i = 0; i < 2; i++) {
                int row = a_row0 + i * 64;
                uint32_t so = base + (uint32_t)(row * APAD + a_col) * 2;
                size_t go = (size_t)(m0 + row) * K + k0 + a_col;
                cpa16(so + AHI_OFF * 2, Ahi + go);
                cpa16(so + ALO_OFF * 2, Alo + go);
            }
            {
                uint32_t so = base + (uint32_t)(b_row * APAD + b_col) * 2;
                size_t go = (size_t)(n0 + b_row) * K + k0 + b_col;
                cpa16(so + BHI_OFF * 2, Bhi + go);
                cpa16(so + BLO_OFF * 2, Blo + go);
            }
            CPA_COMMIT();
            CPA_WAIT(1);
        } else {
            CPA_WAIT(0);
        }
        __syncthreads();

        uint32_t base = sb + (uint32_t)((it & 1) * ST_ELEMS) * 2;
        #pragma unroll
        for (int kk = 0; kk < 32; kk += 16) {
            uint32_t ah[2][4], al[2][4], bh[2][4], bl[2][4];
            #pragma unroll
            for (int mt = 0; mt < 2; mt++) {
                uint32_t ad = base + (uint32_t)((wm * 32 + mt * 16 + a_ld_row) * APAD + kk + a_ld_k) * 2;
                LDSM4(ah[mt][0], ah[mt][1], ah[mt][2], ah[mt][3], ad + AHI_OFF * 2);
                LDSM4(al[mt][0], al[mt][1], al[mt][2], al[mt][3], ad + ALO_OFF * 2);
            }
            #pragma unroll
            for (int np = 0; np < 2; np++) {
                uint32_t bd = base + (uint32_t)((wn * 32 + np * 16 + b_ld_row) * APAD + kk + b_ld_k) * 2;
                LDSM4(bh[np][0], bh[np][1], bh[np][2], bh[np][3], bd + BHI_OFF * 2);
                LDSM4(bl[np][0], bl[np][1], bl[np][2], bl[np][3], bd + BLO_OFF * 2);
            }
            #pragma unroll
            for (int mt = 0; mt < 2; mt++)
                #pragma unroll
                for (int nt = 0; nt < 4; nt++) {
                    const int np = nt >> 1, o = (nt & 1) * 2;
                    MMA16816(c[mt][nt], ah[mt], bh[np][o], bh[np][o + 1]);
                    MMA16816(c[mt][nt], ah[mt], bl[np][o], bl[np][o + 1]);
                    MMA16816(c[mt][nt], al[mt], bh[np][o], bh[np][o + 1]);
                }
        }
        __syncthreads();
    }

    // ---- epilogue: direct stores + bias ----
    #pragma unroll
    for (int mt = 0; mt < 2; mt++) {
        int row = m0 + wm * 32 + mt * 16 + (lane >> 2);
        #pragma unroll
        for (int nt = 0; nt < 4; nt++) {
            int col = n0 + wn * 32 + nt * 8 + (lane & 3) * 2;
            float2 bv = *(const float2*)(bias + col);
            float2 v0, v1;
            v0.x = c[mt][nt][0] + bv.x; v0.y = c[mt][nt][1] + bv.y;
            v1.x = c[mt][nt][2] + bv.x; v1.y = c[mt][nt][3] + bv.y;
            *(float2*)(C + (size_t)row * N + col) = v0;
            *(float2*)(C + (size_t)(row + 8) * N + col) = v1;
        }
    }
}

// ---------------- fused banded attention (unchanged) -------------------------
__global__ __launch_bounds__(128)
void attn_kernel(const float* __restrict__ qp, const float* __restrict__ kp,
                 const float* __restrict__ vp, const float* __restrict__ Ws,
                 const float* __restrict__ bs, float* __restrict__ ao)
{
    const int l = blockIdx.x;
    const int b = blockIdx.y;
    const int h = blockIdx.z;

    int s, d;
    if (h < 5)       { s = 0; d = 1; }
    else if (h < 10) { s = 1; d = 1; }
    else if (h < 12) { s = 2; d = 2; }
    else if (h == 12){ s = 3; d = 4; }
    else             { s = 4; d = 8; }

    const int tid = threadIdx.x;
    __shared__ float qrow[64];
    __shared__ float sc[KW];
    __shared__ float attn[KW];
    __shared__ float red[128];

    const long base = (long)b * L_SZ + l;

    if (tid < 64) qrow[tid] = qp[base * NQK + s * 64 + tid];
    __syncthreads();

    {
        int k = tid >> 2;
        int part = tid & 3;
        int idx = l + (k - KW / 2) * d;
        idx = idx < 0 ? 0 : (idx > L_SZ - 1 ? L_SZ - 1 : idx);
        const float4* kr = (const float4*)(kp + ((long)b * L_SZ + idx) * NQK + s * 64 + part * 16);
        const float4* qr = (const float4*)(qrow + part * 16);
        float sum = 0.f;
        #pragma unroll
        for (int u = 0; u < 4; u++) {
            float4 kv = kr[u];
            float4 qv = qr[u];
            sum += qv.x * kv.x + qv.y * kv.y + qv.z * kv.z + qv.w * kv.w;
        }
        sum += __shfl_xor_sync(0xffffffffu, sum, 1);
        sum += __shfl_xor_sync(0xffffffffu, sum, 2);
        if (part == 0) sc[k] = sum * 0.125f;
    }
    __syncthreads();

    if (tid < 32) {
        const int m = tid;
        float acc = bs[h * KW + m];
        const float* wsrow = Ws + (long)h * KW * KW + m;
        #pragma unroll 8
        for (int k = 0; k < KW; k++)
            acc += sc[k] * wsrow[k * KW];
        float mx = acc;
        #pragma unroll
        for (int o = 16; o; o >>= 1) mx = fmaxf(mx, __shfl_xor_sync(0xffffffffu, mx, o));
        float e = __expf(acc - mx);
        float ss = e;
        #pragma unroll
        for (int o = 16; o; o >>= 1) ss += __shfl_xor_sync(0xffffffffu, ss, o);
        attn[m] = e / ss;
    }
    __syncthreads();

    {
        const int i = tid & 63;
        const int half = tid >> 6;
        float acc = 0.f;
        #pragma unroll 4
        for (int kk = 0; kk < 16; kk++) {
            int k = half * 16 + kk;
            int idx = l + (k - KW / 2) * d;
            idx = idx < 0 ? 0 : (idx > L_SZ - 1 ? L_SZ - 1 : idx);
            acc += attn[k] * vp[((long)b * L_SZ + idx) * NV + h * 64 + i];
        }
        red[tid] = acc;
    }
    __syncthreads();
    if (tid < 64)
        ao[base * NV + h * 64 + tid] = red[tid] + red[tid + 64];
}

// ---------------- launcher ---------------------------------------------------
extern "C" void kernel_launch(void* const* d_in, const int* in_sizes, int n_in,
                              void* d_out, int out_size)
{
    const float* query = (const float*)d_in[0];
    const float* key   = (const float*)d_in[1];
    const float* value = (const float*)d_in[2];
    const float* Wq    = (const float*)d_in[3];
    const float* bq    = (const float*)d_in[4];
    const float* Wk    = (const float*)d_in[5];
    const float* bk    = (const float*)d_in[6];
    const float* Wv    = (const float*)d_in[7];
    const float* bv    = (const float*)d_in[8];
    const float* Ws    = (const float*)d_in[9];
    const float* bs    = (const float*)d_in[10];
    const float* Wc    = (const float*)d_in[11];
    const float* bc    = (const float*)d_in[12];
    float* out = (float*)d_out;

    float *qp, *kp, *vp, *ao;
    __nv_bfloat16 *ahi, *alo, *whi, *wlo;
    cudaGetSymbolAddress((void**)&qp, g_qp);
    cudaGetSymbolAddress((void**)&kp, g_kp);
    cudaGetSymbolAddress((void**)&vp, g_vp);
    cudaGetSymbolAddress((void**)&ao, g_ao);
    cudaGetSymbolAddress((void**)&ahi, g_ahi);
    cudaGetSymbolAddress((void**)&alo, g_alo);
    cudaGetSymbolAddress((void**)&whi, g_whi);
    cudaGetSymbolAddress((void**)&wlo, g_wlo);

    cudaFuncSetAttribute(gemm_hmma, cudaFuncAttributeMaxDynamicSharedMemorySize, GEMM_SMEM);

    const int nact4 = ML * DMODEL / 4;

    // ---- Q projection ----
    conv_act<<<(nact4 + 255) / 256, 256>>>((const float4*)query, (uint2*)ahi, (uint2*)alo, nact4);
    conv_w_seg<<<NQK, 256>>>(Wq, whi, wlo, DMODEL);
    gemm_hmma<<<dim3(NQK / 64, ML / 128), 256, GEMM_SMEM>>>(ahi, alo, whi, wlo, bq, qp, NQK, DMODEL);

    // ---- K projection ----
    conv_act<<<(nact4 + 255) / 256, 256>>>((const float4*)key, (uint2*)ahi, (uint2*)alo, nact4);
    conv_w_seg<<<NQK, 256>>>(Wk, whi, wlo, DMODEL);
    gemm_hmma<<<dim3(NQK / 64, ML / 128), 256, GEMM_SMEM>>>(ahi, alo, whi, wlo, bk, kp, NQK, DMODEL);

    // ---- V projection ----
    conv_act<<<(nact4 + 255) / 256, 256>>>((const float4*)value, (uint2*)ahi, (uint2*)alo, nact4);
    conv_w_seg<<<NV, 256>>>(Wv, whi, wlo, DMODEL);
    gemm_hmma<<<dim3(NV / 64, ML / 128), 256, GEMM_SMEM>>>(ahi, alo, whi, wlo, bv, vp, NV, DMODEL);

    // ---- attention ----
    attn_kernel<<<dim3(L_SZ, B_SZ, HEADS), 128>>>(qp, kp, vp, Ws, bs, ao);

    // ---- output projection ----
    const int nao4 = ML * NV / 4;
    conv_act<<<(nao4 + 255) / 256, 256>>>((const float4*)ao, (uint2*)ahi, (uint2*)alo, nao4);
    conv_w_t<<<DMODEL, 256>>>(Wc, whi, wlo, NV, DMODEL);
    gemm_hmma<<<dim3(DMODEL / 64, ML / 128), 256, GEMM_SMEM>>>(ahi, alo, whi, wlo, bc, out, DMODEL, NV);
}

// round 4
// speedup vs baseline: 2.7848x; 1.1966x over previous
#include <cuda_runtime.h>
#include <cuda_bf16.h>
#include <cstdint>

// Problem constants
#define B_SZ   2
#define L_SZ   4096
#define DMODEL 1024
#define DINT   64
#define KW     32
#define SUBH   5
#define HEADS  14
#define ML     (B_SZ * L_SZ)          // 8192 rows
#define NQK    (SUBH * DINT)          // 320
#define NV     (HEADS * DINT)         // 896

// ---------------- scratch (static device globals; no allocation) -------------
__device__ float g_qp[ML * NQK];
__device__ float g_kp[ML * NQK];
__device__ float g_vp[ML * NV];
__device__ float g_ao[ML * NV];
__device__ __nv_bfloat16 g_ahi[ML * DMODEL];     // activation hi
__device__ __nv_bfloat16 g_alo[ML * DMODEL];     // activation lo
__device__ __nv_bfloat16 g_whi[DMODEL * DMODEL]; // weight (transposed [N,K]) hi
__device__ __nv_bfloat16 g_wlo[DMODEL * DMODEL]; // weight lo

// ---------------- helpers ------------------------------------------------
__device__ __forceinline__ uint32_t smem_u32(const void* p) {
    uint32_t a;
    asm("{ .reg .u64 t; cvta.to.shared.u64 t, %1; cvt.u32.u64 %0, t; }" : "=r"(a) : "l"(p));
    return a;
}
__device__ __forceinline__ void cpa16(uint32_t s, const void* g) {
    asm volatile("cp.async.cg.shared.global [%0], [%1], 16;" :: "r"(s), "l"(g));
}
#define CPA_COMMIT() asm volatile("cp.async.commit_group;" ::: "memory")
#define CPA_WAIT(n)  asm volatile("cp.async.wait_group %0;" :: "n"(n) : "memory")

#define LDSM4(r0, r1, r2, r3, a) \
    asm volatile("ldmatrix.sync.aligned.m8n8.x4.shared.b16 {%0,%1,%2,%3}, [%4];" \
        : "=r"(r0), "=r"(r1), "=r"(r2), "=r"(r3) : "r"(a))

#define MMA16816(c, a, b0, b1) \
    asm volatile("mma.sync.aligned.m16n8k16.row.col.f32.bf16.bf16.f32 " \
        "{%0,%1,%2,%3},{%4,%5,%6,%7},{%8,%9},{%0,%1,%2,%3};" \
        : "+f"((c)[0]), "+f"((c)[1]), "+f"((c)[2]), "+f"((c)[3]) \
        : "r"((a)[0]), "r"((a)[1]), "r"((a)[2]), "r"((a)[3]), "r"(b0), "r"(b1))

// ---------------- conversion kernels -----------------------------------------
__global__ __launch_bounds__(256)
void conv_act(const float4* __restrict__ in, uint2* __restrict__ hi, uint2* __restrict__ lo, int n4)
{
    int i = blockIdx.x * 256 + threadIdx.x;
    if (i >= n4) return;
    float4 v = in[i];
    __nv_bfloat16 hx = __float2bfloat16_rn(v.x);
    __nv_bfloat16 hy = __float2bfloat16_rn(v.y);
    __nv_bfloat16 hz = __float2bfloat16_rn(v.z);
    __nv_bfloat16 hw = __float2bfloat16_rn(v.w);
    __nv_bfloat16 lx = __float2bfloat16_rn(v.x - __bfloat162float(hx));
    __nv_bfloat16 ly = __float2bfloat16_rn(v.y - __bfloat162float(hy));
    __nv_bfloat16 lz = __float2bfloat16_rn(v.z - __bfloat162float(hz));
    __nv_bfloat16 lw = __float2bfloat16_rn(v.w - __bfloat162float(hw));
    __nv_bfloat162 h01, h23, l01, l23;
    h01.x = hx; h01.y = hy; h23.x = hz; h23.y = hw;
    l01.x = lx; l01.y = ly; l23.x = lz; l23.y = lw;
    uint2 ho, loo;
    ho.x = *(uint32_t*)&h01; ho.y = *(uint32_t*)&h23;
    loo.x = *(uint32_t*)&l01; loo.y = *(uint32_t*)&l23;
    hi[i] = ho; lo[i] = loo;
}

// W [heads, K, 64] -> Bt [N, K] bf16 hi/lo
__global__ __launch_bounds__(256)
void conv_w_seg(const float* __restrict__ W, __nv_bfloat16* __restrict__ bhi,
                __nv_bfloat16* __restrict__ blo, int K)
{
    int n = blockIdx.x;
    int head = n >> 6, i = n & 63;
    for (int k = threadIdx.x; k < K; k += 256) {
        float x = W[((size_t)head * K + k) * 64 + i];
        __nv_bfloat16 h = __float2bfloat16_rn(x);
        __nv_bfloat16 l = __float2bfloat16_rn(x - __bfloat162float(h));
        bhi[(size_t)n * K + k] = h;
        blo[(size_t)n * K + k] = l;
    }
}

// Wc [K, N] -> Bt [N, K] bf16 hi/lo (transpose)
__global__ __launch_bounds__(256)
void conv_w_t(const float* __restrict__ W, __nv_bfloat16* __restrict__ bhi,
              __nv_bfloat16* __restrict__ blo, int K, int Ntot)
{
    int n = blockIdx.x;
    for (int k = threadIdx.x; k < K; k += 256) {
        float x = W[(size_t)k * Ntot + n];
        __nv_bfloat16 h = __float2bfloat16_rn(x);
        __nv_bfloat16 l = __float2bfloat16_rn(x - __bfloat162float(h));
        bhi[(size_t)n * K + k] = h;
        blo[(size_t)n * K + k] = l;
    }
}

// ---------------- split-bf16 HMMA GEMM ---------------------------------------
#define APAD 40
#define ST_ELEMS 15360
#define AHI_OFF 0
#define ALO_OFF 5120
#define BHI_OFF 10240
#define BLO_OFF 12800
#define GEMM_SMEM (2 * ST_ELEMS * 2)

__global__ __launch_bounds__(256)
void gemm_hmma(const __nv_bfloat16* __restrict__ Ahi, const __nv_bfloat16* __restrict__ Alo,
               const __nv_bfloat16* __restrict__ Bhi, const __nv_bfloat16* __restrict__ Blo,
               const float* __restrict__ bias, float* __restrict__ C, int N, int K)
{
    extern __shared__ __nv_bfloat16 sm[];
    const int tid = threadIdx.x, lane = tid & 31, wid = tid >> 5;
    const int wm = wid >> 1, wn = wid & 1;
    const int m0 = blockIdx.y * 128, n0 = blockIdx.x * 64;
    const uint32_t sb = smem_u32(sm);

    float c[2][4][4];
    #pragma unroll
    for (int i = 0; i < 2; i++)
        #pragma unroll
        for (int j = 0; j < 4; j++)
            #pragma unroll
            for (int q = 0; q < 4; q++) c[i][j][q] = 0.f;

    const int a_row0 = tid >> 2;
    const int a_col  = (tid & 3) * 8;
    const int b_row  = tid >> 2;
    const int b_col  = (tid & 3) * 8;

    const int nit = K >> 5;

    {
        uint32_t base = sb;
        #pragma unroll
        for (int i = 0; i < 2; i++) {
            int row = a_row0 + i * 64;
            uint32_t so = base + (uint32_t)(row * APAD + a_col) * 2;
            size_t go = (size_t)(m0 + row) * K + a_col;
            cpa16(so + AHI_OFF * 2, Ahi + go);
            cpa16(so + ALO_OFF * 2, Alo + go);
        }
        {
            uint32_t so = base + (uint32_t)(b_row * APAD + b_col) * 2;
            size_t go = (size_t)(n0 + b_row) * K + b_col;
            cpa16(so + BHI_OFF * 2, Bhi + go);
            cpa16(so + BLO_OFF * 2, Blo + go);
        }
        CPA_COMMIT();
    }

    const int r = lane & 7, g = lane >> 3;
    const int a_ld_row = (g & 1) * 8 + r;
    const int a_ld_k   = (g >> 1) * 8;
    const int b_ld_row = (g >> 1) * 8 + r;
    const int b_ld_k   = (g & 1) * 8;

    for (int it = 0; it < nit; ++it) {
        if (it + 1 < nit) {
            uint32_t base = sb + (uint32_t)(((it + 1) & 1) * ST_ELEMS) * 2;
            int k0 = (it + 1) << 5;
            #pragma unroll
            for (int i = 0; i < 2; i++) {
                int row = a_row0 + i * 64;
                uint32_t so = base + (uint32_t)(row * APAD + a_col) * 2;
                size_t go = (size_t)(m0 + row) * K + k0 + a_col;
                cpa16(so + AHI_OFF * 2, Ahi + go);
                cpa16(so + ALO_OFF * 2, Alo + go);
            }
            {
                uint32_t so = base + (uint32_t)(b_row * APAD + b_col) * 2;
                size_t go = (size_t)(n0 + b_row) * K + k0 + b_col;
                cpa16(so + BHI_OFF * 2, Bhi + go);
                cpa16(so + BLO_OFF * 2, Blo + go);
            }
            CPA_COMMIT();
            CPA_WAIT(1);
        } else {
            CPA_WAIT(0);
        }
        __syncthreads();

        uint32_t base = sb + (uint32_t)((it & 1) * ST_ELEMS) * 2;
        #pragma unroll
        for (int kk = 0; kk < 32; kk += 16) {
            uint32_t ah[2][4], al[2][4], bh[2][4], bl[2][4];
            #pragma unroll
            for (int mt = 0; mt < 2; mt++) {
                uint32_t ad = base + (uint32_t)((wm * 32 + mt * 16 + a_ld_row) * APAD + kk + a_ld_k) * 2;
                LDSM4(ah[mt][0], ah[mt][1], ah[mt][2], ah[mt][3], ad + AHI_OFF * 2);
                LDSM4(al[mt][0], al[mt][1], al[mt][2], al[mt][3], ad + ALO_OFF * 2);
            }
            #pragma unroll
            for (int np = 0; np < 2; np++) {
                uint32_t bd = base + (uint32_t)((wn * 32 + np * 16 + b_ld_row) * APAD + kk + b_ld_k) * 2;
                LDSM4(bh[np][0], bh[np][1], bh[np][2], bh[np][3], bd + BHI_OFF * 2);
                LDSM4(bl[np][0], bl[np][1], bl[np][2], bl[np][3], bd + BLO_OFF * 2);
            }
            #pragma unroll
            for (int mt = 0; mt < 2; mt++)
                #pragma unroll
                for (int nt = 0; nt < 4; nt++) {
                    const int np = nt >> 1, o = (nt & 1) * 2;
                    MMA16816(c[mt][nt], ah[mt], bh[np][o], bh[np][o + 1]);
                    MMA16816(c[mt][nt], ah[mt], bl[np][o], bl[np][o + 1]);
                    MMA16816(c[mt][nt], al[mt], bh[np][o], bh[np][o + 1]);
                }
        }
        __syncthreads();
    }

    #pragma unroll
    for (int mt = 0; mt < 2; mt++) {
        int row = m0 + wm * 32 + mt * 16 + (lane >> 2);
        #pragma unroll
        for (int nt = 0; nt < 4; nt++) {
            int col = n0 + wn * 32 + nt * 8 + (lane & 3) * 2;
            float2 bv = *(const float2*)(bias + col);
            float2 v0, v1;
            v0.x = c[mt][nt][0] + bv.x; v0.y = c[mt][nt][1] + bv.y;
            v1.x = c[mt][nt][2] + bv.x; v1.y = c[mt][nt][3] + bv.y;
            *(float2*)(C + (size_t)row * N + col) = v0;
            *(float2*)(C + (size_t)(row + 8) * N + col) = v1;
        }
    }
}

// ---------------- tiled banded attention -------------------------------------
// One CTA = 32 consecutive l for one (h,b). Window union cached in SMEM,
// shared K/V buffer (sequential phases). Templated on dilation.
// smem layout (floats): win[WIN*64] | q[32*64] | ws[32*32] | sc[32*33]
//                       | sm2[32*33] | attnb[32*32] | bs[32]
#define ATTN_FIXED (2048 + 1024 + 1056 + 1056 + 1024 + 32)

template <int DIL>
__global__ __launch_bounds__(256)
void attn_tiled(const float* __restrict__ qp, const float* __restrict__ kp,
                const float* __restrict__ vp, const float* __restrict__ Ws,
                const float* __restrict__ bsg, float* __restrict__ ao, int h0)
{
    constexpr int WIN = 31 * DIL + 32;
    extern __shared__ float sa[];
    float* swin  = sa;
    float* sq    = swin + WIN * 64;
    float* sws   = sq + 2048;
    float* ssc   = sws + 1024;
    float* ssm   = ssc + 1056;
    float* satt  = ssm + 1056;
    float* sbs   = satt + 1024;

    const int l0 = blockIdx.x * 32;
    const int b  = blockIdx.y;
    const int h  = h0 + blockIdx.z;
    const int s  = (h < 5) ? 0 : (h < 10) ? 1 : (h < 12) ? 2 : (h == 12) ? 3 : 4;
    const int tid = threadIdx.x, lane = tid & 31;
    const int w0 = l0 - 16 * DIL;
    const long rowbase = (long)b * L_SZ + l0;

    // ---- load Q tile (32 x 64), Ws (32x32), bs ----
    {
        int idx = tid;                       // 512 float4 total, 2 per thread
        #pragma unroll
        for (int p = 0; p < 2; p++, idx += 256) {
            int row = idx >> 4, q4 = (idx & 15) * 4;
            *(float4*)(sq + row * 64 + q4) =
                *(const float4*)(qp + (rowbase + row) * NQK + s * 64 + q4);
        }
        *(float4*)(sws + tid * 4) = *(const float4*)(Ws + (size_t)h * 1024 + tid * 4);
        if (tid < 32) sbs[tid] = bsg[h * KW + tid];
    }
    // ---- load K window ----
    for (int r = tid >> 4; r < WIN; r += 16) {
        int g = w0 + r; g = g < 0 ? 0 : (g > L_SZ - 1 ? L_SZ - 1 : g);
        int q4 = (tid & 15) * 4;
        *(float4*)(swin + r * 64 + q4) =
            *(const float4*)(kp + ((long)b * L_SZ + g) * NQK + s * 64 + q4);
    }
    __syncthreads();

    // ---- scores: sc[li][k] = q[li] . win[li + k*DIL] / 8 ----
    {
        const int li = tid >> 3;
        const int kb = (tid & 7) * 4;
        float acc0 = 0.f, acc1 = 0.f, acc2 = 0.f, acc3 = 0.f;
        const float* qrow = sq + li * 64;
        const float* wr0 = swin + (li + (kb + 0) * DIL) * 64;
        const float* wr1 = swin + (li + (kb + 1) * DIL) * 64;
        const float* wr2 = swin + (li + (kb + 2) * DIL) * 64;
        const float* wr3 = swin + (li + (kb + 3) * DIL) * 64;
        #pragma unroll
        for (int t4 = 0; t4 < 16; t4++) {
            int i = ((t4 + lane) & 15) * 4;
            float4 qv = *(const float4*)(qrow + i);
            float4 v0 = *(const float4*)(wr0 + i);
            float4 v1 = *(const float4*)(wr1 + i);
            float4 v2 = *(const float4*)(wr2 + i);
            float4 v3 = *(const float4*)(wr3 + i);
            acc0 += qv.x * v0.x + qv.y * v0.y + qv.z * v0.z + qv.w * v0.w;
            acc1 += qv.x * v1.x + qv.y * v1.y + qv.z * v1.z + qv.w * v1.w;
            acc2 += qv.x * v2.x + qv.y * v2.y + qv.z * v2.z + qv.w * v2.w;
            acc3 += qv.x * v3.x + qv.y * v3.y + qv.z * v3.z + qv.w * v3.w;
        }
        ssc[li * 33 + kb + 0] = acc0 * 0.125f;
        ssc[li * 33 + kb + 1] = acc1 * 0.125f;
        ssc[li * 33 + kb + 2] = acc2 * 0.125f;
        ssc[li * 33 + kb + 3] = acc3 * 0.125f;
    }
    __syncthreads();

    // ---- load V window (reuse buffer; K reads done) ----
    for (int r = tid >> 4; r < WIN; r += 16) {
        int g = w0 + r; g = g < 0 ? 0 : (g > L_SZ - 1 ? L_SZ - 1 : g);
        int q4 = (tid & 15) * 4;
        *(float4*)(swin + r * 64 + q4) =
            *(const float4*)(vp + ((long)b * L_SZ + g) * NV + h * 64 + q4);
    }

    // ---- resample: sm2[li][m] = bs[m] + sum_k sc[li][k] * ws[k][m] ----
    {
        const int li = tid >> 3;
        const int m4 = (tid & 7) * 4;
        float a0 = sbs[m4], a1 = sbs[m4 + 1], a2 = sbs[m4 + 2], a3 = sbs[m4 + 3];
        #pragma unroll 8
        for (int k = 0; k < 32; k++) {
            float scv = ssc[li * 33 + k];
            float4 wv = *(const float4*)(sws + k * 32 + m4);
            a0 += scv * wv.x; a1 += scv * wv.y; a2 += scv * wv.z; a3 += scv * wv.w;
        }
        ssm[li * 33 + m4 + 0] = a0;
        ssm[li * 33 + m4 + 1] = a1;
        ssm[li * 33 + m4 + 2] = a2;
        ssm[li * 33 + m4 + 3] = a3;
    }
    __syncthreads();

    // ---- softmax per row: warp w handles rows 4w..4w+3 ----
    {
        const int w = tid >> 5;
        #pragma unroll
        for (int rr = 0; rr < 4; rr++) {
            int li = w * 4 + rr;
            float v = ssm[li * 33 + lane];
            float mx = v;
            #pragma unroll
            for (int o = 16; o; o >>= 1) mx = fmaxf(mx, __shfl_xor_sync(0xffffffffu, mx, o));
            float e = __expf(v - mx);
            float ss = e;
            #pragma unroll
            for (int o = 16; o; o >>= 1) ss += __shfl_xor_sync(0xffffffffu, ss, o);
            satt[li * 32 + lane] = e / ss;
        }
    }
    __syncthreads();

    // ---- attn . V windows ----
    {
        const int li = tid >> 3;
        const int io = (tid & 7) * 8;
        float4 a0 = make_float4(0.f, 0.f, 0.f, 0.f);
        float4 a1 = make_float4(0.f, 0.f, 0.f, 0.f);
        #pragma unroll 8
        for (int k = 0; k < 32; k++) {
            float wv = satt[li * 32 + k];
            const float* vr = swin + (li + k * DIL) * 64 + io;
            float4 v0 = *(const float4*)(vr);
            float4 v1 = *(const float4*)(vr + 4);
            a0.x += wv * v0.x; a0.y += wv * v0.y; a0.z += wv * v0.z; a0.w += wv * v0.w;
            a1.x += wv * v1.x; a1.y += wv * v1.y; a1.z += wv * v1.z; a1.w += wv * v1.w;
        }
        float* op = ao + (rowbase + li) * NV + h * 64 + io;
        *(float4*)op = a0;
        *(float4*)(op + 4) = a1;
    }
}

// ---------------- launcher ---------------------------------------------------
extern "C" void kernel_launch(void* const* d_in, const int* in_sizes, int n_in,
                              void* d_out, int out_size)
{
    const float* query = (const float*)d_in[0];
    const float* key   = (const float*)d_in[1];
    const float* value = (const float*)d_in[2];
    const float* Wq    = (const float*)d_in[3];
    const float* bq    = (const float*)d_in[4];
    const float* Wk    = (const float*)d_in[5];
    const float* bk    = (const float*)d_in[6];
    const float* Wv    = (const float*)d_in[7];
    const float* bv    = (const float*)d_in[8];
    const float* Ws    = (const float*)d_in[9];
    const float* bs    = (const float*)d_in[10];
    const float* Wc    = (const float*)d_in[11];
    const float* bc    = (const float*)d_in[12];
    float* out = (float*)d_out;

    float *qp, *kp, *vp, *ao;
    __nv_bfloat16 *ahi, *alo, *whi, *wlo;
    cudaGetSymbolAddress((void**)&qp, g_qp);
    cudaGetSymbolAddress((void**)&kp, g_kp);
    cudaGetSymbolAddress((void**)&vp, g_vp);
    cudaGetSymbolAddress((void**)&ao, g_ao);
    cudaGetSymbolAddress((void**)&ahi, g_ahi);
    cudaGetSymbolAddress((void**)&alo, g_alo);
    cudaGetSymbolAddress((void**)&whi, g_whi);
    cudaGetSymbolAddress((void**)&wlo, g_wlo);

    cudaFuncSetAttribute(gemm_hmma, cudaFuncAttributeMaxDynamicSharedMemorySize, GEMM_SMEM);

    auto asz = [](int dil) { return (size_t)((31 * dil + 32) * 64 + ATTN_FIXED) * 4; };
    cudaFuncSetAttribute(attn_tiled<1>, cudaFuncAttributeMaxDynamicSharedMemorySize, (int)asz(1));
    cudaFuncSetAttribute(attn_tiled<2>, cudaFuncAttributeMaxDynamicSharedMemorySize, (int)asz(2));
    cudaFuncSetAttribute(attn_tiled<4>, cudaFuncAttributeMaxDynamicSharedMemorySize, (int)asz(4));
    cudaFuncSetAttribute(attn_tiled<8>, cudaFuncAttributeMaxDynamicSharedMemorySize, (int)asz(8));

    const int nact4 = ML * DMODEL / 4;

    // ---- Q projection ----
    conv_act<<<(nact4 + 255) / 256, 256>>>((const float4*)query, (uint2*)ahi, (uint2*)alo, nact4);
    conv_w_seg<<<NQK, 256>>>(Wq, whi, wlo, DMODEL);
    gemm_hmma<<<dim3(NQK / 64, ML / 128), 256, GEMM_SMEM>>>(ahi, alo, whi, wlo, bq, qp, NQK, DMODEL);

    // ---- K projection ----
    conv_act<<<(nact4 + 255) / 256, 256>>>((const float4*)key, (uint2*)ahi, (uint2*)alo, nact4);
    conv_w_seg<<<NQK, 256>>>(Wk, whi, wlo, DMODEL);
    gemm_hmma<<<dim3(NQK / 64, ML / 128), 256, GEMM_SMEM>>>(ahi, alo, whi, wlo, bk, kp, NQK, DMODEL);

    // ---- V projection ----
    conv_act<<<(nact4 + 255) / 256, 256>>>((const float4*)value, (uint2*)ahi, (uint2*)alo, nact4);
    conv_w_seg<<<NV, 256>>>(Wv, whi, wlo, DMODEL);
    gemm_hmma<<<dim3(NV / 64, ML / 128), 256, GEMM_SMEM>>>(ahi, alo, whi, wlo, bv, vp, NV, DMODEL);

    // ---- tiled attention: heads grouped by dilation ----
    attn_tiled<1><<<dim3(L_SZ / 32, B_SZ, 10), 256, asz(1)>>>(qp, kp, vp, Ws, bs, ao, 0);
    attn_tiled<2><<<dim3(L_SZ / 32, B_SZ, 2),  256, asz(2)>>>(qp, kp, vp, Ws, bs, ao, 10);
    attn_tiled<4><<<dim3(L_SZ / 32, B_SZ, 1),  256, asz(4)>>>(qp, kp, vp, Ws, bs, ao, 12);
    attn_tiled<8><<<dim3(L_SZ / 32, B_SZ, 1),  256, asz(8)>>>(qp, kp, vp, Ws, bs, ao, 13);

    // ---- output projection ----
    const int nao4 = ML * NV / 4;
    conv_act<<<(nao4 + 255) / 256, 256>>>((const float4*)ao, (uint2*)ahi, (uint2*)alo, nao4);
    conv_w_t<<<DMODEL, 256>>>(Wc, whi, wlo, NV, DMODEL);
    gemm_hmma<<<dim3(DMODEL / 64, ML / 128), 256, GEMM_SMEM>>>(ahi, alo, whi, wlo, bc, out, DMODEL, NV);
}

// round 5
// speedup vs baseline: 2.8055x; 1.0074x over previous
#include <cuda_runtime.h>
#include <cuda_bf16.h>
#include <cstdint>

// Problem constants
#define B_SZ   2
#define L_SZ   4096
#define DMODEL 1024
#define DINT   64
#define KW     32
#define SUBH   5
#define HEADS  14
#define ML     (B_SZ * L_SZ)          // 8192 rows
#define NQK    (SUBH * DINT)          // 320
#define NV     (HEADS * DINT)         // 896

// ---------------- scratch (static device globals; no allocation) -------------
__device__ float g_qp[ML * NQK];
__device__ float g_kp[ML * NQK];
__device__ float g_vp[ML * NV];
__device__ float g_ao[ML * NV];
__device__ __nv_bfloat16 g_qahi[ML * DMODEL], g_qalo[ML * DMODEL];
__device__ __nv_bfloat16 g_kahi[ML * DMODEL], g_kalo[ML * DMODEL];
__device__ __nv_bfloat16 g_vahi[ML * DMODEL], g_valo[ML * DMODEL];
__device__ __nv_bfloat16 g_oahi[ML * NV],     g_oalo[ML * NV];
__device__ __nv_bfloat16 g_wqhi[NQK * DMODEL], g_wqlo[NQK * DMODEL];
__device__ __nv_bfloat16 g_wkhi[NQK * DMODEL], g_wklo[NQK * DMODEL];
__device__ __nv_bfloat16 g_wvhi[NV * DMODEL],  g_wvlo[NV * DMODEL];
__device__ __nv_bfloat16 g_wchi[DMODEL * NV],  g_wclo[DMODEL * NV];

// ---------------- helpers ------------------------------------------------
__device__ __forceinline__ uint32_t smem_u32(const void* p) {
    uint32_t a;
    asm("{ .reg .u64 t; cvta.to.shared.u64 t, %1; cvt.u32.u64 %0, t; }" : "=r"(a) : "l"(p));
    return a;
}
__device__ __forceinline__ void cpa16(uint32_t s, const void* g) {
    asm volatile("cp.async.cg.shared.global [%0], [%1], 16;" :: "r"(s), "l"(g));
}
#define CPA_COMMIT() asm volatile("cp.async.commit_group;" ::: "memory")
#define CPA_WAIT(n)  asm volatile("cp.async.wait_group %0;" :: "n"(n) : "memory")

#define LDSM4(r0, r1, r2, r3, a) \
    asm volatile("ldmatrix.sync.aligned.m8n8.x4.shared.b16 {%0,%1,%2,%3}, [%4];" \
        : "=r"(r0), "=r"(r1), "=r"(r2), "=r"(r3) : "r"(a))

#define MMA16816(c, a, b0, b1) \
    asm volatile("mma.sync.aligned.m16n8k16.row.col.f32.bf16.bf16.f32 " \
        "{%0,%1,%2,%3},{%4,%5,%6,%7},{%8,%9},{%0,%1,%2,%3};" \
        : "+f"((c)[0]), "+f"((c)[1]), "+f"((c)[2]), "+f"((c)[3]) \
        : "r"((a)[0]), "r"((a)[1]), "r"((a)[2]), "r"((a)[3]), "r"(b0), "r"(b1))

// ---------------- conversion kernels -----------------------------------------
__device__ __forceinline__ uint32_t pack_hi2(float a, float b, float& ra, float& rb) {
    __nv_bfloat162 h;
    h.x = __float2bfloat16_rn(a); h.y = __float2bfloat16_rn(b);
    ra = a - __bfloat162float(h.x); rb = b - __bfloat162float(h.y);
    return *(uint32_t*)&h;
}
__device__ __forceinline__ uint32_t pack2(float a, float b) {
    __nv_bfloat162 h;
    h.x = __float2bfloat16_rn(a); h.y = __float2bfloat16_rn(b);
    return *(uint32_t*)&h;
}

// fp32 -> bf16 hi/lo, 8 elems per thread
__global__ __launch_bounds__(256)
void conv_act(const float4* __restrict__ in, uint4* __restrict__ hi, uint4* __restrict__ lo, int n8)
{
    int i = blockIdx.x * 256 + threadIdx.x;
    if (i >= n8) return;
    float4 a = in[2 * i], b = in[2 * i + 1];
    float r0, r1, r2, r3, r4, r5, r6, r7;
    uint4 h, l;
    h.x = pack_hi2(a.x, a.y, r0, r1);
    h.y = pack_hi2(a.z, a.w, r2, r3);
    h.z = pack_hi2(b.x, b.y, r4, r5);
    h.w = pack_hi2(b.z, b.w, r6, r7);
    l.x = pack2(r0, r1); l.y = pack2(r2, r3);
    l.z = pack2(r4, r5); l.w = pack2(r6, r7);
    hi[i] = h; lo[i] = l;
}

// W [heads, K, 64] -> Bt [N, K] bf16 hi/lo
__global__ __launch_bounds__(256)
void conv_w_seg(const float* __restrict__ W, __nv_bfloat16* __restrict__ bhi,
                __nv_bfloat16* __restrict__ blo, int K)
{
    int n = blockIdx.x;
    int head = n >> 6, i = n & 63;
    for (int k = threadIdx.x; k < K; k += 256) {
        float x = W[((size_t)head * K + k) * 64 + i];
        __nv_bfloat16 h = __float2bfloat16_rn(x);
        __nv_bfloat16 l = __float2bfloat16_rn(x - __bfloat162float(h));
        bhi[(size_t)n * K + k] = h;
        blo[(size_t)n * K + k] = l;
    }
}

// Wc [K, N] -> Bt [N, K] bf16 hi/lo (transpose)
__global__ __launch_bounds__(256)
void conv_w_t(const float* __restrict__ W, __nv_bfloat16* __restrict__ bhi,
              __nv_bfloat16* __restrict__ blo, int K, int Ntot)
{
    int n = blockIdx.x;
    for (int k = threadIdx.x; k < K; k += 256) {
        float x = W[(size_t)k * Ntot + n];
        __nv_bfloat16 h = __float2bfloat16_rn(x);
        __nv_bfloat16 l = __float2bfloat16_rn(x - __bfloat162float(h));
        bhi[(size_t)n * K + k] = h;
        blo[(size_t)n * K + k] = l;
    }
}

// ---------------- split-bf16 HMMA GEMM core -----------------------------------
#define APAD 40
#define ST_ELEMS 15360
#define AHI_OFF 0
#define ALO_OFF 5120
#define BHI_OFF 10240
#define BLO_OFF 12800
#define GEMM_SMEM (2 * ST_ELEMS * 2)

struct GemmCtx {
    int a_row0, a_col, b_row, b_col;
    int a_ld_row, a_ld_k, b_ld_row, b_ld_k;
    int wm, wn, lane;
    uint32_t sb;
};

__device__ __forceinline__ void gemm_tile(
    const GemmCtx& cx,
    const __nv_bfloat16* __restrict__ Ahi, const __nv_bfloat16* __restrict__ Alo,
    const __nv_bfloat16* __restrict__ Bhi, const __nv_bfloat16* __restrict__ Blo,
    const float* __restrict__ bias, float* __restrict__ C,
    int m0, int n0, int N, int K)
{
    float c[2][4][4];
    #pragma unroll
    for (int i = 0; i < 2; i++)
        #pragma unroll
        for (int j = 0; j < 4; j++)
            #pragma unroll
            for (int q = 0; q < 4; q++) c[i][j][q] = 0.f;

    const int nit = K >> 5;

    // prologue
    {
        uint32_t base = cx.sb;
        #pragma unroll
        for (int i = 0; i < 2; i++) {
            int row = cx.a_row0 + i * 64;
            uint32_t so = base + (uint32_t)(row * APAD + cx.a_col) * 2;
            size_t go = (size_t)(m0 + row) * K + cx.a_col;
            cpa16(so + AHI_OFF * 2, Ahi + go);
            cpa16(so + ALO_OFF * 2, Alo + go);
        }
        {
            uint32_t so = base + (uint32_t)(cx.b_row * APAD + cx.b_col) * 2;
            size_t go = (size_t)(n0 + cx.b_row) * K + cx.b_col;
            cpa16(so + BHI_OFF * 2, Bhi + go);
            cpa16(so + BLO_OFF * 2, Blo + go);
        }
        CPA_COMMIT();
    }

    for (int it = 0; it < nit; ++it) {
        if (it + 1 < nit) {
            uint32_t base = cx.sb + (uint32_t)(((it + 1) & 1) * ST_ELEMS) * 2;
            int k0 = (it + 1) << 5;
            #pragma unroll
            for (int i = 0; i < 2; i++) {
                int row = cx.a_row0 + i * 64;
                uint32_t so = base + (uint32_t)(row * APAD + cx.a_col) * 2;
                size_t go = (size_t)(m0 + row) * K + k0 + cx.a_col;
                cpa16(so + AHI_OFF * 2, Ahi + go);
                cpa16(so + ALO_OFF * 2, Alo + go);
            }
            {
                uint32_t so = base + (uint32_t)(cx.b_row * APAD + cx.b_col) * 2;
                size_t go = (size_t)(n0 + cx.b_row) * K + k0 + cx.b_col;
                cpa16(so + BHI_OFF * 2, Bhi + go);
                cpa16(so + BLO_OFF * 2, Blo + go);
            }
            CPA_COMMIT();
            CPA_WAIT(1);
        } else {
            CPA_WAIT(0);
        }
        __syncthreads();

        uint32_t base = cx.sb + (uint32_t)((it & 1) * ST_ELEMS) * 2;
        #pragma unroll
        for (int kk = 0; kk < 32; kk += 16) {
            uint32_t ah[2][4], al[2][4], bh[2][4], bl[2][4];
            #pragma unroll
            for (int mt = 0; mt < 2; mt++) {
                uint32_t ad = base + (uint32_t)((cx.wm * 32 + mt * 16 + cx.a_ld_row) * APAD + kk + cx.a_ld_k) * 2;
                LDSM4(ah[mt][0], ah[mt][1], ah[mt][2], ah[mt][3], ad + AHI_OFF * 2);
                LDSM4(al[mt][0], al[mt][1], al[mt][2], al[mt][3], ad + ALO_OFF * 2);
            }
            #pragma unroll
            for (int np = 0; np < 2; np++) {
                uint32_t bd = base + (uint32_t)((cx.wn * 32 + np * 16 + cx.b_ld_row) * APAD + kk + cx.b_ld_k) * 2;
                LDSM4(bh[np][0], bh[np][1], bh[np][2], bh[np][3], bd + BHI_OFF * 2);
                LDSM4(bl[np][0], bl[np][1], bl[np][2], bl[np][3], bd + BLO_OFF * 2);
            }
            #pragma unroll
            for (int mt = 0; mt < 2; mt++)
                #pragma unroll
                for (int nt = 0; nt < 4; nt++) {
                    const int np = nt >> 1, o = (nt & 1) * 2;
                    MMA16816(c[mt][nt], ah[mt], bh[np][o], bh[np][o + 1]);
                    MMA16816(c[mt][nt], ah[mt], bl[np][o], bl[np][o + 1]);
                    MMA16816(c[mt][nt], al[mt], bh[np][o], bh[np][o + 1]);
                }
        }
        __syncthreads();
    }

    // epilogue
    #pragma unroll
    for (int mt = 0; mt < 2; mt++) {
        int row = m0 + cx.wm * 32 + mt * 16 + (cx.lane >> 2);
        #pragma unroll
        for (int nt = 0; nt < 4; nt++) {
            int col = n0 + cx.wn * 32 + nt * 8 + (cx.lane & 3) * 2;
            float2 bv = *(const float2*)(bias + col);
            float2 v0, v1;
            v0.x = c[mt][nt][0] + bv.x; v0.y = c[mt][nt][1] + bv.y;
            v1.x = c[mt][nt][2] + bv.x; v1.y = c[mt][nt][3] + bv.y;
            *(float2*)(C + (size_t)row * N + col) = v0;
            *(float2*)(C + (size_t)(row + 8) * N + col) = v1;
        }
    }
}

__device__ __forceinline__ GemmCtx make_ctx(uint32_t sb) {
    GemmCtx cx;
    const int tid = threadIdx.x, lane = tid & 31, wid = tid >> 5;
    cx.lane = lane; cx.wm = wid >> 1; cx.wn = wid & 1;
    cx.a_row0 = tid >> 2; cx.a_col = (tid & 3) * 8;
    cx.b_row = tid >> 2;  cx.b_col = (tid & 3) * 8;
    const int r = lane & 7, g = lane >> 3;
    cx.a_ld_row = (g & 1) * 8 + r; cx.a_ld_k = (g >> 1) * 8;
    cx.b_ld_row = (g >> 1) * 8 + r; cx.b_ld_k = (g & 1) * 8;
    cx.sb = sb;
    return cx;
}

// ---------------- persistent fused Q/K/V projection GEMM ---------------------
// 1536 tiles = 64 m-bands x (5 Q + 5 K + 14 V) n-tiles, m-major for L2 reuse.
__global__ __launch_bounds__(256, 2)
void gemm_qkv(const __nv_bfloat16* __restrict__ qhi, const __nv_bfloat16* __restrict__ qlo,
              const __nv_bfloat16* __restrict__ khi, const __nv_bfloat16* __restrict__ klo,
              const __nv_bfloat16* __restrict__ vhi, const __nv_bfloat16* __restrict__ vlo,
              const __nv_bfloat16* __restrict__ wqh, const __nv_bfloat16* __restrict__ wql,
              const __nv_bfloat16* __restrict__ wkh, const __nv_bfloat16* __restrict__ wkl,
              const __nv_bfloat16* __restrict__ wvh, const __nv_bfloat16* __restrict__ wvl,
              const float* __restrict__ bq, const float* __restrict__ bk, const float* __restrict__ bv,
              float* __restrict__ qp, float* __restrict__ kp, float* __restrict__ vp)
{
    extern __shared__ __nv_bfloat16 sm[];
    GemmCtx cx = make_ctx(smem_u32(sm));
    const int NT = 64 * 24;

    for (int t = blockIdx.x; t < NT; t += gridDim.x) {
        int m = t / 24, r = t % 24;
        int m0 = m * 128;
        if (r < 5) {
            gemm_tile(cx, qhi, qlo, wqh, wql, bq, qp, m0, r * 64, NQK, DMODEL);
        } else if (r < 10) {
            gemm_tile(cx, khi, klo, wkh, wkl, bk, kp, m0, (r - 5) * 64, NQK, DMODEL);
        } else {
            gemm_tile(cx, vhi, vlo, wvh, wvl, bv, vp, m0, (r - 10) * 64, NV, DMODEL);
        }
    }
}

// ---------------- output projection GEMM (persistent too) --------------------
__global__ __launch_bounds__(256, 2)
void gemm_out(const __nv_bfloat16* __restrict__ Ahi, const __nv_bfloat16* __restrict__ Alo,
              const __nv_bfloat16* __restrict__ Bhi, const __nv_bfloat16* __restrict__ Blo,
              const float* __restrict__ bias, float* __restrict__ C)
{
    extern __shared__ __nv_bfloat16 sm[];
    GemmCtx cx = make_ctx(smem_u32(sm));
    const int NT = 64 * 16;
    for (int t = blockIdx.x; t < NT; t += gridDim.x) {
        int m = t >> 4, r = t & 15;
        gemm_tile(cx, Ahi, Alo, Bhi, Blo, bias, C, m * 128, r * 64, DMODEL, NV);
    }
}

// ---------------- tiled banded attention -------------------------------------
#define ATTN_FIXED (2048 + 1024 + 1056 + 1056 + 1024 + 32)

template <int DIL>
__global__ __launch_bounds__(256)
void attn_tiled(const float* __restrict__ qp, const float* __restrict__ kp,
                const float* __restrict__ vp, const float* __restrict__ Ws,
                const float* __restrict__ bsg, float* __restrict__ ao, int h0)
{
    constexpr int WIN = 31 * DIL + 32;
    extern __shared__ float sa[];
    float* swin  = sa;
    float* sq    = swin + WIN * 64;
    float* sws   = sq + 2048;
    float* ssc   = sws + 1024;
    float* ssm   = ssc + 1056;
    float* satt  = ssm + 1056;
    float* sbs   = satt + 1024;

    const int l0 = blockIdx.x * 32;
    const int b  = blockIdx.y;
    const int h  = h0 + blockIdx.z;
    const int s  = (h < 5) ? 0 : (h < 10) ? 1 : (h < 12) ? 2 : (h == 12) ? 3 : 4;
    const int tid = threadIdx.x, lane = tid & 31;
    const int w0 = l0 - 16 * DIL;
    const long rowbase = (long)b * L_SZ + l0;

    {
        int idx = tid;
        #pragma unroll
        for (int p = 0; p < 2; p++, idx += 256) {
            int row = idx >> 4, q4 = (idx & 15) * 4;
            *(float4*)(sq + row * 64 + q4) =
                *(const float4*)(qp + (rowbase + row) * NQK + s * 64 + q4);
        }
        *(float4*)(sws + tid * 4) = *(const float4*)(Ws + (size_t)h * 1024 + tid * 4);
        if (tid < 32) sbs[tid] = bsg[h * KW + tid];
    }
    for (int r = tid >> 4; r < WIN; r += 16) {
        int g = w0 + r; g = g < 0 ? 0 : (g > L_SZ - 1 ? L_SZ - 1 : g);
        int q4 = (tid & 15) * 4;
        *(float4*)(swin + r * 64 + q4) =
            *(const float4*)(kp + ((long)b * L_SZ + g) * NQK + s * 64 + q4);
    }
    __syncthreads();

    {
        const int li = tid >> 3;
        const int kb = (tid & 7) * 4;
        float acc0 = 0.f, acc1 = 0.f, acc2 = 0.f, acc3 = 0.f;
        const float* qrow = sq + li * 64;
        const float* wr0 = swin + (li + (kb + 0) * DIL) * 64;
        const float* wr1 = swin + (li + (kb + 1) * DIL) * 64;
        const float* wr2 = swin + (li + (kb + 2) * DIL) * 64;
        const float* wr3 = swin + (li + (kb + 3) * DIL) * 64;
        #pragma unroll
        for (int t4 = 0; t4 < 16; t4++) {
            int i = ((t4 + lane) & 15) * 4;
            float4 qv = *(const float4*)(qrow + i);
            float4 v0 = *(const float4*)(wr0 + i);
            float4 v1 = *(const float4*)(wr1 + i);
            float4 v2 = *(const float4*)(wr2 + i);
            float4 v3 = *(const float4*)(wr3 + i);
            acc0 += qv.x * v0.x + qv.y * v0.y + qv.z * v0.z + qv.w * v0.w;
            acc1 += qv.x * v1.x + qv.y * v1.y + qv.z * v1.z + qv.w * v1.w;
            acc2 += qv.x * v2.x + qv.y * v2.y + qv.z * v2.z + qv.w * v2.w;
            acc3 += qv.x * v3.x + qv.y * v3.y + qv.z * v3.z + qv.w * v3.w;
        }
        ssc[li * 33 + kb + 0] = acc0 * 0.125f;
        ssc[li * 33 + kb + 1] = acc1 * 0.125f;
        ssc[li * 33 + kb + 2] = acc2 * 0.125f;
        ssc[li * 33 + kb + 3] = acc3 * 0.125f;
    }
    __syncthreads();

    for (int r = tid >> 4; r < WIN; r += 16) {
        int g = w0 + r; g = g < 0 ? 0 : (g > L_SZ - 1 ? L_SZ - 1 : g);
        int q4 = (tid & 15) * 4;
        *(float4*)(swin + r * 64 + q4) =
            *(const float4*)(vp + ((long)b * L_SZ + g) * NV + h * 64 + q4);
    }

    {
        const int li = tid >> 3;
        const int m4 = (tid & 7) * 4;
        float a0 = sbs[m4], a1 = sbs[m4 + 1], a2 = sbs[m4 + 2], a3 = sbs[m4 + 3];
        #pragma unroll 8
        for (int k = 0; k < 32; k++) {
            float scv = ssc[li * 33 + k];
            float4 wv = *(const float4*)(sws + k * 32 + m4);
            a0 += scv * wv.x; a1 += scv * wv.y; a2 += scv * wv.z; a3 += scv * wv.w;
        }
        ssm[li * 33 + m4 + 0] = a0;
        ssm[li * 33 + m4 + 1] = a1;
        ssm[li * 33 + m4 + 2] = a2;
        ssm[li * 33 + m4 + 3] = a3;
    }
    __syncthreads();

    {
        const int w = tid >> 5;
        #pragma unroll
        for (int rr = 0; rr < 4; rr++) {
            int li = w * 4 + rr;
            float v = ssm[li * 33 + lane];
            float mx = v;
            #pragma unroll
            for (int o = 16; o; o >>= 1) mx = fmaxf(mx, __shfl_xor_sync(0xffffffffu, mx, o));
            float e = __expf(v - mx);
            float ss = e;
            #pragma unroll
            for (int o = 16; o; o >>= 1) ss += __shfl_xor_sync(0xffffffffu, ss, o);
            satt[li * 32 + lane] = e / ss;
        }
    }
    __syncthreads();

    {
        const int li = tid >> 3;
        const int io = (tid & 7) * 8;
        float4 a0 = make_float4(0.f, 0.f, 0.f, 0.f);
        float4 a1 = make_float4(0.f, 0.f, 0.f, 0.f);
        #pragma unroll 8
        for (int k = 0; k < 32; k++) {
            float wv = satt[li * 32 + k];
            const float* vr = swin + (li + k * DIL) * 64 + io;
            float4 v0 = *(const float4*)(vr);
            float4 v1 = *(const float4*)(vr + 4);
            a0.x += wv * v0.x; a0.y += wv * v0.y; a0.z += wv * v0.z; a0.w += wv * v0.w;
            a1.x += wv * v1.x; a1.y += wv * v1.y; a1.z += wv * v1.z; a1.w += wv * v1.w;
        }
        float* op = ao + (rowbase + li) * NV + h * 64 + io;
        *(float4*)op = a0;
        *(float4*)(op + 4) = a1;
    }
}

// ---------------- launcher ---------------------------------------------------
extern "C" void kernel_launch(void* const* d_in, const int* in_sizes, int n_in,
                              void* d_out, int out_size)
{
    const float* query = (const float*)d_in[0];
    const float* key   = (const float*)d_in[1];
    const float* value = (const float*)d_in[2];
    const float* Wq    = (const float*)d_in[3];
    const float* bq    = (const float*)d_in[4];
    const float* Wk    = (const float*)d_in[5];
    const float* bk    = (const float*)d_in[6];
    const float* Wv    = (const float*)d_in[7];
    const float* bv    = (const float*)d_in[8];
    const float* Ws    = (const float*)d_in[9];
    const float* bs    = (const float*)d_in[10];
    const float* Wc    = (const float*)d_in[11];
    const float* bc    = (const float*)d_in[12];
    float* out = (float*)d_out;

    float *qp, *kp, *vp, *ao;
    __nv_bfloat16 *qahi, *qalo, *kahi, *kalo, *vahi, *valo, *oahi, *oalo;
    __nv_bfloat16 *wqh, *wql, *wkh, *wkl, *wvh, *wvl, *wch, *wcl;
    cudaGetSymbolAddress((void**)&qp, g_qp);
    cudaGetSymbolAddress((void**)&kp, g_kp);
    cudaGetSymbolAddress((void**)&vp, g_vp);
    cudaGetSymbolAddress((void**)&ao, g_ao);
    cudaGetSymbolAddress((void**)&qahi, g_qahi); cudaGetSymbolAddress((void**)&qalo, g_qalo);
    cudaGetSymbolAddress((void**)&kahi, g_kahi); cudaGetSymbolAddress((void**)&kalo, g_kalo);
    cudaGetSymbolAddress((void**)&vahi, g_vahi); cudaGetSymbolAddress((void**)&valo, g_valo);
    cudaGetSymbolAddress((void**)&oahi, g_oahi); cudaGetSymbolAddress((void**)&oalo, g_oalo);
    cudaGetSymbolAddress((void**)&wqh, g_wqhi); cudaGetSymbolAddress((void**)&wql, g_wqlo);
    cudaGetSymbolAddress((void**)&wkh, g_wkhi); cudaGetSymbolAddress((void**)&wkl, g_wklo);
    cudaGetSymbolAddress((void**)&wvh, g_wvhi); cudaGetSymbolAddress((void**)&wvl, g_wvlo);
    cudaGetSymbolAddress((void**)&wch, g_wchi); cudaGetSymbolAddress((void**)&wcl, g_wclo);

    cudaFuncSetAttribute(gemm_qkv, cudaFuncAttributeMaxDynamicSharedMemorySize, GEMM_SMEM);
    cudaFuncSetAttribute(gemm_out, cudaFuncAttributeMaxDynamicSharedMemorySize, GEMM_SMEM);

    auto asz = [](int dil) { return (size_t)((31 * dil + 32) * 64 + ATTN_FIXED) * 4; };
    cudaFuncSetAttribute(attn_tiled<1>, cudaFuncAttributeMaxDynamicSharedMemorySize, (int)asz(1));
    cudaFuncSetAttribute(attn_tiled<2>, cudaFuncAttributeMaxDynamicSharedMemorySize, (int)asz(2));
    cudaFuncSetAttribute(attn_tiled<4>, cudaFuncAttributeMaxDynamicSharedMemorySize, (int)asz(4));
    cudaFuncSetAttribute(attn_tiled<8>, cudaFuncAttributeMaxDynamicSharedMemorySize, (int)asz(8));

    const int nact8 = ML * DMODEL / 8;

    // ---- conversions ----
    conv_act<<<(nact8 + 255) / 256, 256>>>((const float4*)query, (uint4*)qahi, (uint4*)qalo, nact8);
    conv_act<<<(nact8 + 255) / 256, 256>>>((const float4*)key,   (uint4*)kahi, (uint4*)kalo, nact8);
    conv_act<<<(nact8 + 255) / 256, 256>>>((const float4*)value, (uint4*)vahi, (uint4*)valo, nact8);
    conv_w_seg<<<NQK, 256>>>(Wq, wqh, wql, DMODEL);
    conv_w_seg<<<NQK, 256>>>(Wk, wkh, wkl, DMODEL);
    conv_w_seg<<<NV, 256>>>(Wv, wvh, wvl, DMODEL);

    // ---- fused persistent Q/K/V projection ----
    gemm_qkv<<<296, 256, GEMM_SMEM>>>(qahi, qalo, kahi, kalo, vahi, valo,
                                      wqh, wql, wkh, wkl, wvh, wvl,
                                      bq, bk, bv, qp, kp, vp);

    // ---- tiled attention: heads grouped by dilation ----
    attn_tiled<1><<<dim3(L_SZ / 32, B_SZ, 10), 256, asz(1)>>>(qp, kp, vp, Ws, bs, ao, 0);
    attn_tiled<2><<<dim3(L_SZ / 32, B_SZ, 2),  256, asz(2)>>>(qp, kp, vp, Ws, bs, ao, 10);
    attn_tiled<4><<<dim3(L_SZ / 32, B_SZ, 1),  256, asz(4)>>>(qp, kp, vp, Ws, bs, ao, 12);
    attn_tiled<8><<<dim3(L_SZ / 32, B_SZ, 1),  256, asz(8)>>>(qp, kp, vp, Ws, bs, ao, 13);

    // ---- output projection ----
    const int nao8 = ML * NV / 8;
    conv_act<<<(nao8 + 255) / 256, 256>>>((const float4*)ao, (uint4*)oahi, (uint4*)oalo, nao8);
    conv_w_t<<<DMODEL, 256>>>(Wc, wch, wcl, NV, DMODEL);
    gemm_out<<<296, 256, GEMM_SMEM>>>(oahi, oalo, wch, wcl, bc, out);
}

// round 6
// speedup vs baseline: 2.9770x; 1.0611x over previous
#include <cuda_runtime.h>
#include <cuda_bf16.h>
#include <cstdint>

// Problem constants
#define B_SZ   2
#define L_SZ   4096
#define DMODEL 1024
#define DINT   64
#define KW     32
#define SUBH   5
#define HEADS  14
#define ML     (B_SZ * L_SZ)          // 8192 rows
#define NQK    320
#define NQKP   384                    // padded to 3*128
#define NV     896

// ---------------- scratch (static device globals; no allocation) -------------
__device__ float g_qp[ML * NQKP];
__device__ float g_kp[ML * NQKP];
__device__ float g_vp[ML * NV];
__device__ __nv_bfloat16 g_qahi[ML * DMODEL], g_qalo[ML * DMODEL];
__device__ __nv_bfloat16 g_kahi[ML * DMODEL], g_kalo[ML * DMODEL];
__device__ __nv_bfloat16 g_vahi[ML * DMODEL], g_valo[ML * DMODEL];
__device__ __nv_bfloat16 g_oahi[ML * NV],     g_oalo[ML * NV];
__device__ __nv_bfloat16 g_wqhi[NQKP * DMODEL], g_wqlo[NQKP * DMODEL];
__device__ __nv_bfloat16 g_wkhi[NQKP * DMODEL], g_wklo[NQKP * DMODEL];
__device__ __nv_bfloat16 g_wvhi[NV * DMODEL],   g_wvlo[NV * DMODEL];
__device__ __nv_bfloat16 g_wchi[DMODEL * NV],   g_wclo[DMODEL * NV];
__device__ float g_bqp[NQKP], g_bkp[NQKP];

// ---------------- helpers ------------------------------------------------
__device__ __forceinline__ uint32_t smem_u32(const void* p) {
    uint32_t a;
    asm("{ .reg .u64 t; cvta.to.shared.u64 t, %1; cvt.u32.u64 %0, t; }" : "=r"(a) : "l"(p));
    return a;
}
__device__ __forceinline__ void cpa16(uint32_t s, const void* g) {
    asm volatile("cp.async.cg.shared.global [%0], [%1], 16;" :: "r"(s), "l"(g));
}
#define CPA_COMMIT() asm volatile("cp.async.commit_group;" ::: "memory")
#define CPA_WAIT(n)  asm volatile("cp.async.wait_group %0;" :: "n"(n) : "memory")

#define LDSM4(r0, r1, r2, r3, a) \
    asm volatile("ldmatrix.sync.aligned.m8n8.x4.shared.b16 {%0,%1,%2,%3}, [%4];" \
        : "=r"(r0), "=r"(r1), "=r"(r2), "=r"(r3) : "r"(a))

#define MMA16816(c, a, b0, b1) \
    asm volatile("mma.sync.aligned.m16n8k16.row.col.f32.bf16.bf16.f32 " \
        "{%0,%1,%2,%3},{%4,%5,%6,%7},{%8,%9},{%0,%1,%2,%3};" \
        : "+f"((c)[0]), "+f"((c)[1]), "+f"((c)[2]), "+f"((c)[3]) \
        : "r"((a)[0]), "r"((a)[1]), "r"((a)[2]), "r"((a)[3]), "r"(b0), "r"(b1))

__device__ __forceinline__ uint32_t pack_hi2(float a, float b, float& ra, float& rb) {
    __nv_bfloat162 h;
    h.x = __float2bfloat16_rn(a); h.y = __float2bfloat16_rn(b);
    ra = a - __bfloat162float(h.x); rb = b - __bfloat162float(h.y);
    return *(uint32_t*)&h;
}
__device__ __forceinline__ uint32_t pack2(float a, float b) {
    __nv_bfloat162 h;
    h.x = __float2bfloat16_rn(a); h.y = __float2bfloat16_rn(b);
    return *(uint32_t*)&h;
}

// ---------------- conversion kernels -----------------------------------------
// fused q/k/v fp32 -> bf16 hi/lo (blockIdx.y selects source)
__global__ __launch_bounds__(256)
void conv_act3(const float4* __restrict__ q, const float4* __restrict__ k,
               const float4* __restrict__ v,
               uint4* __restrict__ qh, uint4* __restrict__ ql,
               uint4* __restrict__ kh, uint4* __restrict__ kl,
               uint4* __restrict__ vh, uint4* __restrict__ vl, int n8)
{
    int i = blockIdx.x * 256 + threadIdx.x;
    if (i >= n8) return;
    const float4* in; uint4 *hi, *lo;
    if (blockIdx.y == 0)      { in = q; hi = qh; lo = ql; }
    else if (blockIdx.y == 1) { in = k; hi = kh; lo = kl; }
    else                      { in = v; hi = vh; lo = vl; }
    float4 a = in[2 * i], b = in[2 * i + 1];
    float r0, r1, r2, r3, r4, r5, r6, r7;
    uint4 h, l;
    h.x = pack_hi2(a.x, a.y, r0, r1);
    h.y = pack_hi2(a.z, a.w, r2, r3);
    h.z = pack_hi2(b.x, b.y, r4, r5);
    h.w = pack_hi2(b.z, b.w, r6, r7);
    l.x = pack2(r0, r1); l.y = pack2(r2, r3);
    l.z = pack2(r4, r5); l.w = pack2(r6, r7);
    hi[i] = h; lo[i] = l;
}

// W [heads, K, 64] -> Bt [Npad, K] bf16 hi/lo (zero rows >= Nreal)
__global__ __launch_bounds__(256)
void conv_w_seg(const float* __restrict__ W, __nv_bfloat16* __restrict__ bhi,
                __nv_bfloat16* __restrict__ blo, int K, int Nreal)
{
    int n = blockIdx.x;
    if (n >= Nreal) {
        for (int kk = threadIdx.x; kk < K; kk += 256) {
            bhi[(size_t)n * K + kk] = __float2bfloat16(0.f);
            blo[(size_t)n * K + kk] = __float2bfloat16(0.f);
        }
        return;
    }
    int head = n >> 6, i = n & 63;
    for (int kk = threadIdx.x; kk < K; kk += 256) {
        float x = W[((size_t)head * K + kk) * 64 + i];
        __nv_bfloat16 h = __float2bfloat16_rn(x);
        __nv_bfloat16 l = __float2bfloat16_rn(x - __bfloat162float(h));
        bhi[(size_t)n * K + kk] = h;
        blo[(size_t)n * K + kk] = l;
    }
}

// Wc [K, N] -> Bt [N, K] bf16 hi/lo (transpose)
__global__ __launch_bounds__(256)
void conv_w_t(const float* __restrict__ W, __nv_bfloat16* __restrict__ bhi,
              __nv_bfloat16* __restrict__ blo, int K, int Ntot)
{
    int n = blockIdx.x;
    for (int k = threadIdx.x; k < K; k += 256) {
        float x = W[(size_t)k * Ntot + n];
        __nv_bfloat16 h = __float2bfloat16_rn(x);
        __nv_bfloat16 l = __float2bfloat16_rn(x - __bfloat162float(h));
        bhi[(size_t)n * K + k] = h;
        blo[(size_t)n * K + k] = l;
    }
}

// pad biases
__global__ void pad_bias(const float* __restrict__ bq, const float* __restrict__ bk,
                         float* __restrict__ bqp, float* __restrict__ bkp)
{
    int i = threadIdx.x;
    if (i < NQKP) {
        bqp[i] = (i < NQK) ? bq[i] : 0.f;
        bkp[i] = (i < NQK) ? bk[i] : 0.f;
    }
}

// ---------------- split-bf16 HMMA GEMM, 128x128 tile --------------------------
#define APAD 40
#define AHI_OFF 0
#define ALO_OFF 5120
#define BHI_OFF 10240
#define BLO_OFF 15360
#define STE     20480                  // elems per stage
#define GEMM_SMEM (2 * STE * 2)        // 81920 bytes

__device__ __forceinline__ void gemm_tile128(
    const __nv_bfloat16* __restrict__ Ahi, const __nv_bfloat16* __restrict__ Alo,
    const __nv_bfloat16* __restrict__ Bhi, const __nv_bfloat16* __restrict__ Blo,
    const float* __restrict__ bias, float* __restrict__ C,
    int m0, int n0, int N, int K, uint32_t sb)
{
    const int tid = threadIdx.x, lane = tid & 31, wid = tid >> 5;
    const int wm = wid >> 1, wn = wid & 1;

    float c[2][8][4];
    #pragma unroll
    for (int i = 0; i < 2; i++)
        #pragma unroll
        for (int j = 0; j < 8; j++)
            #pragma unroll
            for (int q = 0; q < 4; q++) c[i][j][q] = 0.f;

    const int ld_row0 = tid >> 2;          // +64 for second half
    const int ld_col  = (tid & 3) * 8;

    const int r = lane & 7, g = lane >> 3;
    const int a_ld_row = (g & 1) * 8 + r;
    const int a_ld_k   = (g >> 1) * 8;
    const int b_ld_row = (g >> 1) * 8 + r;
    const int b_ld_k   = (g & 1) * 8;

    const int nit = K >> 5;

    // prologue stage 0
    {
        uint32_t base = sb;
        #pragma unroll
        for (int i = 0; i < 2; i++) {
            int row = ld_row0 + i * 64;
            uint32_t so = base + (uint32_t)(row * APAD + ld_col) * 2;
            size_t ga = (size_t)(m0 + row) * K + ld_col;
            size_t gb = (size_t)(n0 + row) * K + ld_col;
            cpa16(so + AHI_OFF * 2, Ahi + ga);
            cpa16(so + ALO_OFF * 2, Alo + ga);
            cpa16(so + BHI_OFF * 2, Bhi + gb);
            cpa16(so + BLO_OFF * 2, Blo + gb);
        }
        CPA_COMMIT();
    }

    for (int it = 0; it < nit; ++it) {
        if (it + 1 < nit) {
            uint32_t base = sb + (uint32_t)(((it + 1) & 1) * STE) * 2;
            int k0 = (it + 1) << 5;
            #pragma unroll
            for (int i = 0; i < 2; i++) {
                int row = ld_row0 + i * 64;
                uint32_t so = base + (uint32_t)(row * APAD + ld_col) * 2;
                size_t ga = (size_t)(m0 + row) * K + k0 + ld_col;
                size_t gb = (size_t)(n0 + row) * K + k0 + ld_col;
                cpa16(so + AHI_OFF * 2, Ahi + ga);
                cpa16(so + ALO_OFF * 2, Alo + ga);
                cpa16(so + BHI_OFF * 2, Bhi + gb);
                cpa16(so + BLO_OFF * 2, Blo + gb);
            }
            CPA_COMMIT();
            CPA_WAIT(1);
        } else {
            CPA_WAIT(0);
        }
        __syncthreads();

        uint32_t base = sb + (uint32_t)((it & 1) * STE) * 2;
        #pragma unroll
        for (int kk = 0; kk < 32; kk += 16) {
            uint32_t ah[2][4], al[2][4];
            #pragma unroll
            for (int mt = 0; mt < 2; mt++) {
                uint32_t ad = base + (uint32_t)((wm * 32 + mt * 16 + a_ld_row) * APAD + kk + a_ld_k) * 2;
                LDSM4(ah[mt][0], ah[mt][1], ah[mt][2], ah[mt][3], ad + AHI_OFF * 2);
                LDSM4(al[mt][0], al[mt][1], al[mt][2], al[mt][3], ad + ALO_OFF * 2);
            }
            #pragma unroll
            for (int np = 0; np < 4; np++) {
                uint32_t bh[4], bl[4];
                uint32_t bd = base + (uint32_t)((wn * 64 + np * 16 + b_ld_row) * APAD + kk + b_ld_k) * 2;
                LDSM4(bh[0], bh[1], bh[2], bh[3], bd + BHI_OFF * 2);
                LDSM4(bl[0], bl[1], bl[2], bl[3], bd + BLO_OFF * 2);
                #pragma unroll
                for (int mt = 0; mt < 2; mt++) {
                    MMA16816(c[mt][np * 2 + 0], ah[mt], bh[0], bh[1]);
                    MMA16816(c[mt][np * 2 + 1], ah[mt], bh[2], bh[3]);
                    MMA16816(c[mt][np * 2 + 0], ah[mt], bl[0], bl[1]);
                    MMA16816(c[mt][np * 2 + 1], ah[mt], bl[2], bl[3]);
                    MMA16816(c[mt][np * 2 + 0], al[mt], bh[0], bh[1]);
                    MMA16816(c[mt][np * 2 + 1], al[mt], bh[2], bh[3]);
                }
            }
        }
        __syncthreads();
    }

    // epilogue
    #pragma unroll
    for (int mt = 0; mt < 2; mt++) {
        int row = m0 + wm * 32 + mt * 16 + (lane >> 2);
        #pragma unroll
        for (int nt = 0; nt < 8; nt++) {
            int col = n0 + wn * 64 + nt * 8 + (lane & 3) * 2;
            float2 bv = *(const float2*)(bias + col);
            float2 v0, v1;
            v0.x = c[mt][nt][0] + bv.x; v0.y = c[mt][nt][1] + bv.y;
            v1.x = c[mt][nt][2] + bv.x; v1.y = c[mt][nt][3] + bv.y;
            *(float2*)(C + (size_t)row * N + col) = v0;
            *(float2*)(C + (size_t)(row + 8) * N + col) = v1;
        }
    }
}

// fused Q/K/V projection: grid (13, 64)
__global__ __launch_bounds__(256, 2)
void gemm_qkv(const __nv_bfloat16* __restrict__ qhi, const __nv_bfloat16* __restrict__ qlo,
              const __nv_bfloat16* __restrict__ khi, const __nv_bfloat16* __restrict__ klo,
              const __nv_bfloat16* __restrict__ vhi, const __nv_bfloat16* __restrict__ vlo,
              const __nv_bfloat16* __restrict__ wqh, const __nv_bfloat16* __restrict__ wql,
              const __nv_bfloat16* __restrict__ wkh, const __nv_bfloat16* __restrict__ wkl,
              const __nv_bfloat16* __restrict__ wvh, const __nv_bfloat16* __restrict__ wvl,
              const float* __restrict__ bqp, const float* __restrict__ bkp, const float* __restrict__ bv,
              float* __restrict__ qp, float* __restrict__ kp, float* __restrict__ vp)
{
    extern __shared__ __nv_bfloat16 sm[];
    uint32_t sb = smem_u32(sm);
    const int m0 = blockIdx.y * 128;
    const int rr = blockIdx.x;
    if (rr < 3)
        gemm_tile128(qhi, qlo, wqh, wql, bqp, qp, m0, rr * 128, NQKP, DMODEL, sb);
    else if (rr < 6)
        gemm_tile128(khi, klo, wkh, wkl, bkp, kp, m0, (rr - 3) * 128, NQKP, DMODEL, sb);
    else
        gemm_tile128(vhi, vlo, wvh, wvl, bv, vp, m0, (rr - 6) * 128, NV, DMODEL, sb);
}

// output projection: grid (8, 64)
__global__ __launch_bounds__(256, 2)
void gemm_out(const __nv_bfloat16* __restrict__ Ahi, const __nv_bfloat16* __restrict__ Alo,
              const __nv_bfloat16* __restrict__ Bhi, const __nv_bfloat16* __restrict__ Blo,
              const float* __restrict__ bias, float* __restrict__ C)
{
    extern __shared__ __nv_bfloat16 sm[];
    uint32_t sb = smem_u32(sm);
    gemm_tile128(Ahi, Alo, Bhi, Blo, bias, C, blockIdx.y * 128, blockIdx.x * 128, DMODEL, NV, sb);
}

// ---------------- tiled banded attention (writes bf16 hi/lo) ------------------
#define ATTN_FIXED (2048 + 1024 + 1056 + 1056 + 1024 + 32)

template <int DIL>
__global__ __launch_bounds__(256)
void attn_tiled(const float* __restrict__ qp, const float* __restrict__ kp,
                const float* __restrict__ vp, const float* __restrict__ Ws,
                const float* __restrict__ bsg,
                __nv_bfloat16* __restrict__ ohi, __nv_bfloat16* __restrict__ olo, int h0)
{
    constexpr int WIN = 31 * DIL + 32;
    extern __shared__ float sa[];
    float* swin  = sa;
    float* sq    = swin + WIN * 64;
    float* sws   = sq + 2048;
    float* ssc   = sws + 1024;
    float* ssm   = ssc + 1056;
    float* satt  = ssm + 1056;
    float* sbs   = satt + 1024;

    const int l0 = blockIdx.x * 32;
    const int b  = blockIdx.y;
    const int h  = h0 + blockIdx.z;
    const int s  = (h < 5) ? 0 : (h < 10) ? 1 : (h < 12) ? 2 : (h == 12) ? 3 : 4;
    const int tid = threadIdx.x, lane = tid & 31;
    const int w0 = l0 - 16 * DIL;
    const long rowbase = (long)b * L_SZ + l0;

    {
        int idx = tid;
        #pragma unroll
        for (int p = 0; p < 2; p++, idx += 256) {
            int row = idx >> 4, q4 = (idx & 15) * 4;
            *(float4*)(sq + row * 64 + q4) =
                *(const float4*)(qp + (rowbase + row) * NQKP + s * 64 + q4);
        }
        *(float4*)(sws + tid * 4) = *(const float4*)(Ws + (size_t)h * 1024 + tid * 4);
        if (tid < 32) sbs[tid] = bsg[h * KW + tid];
    }
    for (int r = tid >> 4; r < WIN; r += 16) {
        int g = w0 + r; g = g < 0 ? 0 : (g > L_SZ - 1 ? L_SZ - 1 : g);
        int q4 = (tid & 15) * 4;
        *(float4*)(swin + r * 64 + q4) =
            *(const float4*)(kp + ((long)b * L_SZ + g) * NQKP + s * 64 + q4);
    }
    __syncthreads();

    {
        const int li = tid >> 3;
        const int kb = (tid & 7) * 4;
        float acc0 = 0.f, acc1 = 0.f, acc2 = 0.f, acc3 = 0.f;
        const float* qrow = sq + li * 64;
        const float* wr0 = swin + (li + (kb + 0) * DIL) * 64;
        const float* wr1 = swin + (li + (kb + 1) * DIL) * 64;
        const float* wr2 = swin + (li + (kb + 2) * DIL) * 64;
        const float* wr3 = swin + (li + (kb + 3) * DIL) * 64;
        #pragma unroll
        for (int t4 = 0; t4 < 16; t4++) {
            int i = ((t4 + lane) & 15) * 4;
            float4 qv = *(const float4*)(qrow + i);
            float4 v0 = *(const float4*)(wr0 + i);
            float4 v1 = *(const float4*)(wr1 + i);
            float4 v2 = *(const float4*)(wr2 + i);
            float4 v3 = *(const float4*)(wr3 + i);
            acc0 += qv.x * v0.x + qv.y * v0.y + qv.z * v0.z + qv.w * v0.w;
            acc1 += qv.x * v1.x + qv.y * v1.y + qv.z * v1.z + qv.w * v1.w;
            acc2 += qv.x * v2.x + qv.y * v2.y + qv.z * v2.z + qv.w * v2.w;
            acc3 += qv.x * v3.x + qv.y * v3.y + qv.z * v3.z + qv.w * v3.w;
        }
        ssc[li * 33 + kb + 0] = acc0 * 0.125f;
        ssc[li * 33 + kb + 1] = acc1 * 0.125f;
        ssc[li * 33 + kb + 2] = acc2 * 0.125f;
        ssc[li * 33 + kb + 3] = acc3 * 0.125f;
    }
    __syncthreads();

    for (int r = tid >> 4; r < WIN; r += 16) {
        int g = w0 + r; g = g < 0 ? 0 : (g > L_SZ - 1 ? L_SZ - 1 : g);
        int q4 = (tid & 15) * 4;
        *(float4*)(swin + r * 64 + q4) =
            *(const float4*)(vp + ((long)b * L_SZ + g) * NV + h * 64 + q4);
    }

    {
        const int li = tid >> 3;
        const int m4 = (tid & 7) * 4;
        float a0 = sbs[m4], a1 = sbs[m4 + 1], a2 = sbs[m4 + 2], a3 = sbs[m4 + 3];
        #pragma unroll 8
        for (int k = 0; k < 32; k++) {
            float scv = ssc[li * 33 + k];
            float4 wv = *(const float4*)(sws + k * 32 + m4);
            a0 += scv * wv.x; a1 += scv * wv.y; a2 += scv * wv.z; a3 += scv * wv.w;
        }
        ssm[li * 33 + m4 + 0] = a0;
        ssm[li * 33 + m4 + 1] = a1;
        ssm[li * 33 + m4 + 2] = a2;
        ssm[li * 33 + m4 + 3] = a3;
    }
    __syncthreads();

    {
        const int w = tid >> 5;
        #pragma unroll
        for (int rr = 0; rr < 4; rr++) {
            int li = w * 4 + rr;
            float v = ssm[li * 33 + lane];
            float mx = v;
            #pragma unroll
            for (int o = 16; o; o >>= 1) mx = fmaxf(mx, __shfl_xor_sync(0xffffffffu, mx, o));
            float e = __expf(v - mx);
            float ss = e;
            #pragma unroll
            for (int o = 16; o; o >>= 1) ss += __shfl_xor_sync(0xffffffffu, ss, o);
            satt[li * 32 + lane] = e / ss;
        }
    }
    __syncthreads();

    {
        const int li = tid >> 3;
        const int io = (tid & 7) * 8;
        float4 a0 = make_float4(0.f, 0.f, 0.f, 0.f);
        float4 a1 = make_float4(0.f, 0.f, 0.f, 0.f);
        #pragma unroll 8
        for (int k = 0; k < 32; k++) {
            float wv = satt[li * 32 + k];
            const float* vr = swin + (li + k * DIL) * 64 + io;
            float4 v0 = *(const float4*)(vr);
            float4 v1 = *(const float4*)(vr + 4);
            a0.x += wv * v0.x; a0.y += wv * v0.y; a0.z += wv * v0.z; a0.w += wv * v0.w;
            a1.x += wv * v1.x; a1.y += wv * v1.y; a1.z += wv * v1.z; a1.w += wv * v1.w;
        }
        // write bf16 hi/lo directly
        float r0, r1, r2, r3, r4, r5, r6, r7;
        uint4 hv, lv;
        hv.x = pack_hi2(a0.x, a0.y, r0, r1);
        hv.y = pack_hi2(a0.z, a0.w, r2, r3);
        hv.z = pack_hi2(a1.x, a1.y, r4, r5);
        hv.w = pack_hi2(a1.z, a1.w, r6, r7);
        lv.x = pack2(r0, r1); lv.y = pack2(r2, r3);
        lv.z = pack2(r4, r5); lv.w = pack2(r6, r7);
        size_t off = (rowbase + li) * NV + h * 64 + io;
        *(uint4*)(ohi + off) = hv;
        *(uint4*)(olo + off) = lv;
    }
}

// ---------------- launcher ---------------------------------------------------
extern "C" void kernel_launch(void* const* d_in, const int* in_sizes, int n_in,
                              void* d_out, int out_size)
{
    const float* query = (const float*)d_in[0];
    const float* key   = (const float*)d_in[1];
    const float* value = (const float*)d_in[2];
    const float* Wq    = (const float*)d_in[3];
    const float* bq    = (const float*)d_in[4];
    const float* Wk    = (const float*)d_in[5];
    const float* bk    = (const float*)d_in[6];
    const float* Wv    = (const float*)d_in[7];
    const float* bv    = (const float*)d_in[8];
    const float* Ws    = (const float*)d_in[9];
    const float* bs    = (const float*)d_in[10];
    const float* Wc    = (const float*)d_in[11];
    const float* bc    = (const float*)d_in[12];
    float* out = (float*)d_out;

    float *qp, *kp, *vp, *bqp, *bkp;
    __nv_bfloat16 *qahi, *qalo, *kahi, *kalo, *vahi, *valo, *oahi, *oalo;
    __nv_bfloat16 *wqh, *wql, *wkh, *wkl, *wvh, *wvl, *wch, *wcl;
    cudaGetSymbolAddress((void**)&qp, g_qp);
    cudaGetSymbolAddress((void**)&kp, g_kp);
    cudaGetSymbolAddress((void**)&vp, g_vp);
    cudaGetSymbolAddress((void**)&bqp, g_bqp);
    cudaGetSymbolAddress((void**)&bkp, g_bkp);
    cudaGetSymbolAddress((void**)&qahi, g_qahi); cudaGetSymbolAddress((void**)&qalo, g_qalo);
    cudaGetSymbolAddress((void**)&kahi, g_kahi); cudaGetSymbolAddress((void**)&kalo, g_kalo);
    cudaGetSymbolAddress((void**)&vahi, g_vahi); cudaGetSymbolAddress((void**)&valo, g_valo);
    cudaGetSymbolAddress((void**)&oahi, g_oahi); cudaGetSymbolAddress((void**)&oalo, g_oalo);
    cudaGetSymbolAddress((void**)&wqh, g_wqhi); cudaGetSymbolAddress((void**)&wql, g_wqlo);
    cudaGetSymbolAddress((void**)&wkh, g_wkhi); cudaGetSymbolAddress((void**)&wkl, g_wklo);
    cudaGetSymbolAddress((void**)&wvh, g_wvhi); cudaGetSymbolAddress((void**)&wvl, g_wvlo);
    cudaGetSymbolAddress((void**)&wch, g_wchi); cudaGetSymbolAddress((void**)&wcl, g_wclo);

    cudaFuncSetAttribute(gemm_qkv, cudaFuncAttributeMaxDynamicSharedMemorySize, GEMM_SMEM);
    cudaFuncSetAttribute(gemm_out, cudaFuncAttributeMaxDynamicSharedMemorySize, GEMM_SMEM);

    auto asz = [](int dil) { return (size_t)((31 * dil + 32) * 64 + ATTN_FIXED) * 4; };
    cudaFuncSetAttribute(attn_tiled<1>, cudaFuncAttributeMaxDynamicSharedMemorySize, (int)asz(1));
    cudaFuncSetAttribute(attn_tiled<2>, cudaFuncAttributeMaxDynamicSharedMemorySize, (int)asz(2));
    cudaFuncSetAttribute(attn_tiled<4>, cudaFuncAttributeMaxDynamicSharedMemorySize, (int)asz(4));
    cudaFuncSetAttribute(attn_tiled<8>, cudaFuncAttributeMaxDynamicSharedMemorySize, (int)asz(8));

    const int nact8 = ML * DMODEL / 8;

    // ---- conversions ----
    conv_act3<<<dim3((nact8 + 255) / 256, 3), 256>>>(
        (const float4*)query, (const float4*)key, (const float4*)value,
        (uint4*)qahi, (uint4*)qalo, (uint4*)kahi, (uint4*)kalo, (uint4*)vahi, (uint4*)valo, nact8);
    conv_w_seg<<<NQKP, 256>>>(Wq, wqh, wql, DMODEL, NQK);
    conv_w_seg<<<NQKP, 256>>>(Wk, wkh, wkl, DMODEL, NQK);
    conv_w_seg<<<NV, 256>>>(Wv, wvh, wvl, DMODEL, NV);
    pad_bias<<<1, NQKP>>>(bq, bk, bqp, bkp);

    // ---- fused Q/K/V projection (128x128 tiles) ----
    gemm_qkv<<<dim3(13, 64), 256, GEMM_SMEM>>>(qahi, qalo, kahi, kalo, vahi, valo,
                                               wqh, wql, wkh, wkl, wvh, wvl,
                                               bqp, bkp, bv, qp, kp, vp);

    // ---- tiled attention (writes bf16 hi/lo) ----
    attn_tiled<1><<<dim3(L_SZ / 32, B_SZ, 10), 256, asz(1)>>>(qp, kp, vp, Ws, bs, oahi, oalo, 0);
    attn_tiled<2><<<dim3(L_SZ / 32, B_SZ, 2),  256, asz(2)>>>(qp, kp, vp, Ws, bs, oahi, oalo, 10);
    attn_tiled<4><<<dim3(L_SZ / 32, B_SZ, 1),  256, asz(4)>>>(qp, kp, vp, Ws, bs, oahi, oalo, 12);
    attn_tiled<8><<<dim3(L_SZ / 32, B_SZ, 1),  256, asz(8)>>>(qp, kp, vp, Ws, bs, oahi, oalo, 13);

    // ---- output projection ----
    conv_w_t<<<DMODEL, 256>>>(Wc, wch, wcl, NV, DMODEL);
    gemm_out<<<dim3(8, 64), 256, GEMM_SMEM>>>(oahi, oalo, wch, wcl, bc, out);
}

// round 7
// speedup vs baseline: 3.7521x; 1.2604x over previous
#include <cuda_runtime.h>
#include <cuda_fp16.h>
#include <cstdint>

// Problem constants
#define B_SZ   2
#define L_SZ   4096
#define DMODEL 1024
#define DINT   64
#define KW     32
#define SUBH   5
#define HEADS  14
#define ML     (B_SZ * L_SZ)          // 8192 rows
#define NQK    320
#define NQKP   384                    // padded to 3*128
#define NV     896

// ---------------- scratch (static device globals; no allocation) -------------
__device__ float g_qp[ML * NQKP];
__device__ float g_kp[ML * NQKP];
__device__ float g_vp[ML * NV];
__device__ __half g_qahi[ML * DMODEL], g_qalo[ML * DMODEL];
__device__ __half g_kahi[ML * DMODEL], g_kalo[ML * DMODEL];
__device__ __half g_vahi[ML * DMODEL], g_valo[ML * DMODEL];
__device__ __half g_oahi[ML * NV],     g_oalo[ML * NV];
__device__ __half g_wq[NQKP * DMODEL];
__device__ __half g_wk[NQKP * DMODEL];
__device__ __half g_wv[NV * DMODEL];
__device__ __half g_wc[DMODEL * NV];
__device__ float g_bqp[NQKP], g_bkp[NQKP];

// ---------------- helpers ------------------------------------------------
__device__ __forceinline__ uint32_t smem_u32(const void* p) {
    uint32_t a;
    asm("{ .reg .u64 t; cvta.to.shared.u64 t, %1; cvt.u32.u64 %0, t; }" : "=r"(a) : "l"(p));
    return a;
}
__device__ __forceinline__ void cpa16(uint32_t s, const void* g) {
    asm volatile("cp.async.cg.shared.global [%0], [%1], 16;" :: "r"(s), "l"(g));
}
#define CPA_COMMIT() asm volatile("cp.async.commit_group;" ::: "memory")
#define CPA_WAIT(n)  asm volatile("cp.async.wait_group %0;" :: "n"(n) : "memory")

#define LDSM4(r0, r1, r2, r3, a) \
    asm volatile("ldmatrix.sync.aligned.m8n8.x4.shared.b16 {%0,%1,%2,%3}, [%4];" \
        : "=r"(r0), "=r"(r1), "=r"(r2), "=r"(r3) : "r"(a))

#define MMAF16(c, a, b0, b1) \
    asm volatile("mma.sync.aligned.m16n8k16.row.col.f32.f16.f16.f32 " \
        "{%0,%1,%2,%3},{%4,%5,%6,%7},{%8,%9},{%0,%1,%2,%3};" \
        : "+f"((c)[0]), "+f"((c)[1]), "+f"((c)[2]), "+f"((c)[3]) \
        : "r"((a)[0]), "r"((a)[1]), "r"((a)[2]), "r"((a)[3]), "r"(b0), "r"(b1))

__device__ __forceinline__ uint32_t pack_hi2(float a, float b, float& ra, float& rb) {
    __half2 h;
    h.x = __float2half_rn(a); h.y = __float2half_rn(b);
    ra = a - __half2float(h.x); rb = b - __half2float(h.y);
    return *(uint32_t*)&h;
}
__device__ __forceinline__ uint32_t pack2(float a, float b) {
    __half2 h;
    h.x = __float2half_rn(a); h.y = __float2half_rn(b);
    return *(uint32_t*)&h;
}

// ---------------- conversion kernels -----------------------------------------
// fused q/k/v fp32 -> fp16 hi/lo (blockIdx.y selects source)
__global__ __launch_bounds__(256)
void conv_act3(const float4* __restrict__ q, const float4* __restrict__ k,
               const float4* __restrict__ v,
               uint4* __restrict__ qh, uint4* __restrict__ ql,
               uint4* __restrict__ kh, uint4* __restrict__ kl,
               uint4* __restrict__ vh, uint4* __restrict__ vl, int n8)
{
    int i = blockIdx.x * 256 + threadIdx.x;
    if (i >= n8) return;
    const float4* in; uint4 *hi, *lo;
    if (blockIdx.y == 0)      { in = q; hi = qh; lo = ql; }
    else if (blockIdx.y == 1) { in = k; hi = kh; lo = kl; }
    else                      { in = v; hi = vh; lo = vl; }
    float4 a = in[2 * i], b = in[2 * i + 1];
    float r0, r1, r2, r3, r4, r5, r6, r7;
    uint4 h, l;
    h.x = pack_hi2(a.x, a.y, r0, r1);
    h.y = pack_hi2(a.z, a.w, r2, r3);
    h.z = pack_hi2(b.x, b.y, r4, r5);
    h.w = pack_hi2(b.z, b.w, r6, r7);
    l.x = pack2(r0, r1); l.y = pack2(r2, r3);
    l.z = pack2(r4, r5); l.w = pack2(r6, r7);
    hi[i] = h; lo[i] = l;
}

// W [heads, K, 64] -> Bt [Npad, K] fp16 (zero rows >= Nreal)
__global__ __launch_bounds__(256)
void conv_w_seg(const float* __restrict__ W, __half* __restrict__ bh, int K, int Nreal)
{
    int n = blockIdx.x;
    if (n >= Nreal) {
        for (int kk = threadIdx.x; kk < K; kk += 256)
            bh[(size_t)n * K + kk] = __float2half(0.f);
        return;
    }
    int head = n >> 6, i = n & 63;
    for (int kk = threadIdx.x; kk < K; kk += 256)
        bh[(size_t)n * K + kk] = __float2half_rn(W[((size_t)head * K + kk) * 64 + i]);
}

// Wc [K, N] -> Bt [N, K] fp16 (transpose)
__global__ __launch_bounds__(256)
void conv_w_t(const float* __restrict__ W, __half* __restrict__ bh, int K, int Ntot)
{
    int n = blockIdx.x;
    for (int k = threadIdx.x; k < K; k += 256)
        bh[(size_t)n * K + k] = __float2half_rn(W[(size_t)k * Ntot + n]);
}

__global__ void pad_bias(const float* __restrict__ bq, const float* __restrict__ bk,
                         float* __restrict__ bqp, float* __restrict__ bkp)
{
    int i = threadIdx.x;
    if (i < NQKP) {
        bqp[i] = (i < NQK) ? bq[i] : 0.f;
        bkp[i] = (i < NQK) ? bk[i] : 0.f;
    }
}

// ---------------- split-fp16 HMMA GEMM, 128x128 tile, 2 passes ---------------
#define APAD 40
#define AHI_OFF 0
#define ALO_OFF 5120
#define BH_OFF  10240
#define STE     15360                  // half-elems per stage
#define GEMM_SMEM (2 * STE * 2)        // 61440 bytes

__device__ __forceinline__ void gemm_tile128(
    const __half* __restrict__ Ahi, const __half* __restrict__ Alo,
    const __half* __restrict__ Bh,
    const float* __restrict__ bias, float* __restrict__ C,
    int m0, int n0, int N, int K, uint32_t sb)
{
    const int tid = threadIdx.x, lane = tid & 31, wid = tid >> 5;
    const int wm = wid >> 1, wn = wid & 1;

    float c[2][8][4];
    #pragma unroll
    for (int i = 0; i < 2; i++)
        #pragma unroll
        for (int j = 0; j < 8; j++)
            #pragma unroll
            for (int q = 0; q < 4; q++) c[i][j][q] = 0.f;

    const int ld_row0 = tid >> 2;          // +64 for second half
    const int ld_col  = (tid & 3) * 8;

    const int r = lane & 7, g = lane >> 3;
    const int a_ld_row = (g & 1) * 8 + r;
    const int a_ld_k   = (g >> 1) * 8;
    const int b_ld_row = (g >> 1) * 8 + r;
    const int b_ld_k   = (g & 1) * 8;

    const int nit = K >> 5;

    // prologue stage 0
    {
        uint32_t base = sb;
        #pragma unroll
        for (int i = 0; i < 2; i++) {
            int row = ld_row0 + i * 64;
            uint32_t so = base + (uint32_t)(row * APAD + ld_col) * 2;
            size_t ga = (size_t)(m0 + row) * K + ld_col;
            size_t gb = (size_t)(n0 + row) * K + ld_col;
            cpa16(so + AHI_OFF * 2, Ahi + ga);
            cpa16(so + ALO_OFF * 2, Alo + ga);
            cpa16(so + BH_OFF * 2,  Bh + gb);
        }
        CPA_COMMIT();
    }

    for (int it = 0; it < nit; ++it) {
        if (it + 1 < nit) {
            uint32_t base = sb + (uint32_t)(((it + 1) & 1) * STE) * 2;
            int k0 = (it + 1) << 5;
            #pragma unroll
            for (int i = 0; i < 2; i++) {
                int row = ld_row0 + i * 64;
                uint32_t so = base + (uint32_t)(row * APAD + ld_col) * 2;
                size_t ga = (size_t)(m0 + row) * K + k0 + ld_col;
                size_t gb = (size_t)(n0 + row) * K + k0 + ld_col;
                cpa16(so + AHI_OFF * 2, Ahi + ga);
                cpa16(so + ALO_OFF * 2, Alo + ga);
                cpa16(so + BH_OFF * 2,  Bh + gb);
            }
            CPA_COMMIT();
            CPA_WAIT(1);
        } else {
            CPA_WAIT(0);
        }
        __syncthreads();

        uint32_t base = sb + (uint32_t)((it & 1) * STE) * 2;
        #pragma unroll
        for (int kk = 0; kk < 32; kk += 16) {
            uint32_t ah[2][4], al[2][4];
            #pragma unroll
            for (int mt = 0; mt < 2; mt++) {
                uint32_t ad = base + (uint32_t)((wm * 32 + mt * 16 + a_ld_row) * APAD + kk + a_ld_k) * 2;
                LDSM4(ah[mt][0], ah[mt][1], ah[mt][2], ah[mt][3], ad + AHI_OFF * 2);
                LDSM4(al[mt][0], al[mt][1], al[mt][2], al[mt][3], ad + ALO_OFF * 2);
            }
            #pragma unroll
            for (int np = 0; np < 4; np++) {
                uint32_t bh[4];
                uint32_t bd = base + (uint32_t)((wn * 64 + np * 16 + b_ld_row) * APAD + kk + b_ld_k) * 2;
                LDSM4(bh[0], bh[1], bh[2], bh[3], bd + BH_OFF * 2);
                #pragma unroll
                for (int mt = 0; mt < 2; mt++) {
                    MMAF16(c[mt][np * 2 + 0], ah[mt], bh[0], bh[1]);
                    MMAF16(c[mt][np * 2 + 1], ah[mt], bh[2], bh[3]);
                    MMAF16(c[mt][np * 2 + 0], al[mt], bh[0], bh[1]);
                    MMAF16(c[mt][np * 2 + 1], al[mt], bh[2], bh[3]);
                }
            }
        }
        __syncthreads();
    }

    // epilogue
    #pragma unroll
    for (int mt = 0; mt < 2; mt++) {
        int row = m0 + wm * 32 + mt * 16 + (lane >> 2);
        #pragma unroll
        for (int nt = 0; nt < 8; nt++) {
            int col = n0 + wn * 64 + nt * 8 + (lane & 3) * 2;
            float2 bv = *(const float2*)(bias + col);
            float2 v0, v1;
            v0.x = c[mt][nt][0] + bv.x; v0.y = c[mt][nt][1] + bv.y;
            v1.x = c[mt][nt][2] + bv.x; v1.y = c[mt][nt][3] + bv.y;
            *(float2*)(C + (size_t)row * N + col) = v0;
            *(float2*)(C + (size_t)(row + 8) * N + col) = v1;
        }
    }
}

// fused Q/K/V projection: grid (13, 64)
__global__ __launch_bounds__(256, 2)
void gemm_qkv(const __half* __restrict__ qhi, const __half* __restrict__ qlo,
              const __half* __restrict__ khi, const __half* __restrict__ klo,
              const __half* __restrict__ vhi, const __half* __restrict__ vlo,
              const __half* __restrict__ wq, const __half* __restrict__ wk,
              const __half* __restrict__ wv,
              const float* __restrict__ bqp, const float* __restrict__ bkp, const float* __restrict__ bv,
              float* __restrict__ qp, float* __restrict__ kp, float* __restrict__ vp)
{
    extern __shared__ __half sm[];
    uint32_t sb = smem_u32(sm);
    const int m0 = blockIdx.y * 128;
    const int rr = blockIdx.x;
    if (rr < 3)
        gemm_tile128(qhi, qlo, wq, bqp, qp, m0, rr * 128, NQKP, DMODEL, sb);
    else if (rr < 6)
        gemm_tile128(khi, klo, wk, bkp, kp, m0, (rr - 3) * 128, NQKP, DMODEL, sb);
    else
        gemm_tile128(vhi, vlo, wv, bv, vp, m0, (rr - 6) * 128, NV, DMODEL, sb);
}

// output projection: grid (8, 64)
__global__ __launch_bounds__(256, 2)
void gemm_out(const __half* __restrict__ Ahi, const __half* __restrict__ Alo,
              const __half* __restrict__ Bh,
              const float* __restrict__ bias, float* __restrict__ C)
{
    extern __shared__ __half sm[];
    uint32_t sb = smem_u32(sm);
    gemm_tile128(Ahi, Alo, Bh, bias, C, blockIdx.y * 128, blockIdx.x * 128, DMODEL, NV, sb);
}

// ---------------- tiled banded attention (writes fp16 hi/lo) ------------------
#define ATTN_FIXED (2048 + 1024 + 1056 + 1056 + 1024 + 32)

template <int DILT, bool DYN>
__device__ __forceinline__ void attn_body(
    const float* __restrict__ qp, const float* __restrict__ kp,
    const float* __restrict__ vp, const float* __restrict__ Ws,
    const float* __restrict__ bsg,
    __half* __restrict__ ohi, __half* __restrict__ olo,
    int h, int dil_rt)
{
    const int DIL = DYN ? dil_rt : DILT;
    const int WIN = 31 * DIL + 32;
    extern __shared__ float sa[];
    float* swin  = sa;
    float* sq    = swin + WIN * 64;
    float* sws   = sq + 2048;
    float* ssc   = sws + 1024;
    float* ssm   = ssc + 1056;
    float* satt  = ssm + 1056;
    float* sbs   = satt + 1024;

    const int l0 = blockIdx.x * 32;
    const int b  = blockIdx.y;
    const int s  = (h < 5) ? 0 : (h < 10) ? 1 : (h < 12) ? 2 : (h == 12) ? 3 : 4;
    const int tid = threadIdx.x, lane = tid & 31;
    const int w0 = l0 - 16 * DIL;
    const long rowbase = (long)b * L_SZ + l0;

    {
        int idx = tid;
        #pragma unroll
        for (int p = 0; p < 2; p++, idx += 256) {
            int row = idx >> 4, q4 = (idx & 15) * 4;
            *(float4*)(sq + row * 64 + q4) =
                *(const float4*)(qp + (rowbase + row) * NQKP + s * 64 + q4);
        }
        *(float4*)(sws + tid * 4) = *(const float4*)(Ws + (size_t)h * 1024 + tid * 4);
        if (tid < 32) sbs[tid] = bsg[h * KW + tid];
    }
    for (int r = tid >> 4; r < WIN; r += 16) {
        int g = w0 + r; g = g < 0 ? 0 : (g > L_SZ - 1 ? L_SZ - 1 : g);
        int q4 = (tid & 15) * 4;
        *(float4*)(swin + r * 64 + q4) =
            *(const float4*)(kp + ((long)b * L_SZ + g) * NQKP + s * 64 + q4);
    }
    __syncthreads();

    {
        const int li = tid >> 3;
        const int kb = (tid & 7) * 4;
        float acc0 = 0.f, acc1 = 0.f, acc2 = 0.f, acc3 = 0.f;
        const float* qrow = sq + li * 64;
        const float* wr0 = swin + (li + (kb + 0) * DIL) * 64;
        const float* wr1 = swin + (li + (kb + 1) * DIL) * 64;
        const float* wr2 = swin + (li + (kb + 2) * DIL) * 64;
        const float* wr3 = swin + (li + (kb + 3) * DIL) * 64;
        #pragma unroll
        for (int t4 = 0; t4 < 16; t4++) {
            int i = ((t4 + lane) & 15) * 4;
            float4 qv = *(const float4*)(qrow + i);
            float4 v0 = *(const float4*)(wr0 + i);
            float4 v1 = *(const float4*)(wr1 + i);
            float4 v2 = *(const float4*)(wr2 + i);
            float4 v3 = *(const float4*)(wr3 + i);
            acc0 += qv.x * v0.x + qv.y * v0.y + qv.z * v0.z + qv.w * v0.w;
            acc1 += qv.x * v1.x + qv.y * v1.y + qv.z * v1.z + qv.w * v1.w;
            acc2 += qv.x * v2.x + qv.y * v2.y + qv.z * v2.z + qv.w * v2.w;
            acc3 += qv.x * v3.x + qv.y * v3.y + qv.z * v3.z + qv.w * v3.w;
        }
        ssc[li * 33 + kb + 0] = acc0 * 0.125f;
        ssc[li * 33 + kb + 1] = acc1 * 0.125f;
        ssc[li * 33 + kb + 2] = acc2 * 0.125f;
        ssc[li * 33 + kb + 3] = acc3 * 0.125f;
    }
    __syncthreads();

    for (int r = tid >> 4; r < WIN; r += 16) {
        int g = w0 + r; g = g < 0 ? 0 : (g > L_SZ - 1 ? L_SZ - 1 : g);
        int q4 = (tid & 15) * 4;
        *(float4*)(swin + r * 64 + q4) =
            *(const float4*)(vp + ((long)b * L_SZ + g) * NV + h * 64 + q4);
    }

    {
        const int li = tid >> 3;
        const int m4 = (tid & 7) * 4;
        float a0 = sbs[m4], a1 = sbs[m4 + 1], a2 = sbs[m4 + 2], a3 = sbs[m4 + 3];
        #pragma unroll 8
        for (int k = 0; k < 32; k++) {
            float scv = ssc[li * 33 + k];
            float4 wv = *(const float4*)(sws + k * 32 + m4);
            a0 += scv * wv.x; a1 += scv * wv.y; a2 += scv * wv.z; a3 += scv * wv.w;
        }
        ssm[li * 33 + m4 + 0] = a0;
        ssm[li * 33 + m4 + 1] = a1;
        ssm[li * 33 + m4 + 2] = a2;
        ssm[li * 33 + m4 + 3] = a3;
    }
    __syncthreads();

    {
        const int w = tid >> 5;
        #pragma unroll
        for (int rr = 0; rr < 4; rr++) {
            int li = w * 4 + rr;
            float v = ssm[li * 33 + lane];
            float mx = v;
            #pragma unroll
            for (int o = 16; o; o >>= 1) mx = fmaxf(mx, __shfl_xor_sync(0xffffffffu, mx, o));
            float e = __expf(v - mx);
            float ss = e;
            #pragma unroll
            for (int o = 16; o; o >>= 1) ss += __shfl_xor_sync(0xffffffffu, ss, o);
            satt[li * 32 + lane] = e / ss;
        }
    }
    __syncthreads();

    {
        const int li = tid >> 3;
        const int io = (tid & 7) * 8;
        float4 a0 = make_float4(0.f, 0.f, 0.f, 0.f);
        float4 a1 = make_float4(0.f, 0.f, 0.f, 0.f);
        #pragma unroll 8
        for (int k = 0; k < 32; k++) {
            float wv = satt[li * 32 + k];
            const float* vr = swin + (li + k * DIL) * 64 + io;
            float4 v0 = *(const float4*)(vr);
            float4 v1 = *(const float4*)(vr + 4);
            a0.x += wv * v0.x; a0.y += wv * v0.y; a0.z += wv * v0.z; a0.w += wv * v0.w;
            a1.x += wv * v1.x; a1.y += wv * v1.y; a1.z += wv * v1.z; a1.w += wv * v1.w;
        }
        float r0, r1, r2, r3, r4, r5, r6, r7;
        uint4 hv, lv;
        hv.x = pack_hi2(a0.x, a0.y, r0, r1);
        hv.y = pack_hi2(a0.z, a0.w, r2, r3);
        hv.z = pack_hi2(a1.x, a1.y, r4, r5);
        hv.w = pack_hi2(a1.z, a1.w, r6, r7);
        lv.x = pack2(r0, r1); lv.y = pack2(r2, r3);
        lv.z = pack2(r4, r5); lv.w = pack2(r6, r7);
        size_t off = (rowbase + li) * NV + h * 64 + io;
        *(uint4*)(ohi + off) = hv;
        *(uint4*)(olo + off) = lv;
    }
}

__global__ __launch_bounds__(256)
void attn_d1(const float* __restrict__ qp, const float* __restrict__ kp,
             const float* __restrict__ vp, const float* __restrict__ Ws,
             const float* __restrict__ bsg,
             __half* __restrict__ ohi, __half* __restrict__ olo)
{
    attn_body<1, false>(qp, kp, vp, Ws, bsg, ohi, olo, blockIdx.z, 1);
}

__global__ __launch_bounds__(256)
void attn_dyn(const float* __restrict__ qp, const float* __restrict__ kp,
              const float* __restrict__ vp, const float* __restrict__ Ws,
              const float* __restrict__ bsg,
              __half* __restrict__ ohi, __half* __restrict__ olo)
{
    const int z = blockIdx.z;                 // 0..3 -> heads 10..13
    const int h = 10 + z;
    const int dil = (z < 2) ? 2 : (z == 2 ? 4 : 8);
    attn_body<0, true>(qp, kp, vp, Ws, bsg, ohi, olo, h, dil);
}

// ---------------- launcher ---------------------------------------------------
extern "C" void kernel_launch(void* const* d_in, const int* in_sizes, int n_in,
                              void* d_out, int out_size)
{
    const float* query = (const float*)d_in[0];
    const float* key   = (const float*)d_in[1];
    const float* value = (const float*)d_in[2];
    const float* Wq    = (const float*)d_in[3];
    const float* bq    = (const float*)d_in[4];
    const float* Wk    = (const float*)d_in[5];
    const float* bk    = (const float*)d_in[6];
    const float* Wv    = (const float*)d_in[7];
    const float* bv    = (const float*)d_in[8];
    const float* Ws    = (const float*)d_in[9];
    const float* bs    = (const float*)d_in[10];
    const float* Wc    = (const float*)d_in[11];
    const float* bc    = (const float*)d_in[12];
    float* out = (float*)d_out;

    float *qp, *kp, *vp, *bqp, *bkp;
    __half *qahi, *qalo, *kahi, *kalo, *vahi, *valo, *oahi, *oalo;
    __half *wq, *wk, *wv, *wc;
    cudaGetSymbolAddress((void**)&qp, g_qp);
    cudaGetSymbolAddress((void**)&kp, g_kp);
    cudaGetSymbolAddress((void**)&vp, g_vp);
    cudaGetSymbolAddress((void**)&bqp, g_bqp);
    cudaGetSymbolAddress((void**)&bkp, g_bkp);
    cudaGetSymbolAddress((void**)&qahi, g_qahi); cudaGetSymbolAddress((void**)&qalo, g_qalo);
    cudaGetSymbolAddress((void**)&kahi, g_kahi); cudaGetSymbolAddress((void**)&kalo, g_kalo);
    cudaGetSymbolAddress((void**)&vahi, g_vahi); cudaGetSymbolAddress((void**)&valo, g_valo);
    cudaGetSymbolAddress((void**)&oahi, g_oahi); cudaGetSymbolAddress((void**)&oalo, g_oalo);
    cudaGetSymbolAddress((void**)&wq, g_wq);
    cudaGetSymbolAddress((void**)&wk, g_wk);
    cudaGetSymbolAddress((void**)&wv, g_wv);
    cudaGetSymbolAddress((void**)&wc, g_wc);

    cudaFuncSetAttribute(gemm_qkv, cudaFuncAttributeMaxDynamicSharedMemorySize, GEMM_SMEM);
    cudaFuncSetAttribute(gemm_out, cudaFuncAttributeMaxDynamicSharedMemorySize, GEMM_SMEM);

    auto asz = [](int dil) { return (size_t)((31 * dil + 32) * 64 + ATTN_FIXED) * 4; };
    cudaFuncSetAttribute(attn_d1,  cudaFuncAttributeMaxDynamicSharedMemorySize, (int)asz(1));
    cudaFuncSetAttribute(attn_dyn, cudaFuncAttributeMaxDynamicSharedMemorySize, (int)asz(8));

    const int nact8 = ML * DMODEL / 8;

    // ---- conversions ----
    conv_act3<<<dim3((nact8 + 255) / 256, 3), 256>>>(
        (const float4*)query, (const float4*)key, (const float4*)value,
        (uint4*)qahi, (uint4*)qalo, (uint4*)kahi, (uint4*)kalo, (uint4*)vahi, (uint4*)valo, nact8);
    conv_w_seg<<<NQKP, 256>>>(Wq, wq, DMODEL, NQK);
    conv_w_seg<<<NQKP, 256>>>(Wk, wk, DMODEL, NQK);
    conv_w_seg<<<NV, 256>>>(Wv, wv, DMODEL, NV);
    pad_bias<<<1, NQKP>>>(bq, bk, bqp, bkp);

    // ---- fused Q/K/V projection (128x128 tiles, 2-pass fp16 split) ----
    gemm_qkv<<<dim3(13, 64), 256, GEMM_SMEM>>>(qahi, qalo, kahi, kalo, vahi, valo,
                                               wq, wk, wv, bqp, bkp, bv, qp, kp, vp);

    // ---- tiled attention ----
    attn_d1<<<dim3(L_SZ / 32, B_SZ, 10), 256, asz(1)>>>(qp, kp, vp, Ws, bs, oahi, oalo);
    attn_dyn<<<dim3(L_SZ / 32, B_SZ, 4), 256, asz(8)>>>(qp, kp, vp, Ws, bs, oahi, oalo);

    // ---- output projection ----
    conv_w_t<<<DMODEL, 256>>>(Wc, wc, NV, DMODEL);
    gemm_out<<<dim3(8, 64), 256, GEMM_SMEM>>>(oahi, oalo, wc, bc, out);
}

// round 8
// speedup vs baseline: 5.1122x; 1.3625x over previous
#include <cuda_runtime.h>
#include <cuda_fp16.h>
#include <cstdint>

// Problem constants
#define B_SZ   2
#define L_SZ   4096
#define DMODEL 1024
#define DINT   64
#define KW     32
#define SUBH   5
#define HEADS  14
#define ML     (B_SZ * L_SZ)          // 8192 rows
#define NQK    320
#define NQKP   384                    // padded to 3*128
#define NV     896

// ---------------- scratch (static device globals; no allocation) -------------
__device__ float g_qp[ML * NQKP];
__device__ float g_kp[ML * NQKP];
__device__ float g_vp[ML * NV];
__device__ __half g_qa[ML * DMODEL];
__device__ __half g_ka[ML * DMODEL];
__device__ __half g_va[ML * DMODEL];
__device__ __half g_oa[ML * NV];
__device__ __half g_wq[NQKP * DMODEL];
__device__ __half g_wk[NQKP * DMODEL];
__device__ __half g_wv[NV * DMODEL];
__device__ __half g_wc[DMODEL * NV];
__device__ float g_bqp[NQKP], g_bkp[NQKP];

// ---------------- helpers ------------------------------------------------
__device__ __forceinline__ uint32_t smem_u32(const void* p) {
    uint32_t a;
    asm("{ .reg .u64 t; cvta.to.shared.u64 t, %1; cvt.u32.u64 %0, t; }" : "=r"(a) : "l"(p));
    return a;
}
__device__ __forceinline__ void cpa16(uint32_t s, const void* g) {
    asm volatile("cp.async.cg.shared.global [%0], [%1], 16;" :: "r"(s), "l"(g));
}
#define CPA_COMMIT() asm volatile("cp.async.commit_group;" ::: "memory")
#define CPA_WAIT(n)  asm volatile("cp.async.wait_group %0;" :: "n"(n) : "memory")

#define LDSM4(r0, r1, r2, r3, a) \
    asm volatile("ldmatrix.sync.aligned.m8n8.x4.shared.b16 {%0,%1,%2,%3}, [%4];" \
        : "=r"(r0), "=r"(r1), "=r"(r2), "=r"(r3) : "r"(a))

#define MMAF16(c, a, b0, b1) \
    asm volatile("mma.sync.aligned.m16n8k16.row.col.f32.f16.f16.f32 " \
        "{%0,%1,%2,%3},{%4,%5,%6,%7},{%8,%9},{%0,%1,%2,%3};" \
        : "+f"((c)[0]), "+f"((c)[1]), "+f"((c)[2]), "+f"((c)[3]) \
        : "r"((a)[0]), "r"((a)[1]), "r"((a)[2]), "r"((a)[3]), "r"(b0), "r"(b1))

__device__ __forceinline__ uint32_t pack2(float a, float b) {
    __half2 h;
    h.x = __float2half_rn(a); h.y = __float2half_rn(b);
    return *(uint32_t*)&h;
}

// ---------------- conversion kernels -----------------------------------------
// fused q/k/v fp32 -> fp16 (blockIdx.y selects source)
__global__ __launch_bounds__(256)
void conv_act3(const float4* __restrict__ q, const float4* __restrict__ k,
               const float4* __restrict__ v,
               uint4* __restrict__ qo, uint4* __restrict__ ko, uint4* __restrict__ vo, int n8)
{
    int i = blockIdx.x * 256 + threadIdx.x;
    if (i >= n8) return;
    const float4* in; uint4* o;
    if (blockIdx.y == 0)      { in = q; o = qo; }
    else if (blockIdx.y == 1) { in = k; o = ko; }
    else                      { in = v; o = vo; }
    float4 a = in[2 * i], b = in[2 * i + 1];
    uint4 h;
    h.x = pack2(a.x, a.y);
    h.y = pack2(a.z, a.w);
    h.z = pack2(b.x, b.y);
    h.w = pack2(b.z, b.w);
    o[i] = h;
}

// W [heads, K, 64] -> Bt [Npad, K] fp16 (zero rows >= Nreal)
__global__ __launch_bounds__(256)
void conv_w_seg(const float* __restrict__ W, __half* __restrict__ bh, int K, int Nreal)
{
    int n = blockIdx.x;
    if (n >= Nreal) {
        for (int kk = threadIdx.x; kk < K; kk += 256)
            bh[(size_t)n * K + kk] = __float2half(0.f);
        return;
    }
    int head = n >> 6, i = n & 63;
    for (int kk = threadIdx.x; kk < K; kk += 256)
        bh[(size_t)n * K + kk] = __float2half_rn(W[((size_t)head * K + kk) * 64 + i]);
}

// Wc [K, N] -> Bt [N, K] fp16 (transpose)
__global__ __launch_bounds__(256)
void conv_w_t(const float* __restrict__ W, __half* __restrict__ bh, int K, int Ntot)
{
    int n = blockIdx.x;
    for (int k = threadIdx.x; k < K; k += 256)
        bh[(size_t)n * K + k] = __float2half_rn(W[(size_t)k * Ntot + n]);
}

__global__ void pad_bias(const float* __restrict__ bq, const float* __restrict__ bk,
                         float* __restrict__ bqp, float* __restrict__ bkp)
{
    int i = threadIdx.x;
    if (i < NQKP) {
        bqp[i] = (i < NQK) ? bq[i] : 0.f;
        bkp[i] = (i < NQK) ? bk[i] : 0.f;
    }
}

// ---------------- fp16 HMMA GEMM, 128x128 tile, single pass -------------------
#define APAD 40
#define A_OFF 0
#define B_OFF 5120
#define STE   10240                   // half-elems per stage
#define GEMM_SMEM (2 * STE * 2)       // 40960 bytes

__device__ __forceinline__ void gemm_tile128(
    const __half* __restrict__ A, const __half* __restrict__ B,
    const float* __restrict__ bias, float* __restrict__ C,
    int m0, int n0, int N, int K, uint32_t sb)
{
    const int tid = threadIdx.x, lane = tid & 31, wid = tid >> 5;
    const int wm = wid >> 1, wn = wid & 1;

    float c[2][8][4];
    #pragma unroll
    for (int i = 0; i < 2; i++)
        #pragma unroll
        for (int j = 0; j < 8; j++)
            #pragma unroll
            for (int q = 0; q < 4; q++) c[i][j][q] = 0.f;

    const int ld_row0 = tid >> 2;          // +64 for second half
    const int ld_col  = (tid & 3) * 8;

    const int r = lane & 7, g = lane >> 3;
    const int a_ld_row = (g & 1) * 8 + r;
    const int a_ld_k   = (g >> 1) * 8;
    const int b_ld_row = (g >> 1) * 8 + r;
    const int b_ld_k   = (g & 1) * 8;

    const int nit = K >> 5;

    // prologue stage 0
    {
        uint32_t base = sb;
        #pragma unroll
        for (int i = 0; i < 2; i++) {
            int row = ld_row0 + i * 64;
            uint32_t so = base + (uint32_t)(row * APAD + ld_col) * 2;
            cpa16(so + A_OFF * 2, A + (size_t)(m0 + row) * K + ld_col);
            cpa16(so + B_OFF * 2, B + (size_t)(n0 + row) * K + ld_col);
        }
        CPA_COMMIT();
    }

    for (int it = 0; it < nit; ++it) {
        if (it + 1 < nit) {
            uint32_t base = sb + (uint32_t)(((it + 1) & 1) * STE) * 2;
            int k0 = (it + 1) << 5;
            #pragma unroll
            for (int i = 0; i < 2; i++) {
                int row = ld_row0 + i * 64;
                uint32_t so = base + (uint32_t)(row * APAD + ld_col) * 2;
                cpa16(so + A_OFF * 2, A + (size_t)(m0 + row) * K + k0 + ld_col);
                cpa16(so + B_OFF * 2, B + (size_t)(n0 + row) * K + k0 + ld_col);
            }
            CPA_COMMIT();
            CPA_WAIT(1);
        } else {
            CPA_WAIT(0);
        }
        __syncthreads();

        uint32_t base = sb + (uint32_t)((it & 1) * STE) * 2;
        #pragma unroll
        for (int kk = 0; kk < 32; kk += 16) {
            uint32_t ah[2][4];
            #pragma unroll
            for (int mt = 0; mt < 2; mt++) {
                uint32_t ad = base + (uint32_t)((wm * 32 + mt * 16 + a_ld_row) * APAD + kk + a_ld_k) * 2;
                LDSM4(ah[mt][0], ah[mt][1], ah[mt][2], ah[mt][3], ad + A_OFF * 2);
            }
            #pragma unroll
            for (int np = 0; np < 4; np++) {
                uint32_t bh[4];
                uint32_t bd = base + (uint32_t)((wn * 64 + np * 16 + b_ld_row) * APAD + kk + b_ld_k) * 2;
                LDSM4(bh[0], bh[1], bh[2], bh[3], bd + B_OFF * 2);
                #pragma unroll
                for (int mt = 0; mt < 2; mt++) {
                    MMAF16(c[mt][np * 2 + 0], ah[mt], bh[0], bh[1]);
                    MMAF16(c[mt][np * 2 + 1], ah[mt], bh[2], bh[3]);
                }
            }
        }
        __syncthreads();
    }

    // epilogue
    #pragma unroll
    for (int mt = 0; mt < 2; mt++) {
        int row = m0 + wm * 32 + mt * 16 + (lane >> 2);
        #pragma unroll
        for (int nt = 0; nt < 8; nt++) {
            int col = n0 + wn * 64 + nt * 8 + (lane & 3) * 2;
            float2 bv = *(const float2*)(bias + col);
            float2 v0, v1;
            v0.x = c[mt][nt][0] + bv.x; v0.y = c[mt][nt][1] + bv.y;
            v1.x = c[mt][nt][2] + bv.x; v1.y = c[mt][nt][3] + bv.y;
            *(float2*)(C + (size_t)row * N + col) = v0;
            *(float2*)(C + (size_t)(row + 8) * N + col) = v1;
        }
    }
}

// fused Q/K/V projection: grid (13, 64)
__global__ __launch_bounds__(256, 2)
void gemm_qkv(const __half* __restrict__ qa, const __half* __restrict__ ka,
              const __half* __restrict__ va,
              const __half* __restrict__ wq, const __half* __restrict__ wk,
              const __half* __restrict__ wv,
              const float* __restrict__ bqp, const float* __restrict__ bkp, const float* __restrict__ bv,
              float* __restrict__ qp, float* __restrict__ kp, float* __restrict__ vp)
{
    extern __shared__ __half sm[];
    uint32_t sb = smem_u32(sm);
    const int m0 = blockIdx.y * 128;
    const int rr = blockIdx.x;
    if (rr < 3)
        gemm_tile128(qa, wq, bqp, qp, m0, rr * 128, NQKP, DMODEL, sb);
    else if (rr < 6)
        gemm_tile128(ka, wk, bkp, kp, m0, (rr - 3) * 128, NQKP, DMODEL, sb);
    else
        gemm_tile128(va, wv, bv, vp, m0, (rr - 6) * 128, NV, DMODEL, sb);
}

// output projection: grid (8, 64)
__global__ __launch_bounds__(256, 2)
void gemm_out(const __half* __restrict__ A, const __half* __restrict__ B,
              const float* __restrict__ bias, float* __restrict__ C)
{
    extern __shared__ __half sm[];
    uint32_t sb = smem_u32(sm);
    gemm_tile128(A, B, bias, C, blockIdx.y * 128, blockIdx.x * 128, DMODEL, NV, sb);
}

// ---------------- tiled banded attention (writes fp16) ------------------------
#define ATTN_FIXED (2048 + 1024 + 1056 + 1056 + 1024 + 32)

template <int DILT, bool DYN>
__device__ __forceinline__ void attn_body(
    const float* __restrict__ qp, const float* __restrict__ kp,
    const float* __restrict__ vp, const float* __restrict__ Ws,
    const float* __restrict__ bsg, __half* __restrict__ oa,
    int h, int dil_rt)
{
    const int DIL = DYN ? dil_rt : DILT;
    const int WIN = 31 * DIL + 32;
    extern __shared__ float sa[];
    float* swin  = sa;
    float* sq    = swin + WIN * 64;
    float* sws   = sq + 2048;
    float* ssc   = sws + 1024;
    float* ssm   = ssc + 1056;
    float* satt  = ssm + 1056;
    float* sbs   = satt + 1024;

    const int l0 = blockIdx.x * 32;
    const int b  = blockIdx.y;
    const int s  = (h < 5) ? 0 : (h < 10) ? 1 : (h < 12) ? 2 : (h == 12) ? 3 : 4;
    const int tid = threadIdx.x, lane = tid & 31;
    const int w0 = l0 - 16 * DIL;
    const long rowbase = (long)b * L_SZ + l0;

    {
        int idx = tid;
        #pragma unroll
        for (int p = 0; p < 2; p++, idx += 256) {
            int row = idx >> 4, q4 = (idx & 15) * 4;
            *(float4*)(sq + row * 64 + q4) =
                *(const float4*)(qp + (rowbase + row) * NQKP + s * 64 + q4);
        }
        *(float4*)(sws + tid * 4) = *(const float4*)(Ws + (size_t)h * 1024 + tid * 4);
        if (tid < 32) sbs[tid] = bsg[h * KW + tid];
    }
    for (int r = tid >> 4; r < WIN; r += 16) {
        int g = w0 + r; g = g < 0 ? 0 : (g > L_SZ - 1 ? L_SZ - 1 : g);
        int q4 = (tid & 15) * 4;
        *(float4*)(swin + r * 64 + q4) =
            *(const float4*)(kp + ((long)b * L_SZ + g) * NQKP + s * 64 + q4);
    }
    __syncthreads();

    {
        const int li = tid >> 3;
        const int kb = (tid & 7) * 4;
        float acc0 = 0.f, acc1 = 0.f, acc2 = 0.f, acc3 = 0.f;
        const float* qrow = sq + li * 64;
        const float* wr0 = swin + (li + (kb + 0) * DIL) * 64;
        const float* wr1 = swin + (li + (kb + 1) * DIL) * 64;
        const float* wr2 = swin + (li + (kb + 2) * DIL) * 64;
        const float* wr3 = swin + (li + (kb + 3) * DIL) * 64;
        #pragma unroll
        for (int t4 = 0; t4 < 16; t4++) {
            int i = ((t4 + lane) & 15) * 4;
            float4 qv = *(const float4*)(qrow + i);
            float4 v0 = *(const float4*)(wr0 + i);
            float4 v1 = *(const float4*)(wr1 + i);
            float4 v2 = *(const float4*)(wr2 + i);
            float4 v3 = *(const float4*)(wr3 + i);
            acc0 += qv.x * v0.x + qv.y * v0.y + qv.z * v0.z + qv.w * v0.w;
            acc1 += qv.x * v1.x + qv.y * v1.y + qv.z * v1.z + qv.w * v1.w;
            acc2 += qv.x * v2.x + qv.y * v2.y + qv.z * v2.z + qv.w * v2.w;
            acc3 += qv.x * v3.x + qv.y * v3.y + qv.z * v3.z + qv.w * v3.w;
        }
        ssc[li * 33 + kb + 0] = acc0 * 0.125f;
        ssc[li * 33 + kb + 1] = acc1 * 0.125f;
        ssc[li * 33 + kb + 2] = acc2 * 0.125f;
        ssc[li * 33 + kb + 3] = acc3 * 0.125f;
    }
    __syncthreads();

    for (int r = tid >> 4; r < WIN; r += 16) {
        int g = w0 + r; g = g < 0 ? 0 : (g > L_SZ - 1 ? L_SZ - 1 : g);
        int q4 = (tid & 15) * 4;
        *(float4*)(swin + r * 64 + q4) =
            *(const float4*)(vp + ((long)b * L_SZ + g) * NV + h * 64 + q4);
    }

    {
        const int li = tid >> 3;
        const int m4 = (tid & 7) * 4;
        float a0 = sbs[m4], a1 = sbs[m4 + 1], a2 = sbs[m4 + 2], a3 = sbs[m4 + 3];
        #pragma unroll 8
        for (int k = 0; k < 32; k++) {
            float scv = ssc[li * 33 + k];
            float4 wv = *(const float4*)(sws + k * 32 + m4);
            a0 += scv * wv.x; a1 += scv * wv.y; a2 += scv * wv.z; a3 += scv * wv.w;
        }
        ssm[li * 33 + m4 + 0] = a0;
        ssm[li * 33 + m4 + 1] = a1;
        ssm[li * 33 + m4 + 2] = a2;
        ssm[li * 33 + m4 + 3] = a3;
    }
    __syncthreads();

    {
        const int w = tid >> 5;
        #pragma unroll
        for (int rr = 0; rr < 4; rr++) {
            int li = w * 4 + rr;
            float v = ssm[li * 33 + lane];
            float mx = v;
            #pragma unroll
            for (int o = 16; o; o >>= 1) mx = fmaxf(mx, __shfl_xor_sync(0xffffffffu, mx, o));
            float e = __expf(v - mx);
            float ss = e;
            #pragma unroll
            for (int o = 16; o; o >>= 1) ss += __shfl_xor_sync(0xffffffffu, ss, o);
            satt[li * 32 + lane] = e / ss;
        }
    }
    __syncthreads();

    {
        const int li = tid >> 3;
        const int io = (tid & 7) * 8;
        float4 a0 = make_float4(0.f, 0.f, 0.f, 0.f);
        float4 a1 = make_float4(0.f, 0.f, 0.f, 0.f);
        #pragma unroll 8
        for (int k = 0; k < 32; k++) {
            float wv = satt[li * 32 + k];
            const float* vr = swin + (li + k * DIL) * 64 + io;
            float4 v0 = *(const float4*)(vr);
            float4 v1 = *(const float4*)(vr + 4);
            a0.x += wv * v0.x; a0.y += wv * v0.y; a0.z += wv * v0.z; a0.w += wv * v0.w;
            a1.x += wv * v1.x; a1.y += wv * v1.y; a1.z += wv * v1.z; a1.w += wv * v1.w;
        }
        uint4 hv;
        hv.x = pack2(a0.x, a0.y);
        hv.y = pack2(a0.z, a0.w);
        hv.z = pack2(a1.x, a1.y);
        hv.w = pack2(a1.z, a1.w);
        *(uint4*)(oa + (rowbase + li) * NV + h * 64 + io) = hv;
    }
}

__global__ __launch_bounds__(256)
void attn_d1(const float* __restrict__ qp, const float* __restrict__ kp,
             const float* __restrict__ vp, const float* __restrict__ Ws,
             const float* __restrict__ bsg, __half* __restrict__ oa)
{
    attn_body<1, false>(qp, kp, vp, Ws, bsg, oa, blockIdx.z, 1);
}

__global__ __launch_bounds__(256)
void attn_dyn(const float* __restrict__ qp, const float* __restrict__ kp,
              const float* __restrict__ vp, const float* __restrict__ Ws,
              const float* __restrict__ bsg, __half* __restrict__ oa)
{
    const int z = blockIdx.z;                 // 0..3 -> heads 10..13
    const int h = 10 + z;
    const int dil = (z < 2) ? 2 : (z == 2 ? 4 : 8);
    attn_body<0, true>(qp, kp, vp, Ws, bsg, oa, h, dil);
}

// ---------------- launcher ---------------------------------------------------
extern "C" void kernel_launch(void* const* d_in, const int* in_sizes, int n_in,
                              void* d_out, int out_size)
{
    const float* query = (const float*)d_in[0];
    const float* key   = (const float*)d_in[1];
    const float* value = (const float*)d_in[2];
    const float* Wq    = (const float*)d_in[3];
    const float* bq    = (const float*)d_in[4];
    const float* Wk    = (const float*)d_in[5];
    const float* bk    = (const float*)d_in[6];
    const float* Wv    = (const float*)d_in[7];
    const float* bv    = (const float*)d_in[8];
    const float* Ws    = (const float*)d_in[9];
    const float* bs    = (const float*)d_in[10];
    const float* Wc    = (const float*)d_in[11];
    const float* bc    = (const float*)d_in[12];
    float* out = (float*)d_out;

    float *qp, *kp, *vp, *bqp, *bkp;
    __half *qa, *ka, *va, *oa, *wq, *wk, *wv, *wc;
    cudaGetSymbolAddress((void**)&qp, g_qp);
    cudaGetSymbolAddress((void**)&kp, g_kp);
    cudaGetSymbolAddress((void**)&vp, g_vp);
    cudaGetSymbolAddress((void**)&bqp, g_bqp);
    cudaGetSymbolAddress((void**)&bkp, g_bkp);
    cudaGetSymbolAddress((void**)&qa, g_qa);
    cudaGetSymbolAddress((void**)&ka, g_ka);
    cudaGetSymbolAddress((void**)&va, g_va);
    cudaGetSymbolAddress((void**)&oa, g_oa);
    cudaGetSymbolAddress((void**)&wq, g_wq);
    cudaGetSymbolAddress((void**)&wk, g_wk);
    cudaGetSymbolAddress((void**)&wv, g_wv);
    cudaGetSymbolAddress((void**)&wc, g_wc);

    cudaFuncSetAttribute(gemm_qkv, cudaFuncAttributeMaxDynamicSharedMemorySize, GEMM_SMEM);
    cudaFuncSetAttribute(gemm_out, cudaFuncAttributeMaxDynamicSharedMemorySize, GEMM_SMEM);

    auto asz = [](int dil) { return (size_t)((31 * dil + 32) * 64 + ATTN_FIXED) * 4; };
    cudaFuncSetAttribute(attn_d1,  cudaFuncAttributeMaxDynamicSharedMemorySize, (int)asz(1));
    cudaFuncSetAttribute(attn_dyn, cudaFuncAttributeMaxDynamicSharedMemorySize, (int)asz(8));

    const int nact8 = ML * DMODEL / 8;

    // ---- conversions ----
    conv_act3<<<dim3((nact8 + 255) / 256, 3), 256>>>(
        (const float4*)query, (const float4*)key, (const float4*)value,
        (uint4*)qa, (uint4*)ka, (uint4*)va, nact8);
    conv_w_seg<<<NQKP, 256>>>(Wq, wq, DMODEL, NQK);
    conv_w_seg<<<NQKP, 256>>>(Wk, wk, DMODEL, NQK);
    conv_w_seg<<<NV, 256>>>(Wv, wv, DMODEL, NV);
    pad_bias<<<1, NQKP>>>(bq, bk, bqp, bkp);

    // ---- fused Q/K/V projection (single-pass fp16 HMMA) ----
    gemm_qkv<<<dim3(13, 64), 256, GEMM_SMEM>>>(qa, ka, va, wq, wk, wv,
                                               bqp, bkp, bv, qp, kp, vp);

    // ---- tiled attention ----
    attn_d1<<<dim3(L_SZ / 32, B_SZ, 10), 256, asz(1)>>>(qp, kp, vp, Ws, bs, oa);
    attn_dyn<<<dim3(L_SZ / 32, B_SZ, 4), 256, asz(8)>>>(qp, kp, vp, Ws, bs, oa);

    // ---- output projection ----
    conv_w_t<<<DMODEL, 256>>>(Wc, wc, NV, DMODEL);
    gemm_out<<<dim3(8, 64), 256, GEMM_SMEM>>>(oa, wc, bc, out);
}

// round 11
// speedup vs baseline: 5.4468x; 1.0655x over previous
#include <cuda_runtime.h>
#include <cuda_fp16.h>
#include <cstdint>

// Problem constants
#define B_SZ   2
#define L_SZ   4096
#define DMODEL 1024
#define DINT   64
#define KW     32
#define SUBH   5
#define HEADS  14
#define ML     (B_SZ * L_SZ)          // 8192 rows
#define NQK    320
#define NQKP   384                    // padded to 3*128
#define NV     896

// ---------------- scratch (static device globals; no allocation) -------------
__device__ float g_qp[ML * NQKP];
__device__ float g_kp[ML * NQKP];
__device__ float g_vp[ML * NV];
__device__ float g_sc[SUBH * B_SZ * L_SZ * KW];   // per-subhead scores
__device__ __half g_qa[ML * DMODEL];
__device__ __half g_ka[ML * DMODEL];
__device__ __half g_va[ML * DMODEL];
__device__ __half g_oa[ML * NV];
__device__ __half g_wq[NQKP * DMODEL];
__device__ __half g_wk[NQKP * DMODEL];
__device__ __half g_wv[NV * DMODEL];
__device__ __half g_wc[DMODEL * NV];
__device__ float g_bqp[NQKP], g_bkp[NQKP];

// ---------------- helpers ------------------------------------------------
__device__ __forceinline__ uint32_t smem_u32(const void* p) {
    uint32_t a;
    asm("{ .reg .u64 t; cvta.to.shared.u64 t, %1; cvt.u32.u64 %0, t; }" : "=r"(a) : "l"(p));
    return a;
}
__device__ __forceinline__ void cpa16(uint32_t s, const void* g) {
    asm volatile("cp.async.cg.shared.global [%0], [%1], 16;" :: "r"(s), "l"(g));
}
#define CPA_COMMIT() asm volatile("cp.async.commit_group;" ::: "memory")
#define CPA_WAIT(n)  asm volatile("cp.async.wait_group %0;" :: "n"(n) : "memory")

#define LDSM4(r0, r1, r2, r3, a) \
    asm volatile("ldmatrix.sync.aligned.m8n8.x4.shared.b16 {%0,%1,%2,%3}, [%4];" \
        : "=r"(r0), "=r"(r1), "=r"(r2), "=r"(r3) : "r"(a))

#define MMAF16(c, a, b0, b1) \
    asm volatile("mma.sync.aligned.m16n8k16.row.col.f32.f16.f16.f32 " \
        "{%0,%1,%2,%3},{%4,%5,%6,%7},{%8,%9},{%0,%1,%2,%3};" \
        : "+f"((c)[0]), "+f"((c)[1]), "+f"((c)[2]), "+f"((c)[3]) \
        : "r"((a)[0]), "r"((a)[1]), "r"((a)[2]), "r"((a)[3]), "r"(b0), "r"(b1))

__device__ __forceinline__ uint32_t pack2(float a, float b) {
    __half2 h;
    h.x = __float2half_rn(a); h.y = __float2half_rn(b);
    return *(uint32_t*)&h;
}

// ---------------- conversion kernels -----------------------------------------
// fused q/k/v fp32 -> fp16, 16 elems/thread for MLP
__global__ __launch_bounds__(256)
void conv_act3(const float4* __restrict__ q, const float4* __restrict__ k,
               const float4* __restrict__ v,
               uint4* __restrict__ qo, uint4* __restrict__ ko, uint4* __restrict__ vo, int n8)
{
    const float4* in; uint4* o;
    if (blockIdx.y == 0)      { in = q; o = qo; }
    else if (blockIdx.y == 1) { in = k; o = ko; }
    else                      { in = v; o = vo; }
    int i = blockIdx.x * 512 + threadIdx.x;
    #pragma unroll
    for (int p = 0; p < 2; p++, i += 256) {
        if (i < n8) {
            float4 a = in[2 * i], b = in[2 * i + 1];
            uint4 h;
            h.x = pack2(a.x, a.y);
            h.y = pack2(a.z, a.w);
            h.z = pack2(b.x, b.y);
            h.w = pack2(b.z, b.w);
            o[i] = h;
        }
    }
}

// fused weight conversions + bias padding; grid = 2690 blocks
__global__ __launch_bounds__(256)
void conv_w_all(const float* __restrict__ Wq, const float* __restrict__ Wk,
                const float* __restrict__ Wv, const float* __restrict__ Wc,
                const float* __restrict__ bq, const float* __restrict__ bk,
                __half* __restrict__ wq, __half* __restrict__ wk,
                __half* __restrict__ wv, __half* __restrict__ wc,
                float* __restrict__ bqp, float* __restrict__ bkp)
{
    const int bidx = blockIdx.x, tid = threadIdx.x;
    if (bidx >= 2688) {
        const float* src = (bidx == 2688) ? bq : bk;
        float* dst = (bidx == 2688) ? bqp : bkp;
        for (int i = tid; i < NQKP; i += 256) dst[i] = (i < NQK) ? src[i] : 0.f;
        return;
    }
    if (bidx < 768) {                       // wq / wk, [SUBH,1024,64] -> [384,1024]
        const bool isq = (bidx < 384);
        const float* W = isq ? Wq : Wk;
        __half* dst = isq ? wq : wk;
        int n = isq ? bidx : (bidx - 384);  // FIXED: 384 not a power of 2, no masking
        if (n >= NQK) {
            for (int kk = tid; kk < DMODEL; kk += 256) dst[(size_t)n * DMODEL + kk] = __float2half(0.f);
            return;
        }
        int head = n >> 6, i = n & 63;
        for (int kk = tid; kk < DMODEL; kk += 256)
            dst[(size_t)n * DMODEL + kk] = __float2half_rn(W[((size_t)head * DMODEL + kk) * 64 + i]);
    } else if (bidx < 1664) {               // wv, [HEADS,1024,64] -> [896,1024]
        int n = bidx - 768;
        int head = n >> 6, i = n & 63;
        for (int kk = tid; kk < DMODEL; kk += 256)
            wv[(size_t)n * DMODEL + kk] = __float2half_rn(Wv[((size_t)head * DMODEL + kk) * 64 + i]);
    } else {                                // wc, [896,1024] -> [1024,896] transposed
        int n = bidx - 1664;
        for (int kk = tid; kk < NV; kk += 256)
            wc[(size_t)n * NV + kk] = __float2half_rn(Wc[(size_t)kk * DMODEL + n]);
    }
}

// ---------------- fp16 HMMA GEMM, 128x128 tile, single pass -------------------
#define APAD 40
#define A_OFF 0
#define B_OFF 5120
#define STE   10240                   // half-elems per stage
#define GEMM_SMEM (2 * STE * 2)       // 40960 bytes

__device__ __forceinline__ void gemm_tile128(
    const __half* __restrict__ A, const __half* __restrict__ B,
    const float* __restrict__ bias, float* __restrict__ C,
    int m0, int n0, int N, int K, uint32_t sb)
{
    const int tid = threadIdx.x, lane = tid & 31, wid = tid >> 5;
    const int wm = wid >> 1, wn = wid & 1;

    float c[2][8][4];
    #pragma unroll
    for (int i = 0; i < 2; i++)
        #pragma unroll
        for (int j = 0; j < 8; j++)
            #pragma unroll
            for (int q = 0; q < 4; q++) c[i][j][q] = 0.f;

    const int ld_row0 = tid >> 2;
    const int ld_col  = (tid & 3) * 8;

    const int r = lane & 7, g = lane >> 3;
    const int a_ld_row = (g & 1) * 8 + r;
    const int a_ld_k   = (g >> 1) * 8;
    const int b_ld_row = (g >> 1) * 8 + r;
    const int b_ld_k   = (g & 1) * 8;

    const int nit = K >> 5;

    {
        uint32_t base = sb;
        #pragma unroll
        for (int i = 0; i < 2; i++) {
            int row = ld_row0 + i * 64;
            uint32_t so = base + (uint32_t)(row * APAD + ld_col) * 2;
            cpa16(so + A_OFF * 2, A + (size_t)(m0 + row) * K + ld_col);
            cpa16(so + B_OFF * 2, B + (size_t)(n0 + row) * K + ld_col);
        }
        CPA_COMMIT();
    }

    for (int it = 0; it < nit; ++it) {
        if (it + 1 < nit) {
            uint32_t base = sb + (uint32_t)(((it + 1) & 1) * STE) * 2;
            int k0 = (it + 1) << 5;
            #pragma unroll
            for (int i = 0; i < 2; i++) {
                int row = ld_row0 + i * 64;
                uint32_t so = base + (uint32_t)(row * APAD + ld_col) * 2;
                cpa16(so + A_OFF * 2, A + (size_t)(m0 + row) * K + k0 + ld_col);
                cpa16(so + B_OFF * 2, B + (size_t)(n0 + row) * K + k0 + ld_col);
            }
            CPA_COMMIT();
            CPA_WAIT(1);
        } else {
            CPA_WAIT(0);
        }
        __syncthreads();

        uint32_t base = sb + (uint32_t)((it & 1) * STE) * 2;
        #pragma unroll
        for (int kk = 0; kk < 32; kk += 16) {
            uint32_t ah[2][4];
            #pragma unroll
            for (int mt = 0; mt < 2; mt++) {
                uint32_t ad = base + (uint32_t)((wm * 32 + mt * 16 + a_ld_row) * APAD + kk + a_ld_k) * 2;
                LDSM4(ah[mt][0], ah[mt][1], ah[mt][2], ah[mt][3], ad + A_OFF * 2);
            }
            #pragma unroll
            for (int np = 0; np < 4; np++) {
                uint32_t bh[4];
                uint32_t bd = base + (uint32_t)((wn * 64 + np * 16 + b_ld_row) * APAD + kk + b_ld_k) * 2;
                LDSM4(bh[0], bh[1], bh[2], bh[3], bd + B_OFF * 2);
                #pragma unroll
                for (int mt = 0; mt < 2; mt++) {
                    MMAF16(c[mt][np * 2 + 0], ah[mt], bh[0], bh[1]);
                    MMAF16(c[mt][np * 2 + 1], ah[mt], bh[2], bh[3]);
                }
            }
        }
        __syncthreads();
    }

    #pragma unroll
    for (int mt = 0; mt < 2; mt++) {
        int row = m0 + wm * 32 + mt * 16 + (lane >> 2);
        #pragma unroll
        for (int nt = 0; nt < 8; nt++) {
            int col = n0 + wn * 64 + nt * 8 + (lane & 3) * 2;
            float2 bv = *(const float2*)(bias + col);
            float2 v0, v1;
            v0.x = c[mt][nt][0] + bv.x; v0.y = c[mt][nt][1] + bv.y;
            v1.x = c[mt][nt][2] + bv.x; v1.y = c[mt][nt][3] + bv.y;
            *(float2*)(C + (size_t)row * N + col) = v0;
            *(float2*)(C + (size_t)(row + 8) * N + col) = v1;
        }
    }
}

// fused Q/K/V projection: grid (13, 64)
__global__ __launch_bounds__(256, 2)
void gemm_qkv(const __half* __restrict__ qa, const __half* __restrict__ ka,
              const __half* __restrict__ va,
              const __half* __restrict__ wq, const __half* __restrict__ wk,
              const __half* __restrict__ wv,
              const float* __restrict__ bqp, const float* __restrict__ bkp, const float* __restrict__ bv,
              float* __restrict__ qp, float* __restrict__ kp, float* __restrict__ vp)
{
    extern __shared__ __half sm[];
    uint32_t sb = smem_u32(sm);
    const int m0 = blockIdx.y * 128;
    const int rr = blockIdx.x;
    if (rr < 3)
        gemm_tile128(qa, wq, bqp, qp, m0, rr * 128, NQKP, DMODEL, sb);
    else if (rr < 6)
        gemm_tile128(ka, wk, bkp, kp, m0, (rr - 3) * 128, NQKP, DMODEL, sb);
    else
        gemm_tile128(va, wv, bv, vp, m0, (rr - 6) * 128, NV, DMODEL, sb);
}

// output projection: grid (8, 64)
__global__ __launch_bounds__(256, 2)
void gemm_out(const __half* __restrict__ A, const __half* __restrict__ B,
              const float* __restrict__ bias, float* __restrict__ C)
{
    extern __shared__ __half sm[];
    uint32_t sb = smem_u32(sm);
    gemm_tile128(A, B, bias, C, blockIdx.y * 128, blockIdx.x * 128, DMODEL, NV, sb);
}

// ---------------- scores kernel: per (subhead, b, l-tile) ---------------------
template <int DILT, bool DYN>
__device__ __forceinline__ void scores_body(
    const float* __restrict__ qp, const float* __restrict__ kp,
    float* __restrict__ sc, int s, int dil_rt)
{
    const int DIL = DYN ? dil_rt : DILT;
    const int WIN = 31 * DIL + 32;
    extern __shared__ float sa[];
    float* swin = sa;                 // WIN*64
    float* sq   = swin + WIN * 64;    // 2048

    const int l0 = blockIdx.x * 32;
    const int b  = blockIdx.y;
    const int tid = threadIdx.x, lane = tid & 31;
    const int w0 = l0 - 16 * DIL;
    const long rowbase = (long)b * L_SZ + l0;

    {
        int idx = tid;
        #pragma unroll
        for (int p = 0; p < 2; p++, idx += 256) {
            int row = idx >> 4, q4 = (idx & 15) * 4;
            *(float4*)(sq + row * 64 + q4) =
                *(const float4*)(qp + (rowbase + row) * NQKP + s * 64 + q4);
        }
    }
    for (int r = tid >> 4; r < WIN; r += 16) {
        int g = w0 + r; g = g < 0 ? 0 : (g > L_SZ - 1 ? L_SZ - 1 : g);
        int q4 = (tid & 15) * 4;
        *(float4*)(swin + r * 64 + q4) =
            *(const float4*)(kp + ((long)b * L_SZ + g) * NQKP + s * 64 + q4);
    }
    __syncthreads();

    {
        const int li = tid >> 3;
        const int kb = (tid & 7) * 4;
        float acc0 = 0.f, acc1 = 0.f, acc2 = 0.f, acc3 = 0.f;
        const float* qrow = sq + li * 64;
        const float* wr0 = swin + (li + (kb + 0) * DIL) * 64;
        const float* wr1 = swin + (li + (kb + 1) * DIL) * 64;
        const float* wr2 = swin + (li + (kb + 2) * DIL) * 64;
        const float* wr3 = swin + (li + (kb + 3) * DIL) * 64;
        #pragma unroll
        for (int t4 = 0; t4 < 16; t4++) {
            int i = ((t4 + lane) & 15) * 4;
            float4 qv = *(const float4*)(qrow + i);
            float4 v0 = *(const float4*)(wr0 + i);
            float4 v1 = *(const float4*)(wr1 + i);
            float4 v2 = *(const float4*)(wr2 + i);
            float4 v3 = *(const float4*)(wr3 + i);
            acc0 += qv.x * v0.x + qv.y * v0.y + qv.z * v0.z + qv.w * v0.w;
            acc1 += qv.x * v1.x + qv.y * v1.y + qv.z * v1.z + qv.w * v1.w;
            acc2 += qv.x * v2.x + qv.y * v2.y + qv.z * v2.z + qv.w * v2.w;
            acc3 += qv.x * v3.x + qv.y * v3.y + qv.z * v3.z + qv.w * v3.w;
        }
        float4 o;
        o.x = acc0 * 0.125f; o.y = acc1 * 0.125f; o.z = acc2 * 0.125f; o.w = acc3 * 0.125f;
        *(float4*)(sc + (((size_t)s * B_SZ + b) * L_SZ + l0 + li) * KW + kb) = o;
    }
}

__global__ __launch_bounds__(256)
void scores_d1(const float* __restrict__ qp, const float* __restrict__ kp, float* __restrict__ sc)
{
    scores_body<1, false>(qp, kp, sc, blockIdx.z, 1);
}
__global__ __launch_bounds__(256)
void scores_dyn(const float* __restrict__ qp, const float* __restrict__ kp, float* __restrict__ sc)
{
    const int z = blockIdx.z;              // 0..2 -> s=2,3,4
    const int dil = (z == 0) ? 2 : (z == 1 ? 4 : 8);
    scores_body<0, true>(qp, kp, sc, 2 + z, dil);
}

// ---------------- head kernel: resample + softmax + AV ------------------------
// ssc stride = 36 floats (multiple of 4 -> float4-aligned staging)
#define HEAD_FIXED (1024 + 1152 + 1056 + 1024 + 32)

template <int DILT, bool DYN>
__device__ __forceinline__ void head_body(
    const float* __restrict__ vp, const float* __restrict__ sc_g,
    const float* __restrict__ Ws, const float* __restrict__ bsg,
    __half* __restrict__ oa, int h, int s, int dil_rt)
{
    const int DIL = DYN ? dil_rt : DILT;
    const int WIN = 31 * DIL + 32;
    extern __shared__ float sa[];
    float* swin = sa;                   // WIN*64
    float* sws  = swin + WIN * 64;      // 1024
    float* ssc  = sws + 1024;           // 32*36 = 1152
    float* ssm  = ssc + 1152;           // 1056
    float* satt = ssm + 1056;           // 1024
    float* sbs  = satt + 1024;          // 32

    const int l0 = blockIdx.x * 32;
    const int b  = blockIdx.y;
    const int tid = threadIdx.x, lane = tid & 31;
    const int w0 = l0 - 16 * DIL;
    const long rowbase = (long)b * L_SZ + l0;

    // loads: Ws, bs, sc tile, V window
    *(float4*)(sws + tid * 4) = *(const float4*)(Ws + (size_t)h * 1024 + tid * 4);
    if (tid < 32) sbs[tid] = bsg[h * KW + tid];
    {
        int li = tid >> 3, kb = (tid & 7) * 4;
        *(float4*)(ssc + li * 36 + kb) =
            *(const float4*)(sc_g + (((size_t)s * B_SZ + b) * L_SZ + l0 + li) * KW + kb);
    }
    for (int r = tid >> 4; r < WIN; r += 16) {
        int g = w0 + r; g = g < 0 ? 0 : (g > L_SZ - 1 ? L_SZ - 1 : g);
        int q4 = (tid & 15) * 4;
        *(float4*)(swin + r * 64 + q4) =
            *(const float4*)(vp + ((long)b * L_SZ + g) * NV + h * 64 + q4);
    }
    __syncthreads();

    // resample
    {
        const int li = tid >> 3;
        const int m4 = (tid & 7) * 4;
        float a0 = sbs[m4], a1 = sbs[m4 + 1], a2 = sbs[m4 + 2], a3 = sbs[m4 + 3];
        #pragma unroll 8
        for (int k = 0; k < 32; k++) {
            float scv = ssc[li * 36 + k];
            float4 wv = *(const float4*)(sws + k * 32 + m4);
            a0 += scv * wv.x; a1 += scv * wv.y; a2 += scv * wv.z; a3 += scv * wv.w;
        }
        ssm[li * 33 + m4 + 0] = a0;
        ssm[li * 33 + m4 + 1] = a1;
        ssm[li * 33 + m4 + 2] = a2;
        ssm[li * 33 + m4 + 3] = a3;
    }
    __syncthreads();

    // softmax
    {
        const int w = tid >> 5;
        #pragma unroll
        for (int rr = 0; rr < 4; rr++) {
            int li = w * 4 + rr;
            float v = ssm[li * 33 + lane];
            float mx = v;
            #pragma unroll
            for (int o = 16; o; o >>= 1) mx = fmaxf(mx, __shfl_xor_sync(0xffffffffu, mx, o));
            float e = __expf(v - mx);
            float ss = e;
            #pragma unroll
            for (int o = 16; o; o >>= 1) ss += __shfl_xor_sync(0xffffffffu, ss, o);
            satt[li * 32 + lane] = e / ss;
        }
    }
    __syncthreads();

    // AV
    {
        const int li = tid >> 3;
        const int io = (tid & 7) * 8;
        float4 a0 = make_float4(0.f, 0.f, 0.f, 0.f);
        float4 a1 = make_float4(0.f, 0.f, 0.f, 0.f);
        #pragma unroll 8
        for (int k = 0; k < 32; k++) {
            float wv = satt[li * 32 + k];
            const float* vr = swin + (li + k * DIL) * 64 + io;
            float4 v0 = *(const float4*)(vr);
            float4 v1 = *(const float4*)(vr + 4);
            a0.x += wv * v0.x; a0.y += wv * v0.y; a0.z += wv * v0.z; a0.w += wv * v0.w;
            a1.x += wv * v1.x; a1.y += wv * v1.y; a1.z += wv * v1.z; a1.w += wv * v1.w;
        }
        uint4 hv;
        hv.x = pack2(a0.x, a0.y);
        hv.y = pack2(a0.z, a0.w);
        hv.z = pack2(a1.x, a1.y);
        hv.w = pack2(a1.z, a1.w);
        *(uint4*)(oa + (rowbase + li) * NV + h * 64 + io) = hv;
    }
}

__global__ __launch_bounds__(256)
void head_d1(const float* __restrict__ vp, const float* __restrict__ sc,
             const float* __restrict__ Ws, const float* __restrict__ bsg,
             __half* __restrict__ oa)
{
    const int h = blockIdx.z;
    head_body<1, false>(vp, sc, Ws, bsg, oa, h, (h < 5) ? 0 : 1, 1);
}
__global__ __launch_bounds__(256)
void head_dyn(const float* __restrict__ vp, const float* __restrict__ sc,
              const float* __restrict__ Ws, const float* __restrict__ bsg,
              __half* __restrict__ oa)
{
    const int z = blockIdx.z;              // 0..3 -> heads 10..13
    const int h = 10 + z;
    const int s = (h < 12) ? 2 : (h == 12 ? 3 : 4);
    const int dil = (h < 12) ? 2 : (h == 12 ? 4 : 8);
    head_body<0, true>(vp, sc, Ws, bsg, oa, h, s, dil);
}

// ---------------- launcher ---------------------------------------------------
extern "C" void kernel_launch(void* const* d_in, const int* in_sizes, int n_in,
                              void* d_out, int out_size)
{
    const float* query = (const float*)d_in[0];
    const float* key   = (const float*)d_in[1];
    const float* value = (const float*)d_in[2];
    const float* Wq    = (const float*)d_in[3];
    const float* bq    = (const float*)d_in[4];
    const float* Wk    = (const float*)d_in[5];
    const float* bk    = (const float*)d_in[6];
    const float* Wv    = (const float*)d_in[7];
    const float* bv    = (const float*)d_in[8];
    const float* Ws    = (const float*)d_in[9];
    const float* bs    = (const float*)d_in[10];
    const float* Wc    = (const float*)d_in[11];
    const float* bc    = (const float*)d_in[12];
    float* out = (float*)d_out;

    float *qp, *kp, *vp, *sc, *bqp, *bkp;
    __half *qa, *ka, *va, *oa, *wq, *wk, *wv, *wc;
    cudaGetSymbolAddress((void**)&qp, g_qp);
    cudaGetSymbolAddress((void**)&kp, g_kp);
    cudaGetSymbolAddress((void**)&vp, g_vp);
    cudaGetSymbolAddress((void**)&sc, g_sc);
    cudaGetSymbolAddress((void**)&bqp, g_bqp);
    cudaGetSymbolAddress((void**)&bkp, g_bkp);
    cudaGetSymbolAddress((void**)&qa, g_qa);
    cudaGetSymbolAddress((void**)&ka, g_ka);
    cudaGetSymbolAddress((void**)&va, g_va);
    cudaGetSymbolAddress((void**)&oa, g_oa);
    cudaGetSymbolAddress((void**)&wq, g_wq);
    cudaGetSymbolAddress((void**)&wk, g_wk);
    cudaGetSymbolAddress((void**)&wv, g_wv);
    cudaGetSymbolAddress((void**)&wc, g_wc);

    cudaFuncSetAttribute(gemm_qkv, cudaFuncAttributeMaxDynamicSharedMemorySize, GEMM_SMEM);
    cudaFuncSetAttribute(gemm_out, cudaFuncAttributeMaxDynamicSharedMemorySize, GEMM_SMEM);

    auto ssz = [](int dil) { return (size_t)((31 * dil + 32) * 64 + 2048) * 4; };
    auto hsz = [](int dil) { return (size_t)((31 * dil + 32) * 64 + HEAD_FIXED) * 4; };
    cudaFuncSetAttribute(scores_d1,  cudaFuncAttributeMaxDynamicSharedMemorySize, (int)ssz(1));
    cudaFuncSetAttribute(scores_dyn, cudaFuncAttributeMaxDynamicSharedMemorySize, (int)ssz(8));
    cudaFuncSetAttribute(head_d1,    cudaFuncAttributeMaxDynamicSharedMemorySize, (int)hsz(1));
    cudaFuncSetAttribute(head_dyn,   cudaFuncAttributeMaxDynamicSharedMemorySize, (int)hsz(8));

    const int nact8 = ML * DMODEL / 8;

    // ---- conversions ----
    conv_act3<<<dim3((nact8 + 511) / 512, 3), 256>>>(
        (const float4*)query, (const float4*)key, (const float4*)value,
        (uint4*)qa, (uint4*)ka, (uint4*)va, nact8);
    conv_w_all<<<2690, 256>>>(Wq, Wk, Wv, Wc, bq, bk, wq, wk, wv, wc, bqp, bkp);

    // ---- fused Q/K/V projection ----
    gemm_qkv<<<dim3(13, 64), 256, GEMM_SMEM>>>(qa, ka, va, wq, wk, wv,
                                               bqp, bkp, bv, qp, kp, vp);

    // ---- per-subhead scores (computed once, shared across heads) ----
    scores_d1<<<dim3(L_SZ / 32, B_SZ, 2),  256, ssz(1)>>>(qp, kp, sc);
    scores_dyn<<<dim3(L_SZ / 32, B_SZ, 3), 256, ssz(8)>>>(qp, kp, sc);

    // ---- per-head resample + softmax + AV ----
    head_d1<<<dim3(L_SZ / 32, B_SZ, 10), 256, hsz(1)>>>(vp, sc, Ws, bs, oa);
    head_dyn<<<dim3(L_SZ / 32, B_SZ, 4), 256, hsz(8)>>>(vp, sc, Ws, bs, oa);

    // ---- output projection ----
    gemm_out<<<dim3(8, 64), 256, GEMM_SMEM>>>(oa, wc, bc, out);
}

// round 12
// speedup vs baseline: 6.7750x; 1.2439x over previous
#include <cuda_runtime.h>
#include <cuda_fp16.h>
#include <cstdint>

// Problem constants
#define B_SZ   2
#define L_SZ   4096
#define DMODEL 1024
#define DINT   64
#define KW     32
#define SUBH   5
#define HEADS  14
#define ML     (B_SZ * L_SZ)          // 8192 rows
#define NQK    320
#define NQKP   384                    // padded to 3*128
#define NV     896

// ---------------- scratch (static device globals; no allocation) -------------
__device__ float g_qp[ML * NQKP];
__device__ float g_kp[ML * NQKP];
__device__ __half g_vp[ML * NV];                  // V projection now fp16
__device__ float g_sc[SUBH * B_SZ * L_SZ * KW];   // per-subhead scores
__device__ __half g_qa[ML * DMODEL];
__device__ __half g_ka[ML * DMODEL];
__device__ __half g_va[ML * DMODEL];
__device__ __half g_oa[ML * NV];
__device__ __half g_wq[NQKP * DMODEL];
__device__ __half g_wk[NQKP * DMODEL];
__device__ __half g_wv[NV * DMODEL];
__device__ __half g_wc[DMODEL * NV];
__device__ float g_bqp[NQKP], g_bkp[NQKP];

// ---------------- helpers ------------------------------------------------
__device__ __forceinline__ uint32_t smem_u32(const void* p) {
    uint32_t a;
    asm("{ .reg .u64 t; cvta.to.shared.u64 t, %1; cvt.u32.u64 %0, t; }" : "=r"(a) : "l"(p));
    return a;
}
__device__ __forceinline__ void cpa16(uint32_t s, const void* g) {
    asm volatile("cp.async.cg.shared.global [%0], [%1], 16;" :: "r"(s), "l"(g));
}
#define CPA_COMMIT() asm volatile("cp.async.commit_group;" ::: "memory")
#define CPA_WAIT(n)  asm volatile("cp.async.wait_group %0;" :: "n"(n) : "memory")

#define LDSM4(r0, r1, r2, r3, a) \
    asm volatile("ldmatrix.sync.aligned.m8n8.x4.shared.b16 {%0,%1,%2,%3}, [%4];" \
        : "=r"(r0), "=r"(r1), "=r"(r2), "=r"(r3) : "r"(a))

#define MMAF16(c, a, b0, b1) \
    asm volatile("mma.sync.aligned.m16n8k16.row.col.f32.f16.f16.f32 " \
        "{%0,%1,%2,%3},{%4,%5,%6,%7},{%8,%9},{%0,%1,%2,%3};" \
        : "+f"((c)[0]), "+f"((c)[1]), "+f"((c)[2]), "+f"((c)[3]) \
        : "r"((a)[0]), "r"((a)[1]), "r"((a)[2]), "r"((a)[3]), "r"(b0), "r"(b1))

__device__ __forceinline__ uint32_t pack2(float a, float b) {
    __half2 h;
    h.x = __float2half_rn(a); h.y = __float2half_rn(b);
    return *(uint32_t*)&h;
}

// ---------------- conversion kernels -----------------------------------------
__global__ __launch_bounds__(256)
void conv_act3(const float4* __restrict__ q, const float4* __restrict__ k,
               const float4* __restrict__ v,
               uint4* __restrict__ qo, uint4* __restrict__ ko, uint4* __restrict__ vo, int n8)
{
    const float4* in; uint4* o;
    if (blockIdx.y == 0)      { in = q; o = qo; }
    else if (blockIdx.y == 1) { in = k; o = ko; }
    else                      { in = v; o = vo; }
    int i = blockIdx.x * 512 + threadIdx.x;
    #pragma unroll
    for (int p = 0; p < 2; p++, i += 256) {
        if (i < n8) {
            float4 a = in[2 * i], b = in[2 * i + 1];
            uint4 h;
            h.x = pack2(a.x, a.y);
            h.y = pack2(a.z, a.w);
            h.z = pack2(b.x, b.y);
            h.w = pack2(b.z, b.w);
            o[i] = h;
        }
    }
}

// fused weight conversions + bias padding; grid = 2690 blocks
__global__ __launch_bounds__(256)
void conv_w_all(const float* __restrict__ Wq, const float* __restrict__ Wk,
                const float* __restrict__ Wv, const float* __restrict__ Wc,
                const float* __restrict__ bq, const float* __restrict__ bk,
                __half* __restrict__ wq, __half* __restrict__ wk,
                __half* __restrict__ wv, __half* __restrict__ wc,
                float* __restrict__ bqp, float* __restrict__ bkp)
{
    const int bidx = blockIdx.x, tid = threadIdx.x;
    if (bidx >= 2688) {
        const float* src = (bidx == 2688) ? bq : bk;
        float* dst = (bidx == 2688) ? bqp : bkp;
        for (int i = tid; i < NQKP; i += 256) dst[i] = (i < NQK) ? src[i] : 0.f;
        return;
    }
    if (bidx < 768) {
        const bool isq = (bidx < 384);
        const float* W = isq ? Wq : Wk;
        __half* dst = isq ? wq : wk;
        int n = isq ? bidx : (bidx - 384);
        if (n >= NQK) {
            for (int kk = tid; kk < DMODEL; kk += 256) dst[(size_t)n * DMODEL + kk] = __float2half(0.f);
            return;
        }
        int head = n >> 6, i = n & 63;
        for (int kk = tid; kk < DMODEL; kk += 256)
            dst[(size_t)n * DMODEL + kk] = __float2half_rn(W[((size_t)head * DMODEL + kk) * 64 + i]);
    } else if (bidx < 1664) {
        int n = bidx - 768;
        int head = n >> 6, i = n & 63;
        for (int kk = tid; kk < DMODEL; kk += 256)
            wv[(size_t)n * DMODEL + kk] = __float2half_rn(Wv[((size_t)head * DMODEL + kk) * 64 + i]);
    } else {
        int n = bidx - 1664;
        for (int kk = tid; kk < NV; kk += 256)
            wc[(size_t)n * NV + kk] = __float2half_rn(Wc[(size_t)kk * DMODEL + n]);
    }
}

// ---------------- fp16 HMMA GEMM, 128x128 tile, K-chunk 64 -------------------
#define APAD 72
#define A_OFF 0
#define B_OFF 9216                    // 128 * 72
#define STE   18432                   // half-elems per stage (A+B)
#define GEMM_SMEM (2 * STE * 2)       // 73728 bytes

template <bool OUT_HALF>
__device__ __forceinline__ void gemm_tile128(
    const __half* __restrict__ A, const __half* __restrict__ B,
    const float* __restrict__ bias, void* __restrict__ Cv,
    int m0, int n0, int N, int K, uint32_t sb)
{
    const int tid = threadIdx.x, lane = tid & 31, wid = tid >> 5;
    const int wm = wid >> 1, wn = wid & 1;

    float c[2][8][4];
    #pragma unroll
    for (int i = 0; i < 2; i++)
        #pragma unroll
        for (int j = 0; j < 8; j++)
            #pragma unroll
            for (int q = 0; q < 4; q++) c[i][j][q] = 0.f;

    const int ld_row0 = tid >> 3;          // 0..31, +32 per iter
    const int ld_col  = (tid & 7) * 8;     // 0..56

    const int r = lane & 7, g = lane >> 3;
    const int a_ld_row = (g & 1) * 8 + r;
    const int a_ld_k   = (g >> 1) * 8;
    const int b_ld_row = (g >> 1) * 8 + r;
    const int b_ld_k   = (g & 1) * 8;

    const int nit = K >> 6;

    {
        uint32_t base = sb;
        #pragma unroll
        for (int i = 0; i < 4; i++) {
            int row = ld_row0 + i * 32;
            uint32_t so = base + (uint32_t)(row * APAD + ld_col) * 2;
            cpa16(so + A_OFF * 2, A + (size_t)(m0 + row) * K + ld_col);
            cpa16(so + B_OFF * 2, B + (size_t)(n0 + row) * K + ld_col);
        }
        CPA_COMMIT();
    }

    for (int it = 0; it < nit; ++it) {
        if (it + 1 < nit) {
            uint32_t base = sb + (uint32_t)(((it + 1) & 1) * STE) * 2;
            int k0 = (it + 1) << 6;
            #pragma unroll
            for (int i = 0; i < 4; i++) {
                int row = ld_row0 + i * 32;
                uint32_t so = base + (uint32_t)(row * APAD + ld_col) * 2;
                cpa16(so + A_OFF * 2, A + (size_t)(m0 + row) * K + k0 + ld_col);
                cpa16(so + B_OFF * 2, B + (size_t)(n0 + row) * K + k0 + ld_col);
            }
            CPA_COMMIT();
            CPA_WAIT(1);
        } else {
            CPA_WAIT(0);
        }
        __syncthreads();

        uint32_t base = sb + (uint32_t)((it & 1) * STE) * 2;
        #pragma unroll
        for (int kk = 0; kk < 64; kk += 16) {
            uint32_t ah[2][4];
            #pragma unroll
            for (int mt = 0; mt < 2; mt++) {
                uint32_t ad = base + (uint32_t)((wm * 32 + mt * 16 + a_ld_row) * APAD + kk + a_ld_k) * 2;
                LDSM4(ah[mt][0], ah[mt][1], ah[mt][2], ah[mt][3], ad + A_OFF * 2);
            }
            #pragma unroll
            for (int np = 0; np < 4; np++) {
                uint32_t bh[4];
                uint32_t bd = base + (uint32_t)((wn * 64 + np * 16 + b_ld_row) * APAD + kk + b_ld_k) * 2;
                LDSM4(bh[0], bh[1], bh[2], bh[3], bd + B_OFF * 2);
                #pragma unroll
                for (int mt = 0; mt < 2; mt++) {
                    MMAF16(c[mt][np * 2 + 0], ah[mt], bh[0], bh[1]);
                    MMAF16(c[mt][np * 2 + 1], ah[mt], bh[2], bh[3]);
                }
            }
        }
        __syncthreads();
    }

    // epilogue
    #pragma unroll
    for (int mt = 0; mt < 2; mt++) {
        int row = m0 + wm * 32 + mt * 16 + (lane >> 2);
        #pragma unroll
        for (int nt = 0; nt < 8; nt++) {
            int col = n0 + wn * 64 + nt * 8 + (lane & 3) * 2;
            float2 bv = *(const float2*)(bias + col);
            float x0 = c[mt][nt][0] + bv.x, y0 = c[mt][nt][1] + bv.y;
            float x1 = c[mt][nt][2] + bv.x, y1 = c[mt][nt][3] + bv.y;
            if (OUT_HALF) {
                __half* C = (__half*)Cv;
                *(uint32_t*)(C + (size_t)row * N + col) = pack2(x0, y0);
                *(uint32_t*)(C + (size_t)(row + 8) * N + col) = pack2(x1, y1);
            } else {
                float* C = (float*)Cv;
                float2 v0; v0.x = x0; v0.y = y0;
                float2 v1; v1.x = x1; v1.y = y1;
                *(float2*)(C + (size_t)row * N + col) = v0;
                *(float2*)(C + (size_t)(row + 8) * N + col) = v1;
            }
        }
    }
}

// fused Q/K/V projection: grid (13, 64)
__global__ __launch_bounds__(256, 2)
void gemm_qkv(const __half* __restrict__ qa, const __half* __restrict__ ka,
              const __half* __restrict__ va,
              const __half* __restrict__ wq, const __half* __restrict__ wk,
              const __half* __restrict__ wv,
              const float* __restrict__ bqp, const float* __restrict__ bkp, const float* __restrict__ bv,
              float* __restrict__ qp, float* __restrict__ kp, __half* __restrict__ vp)
{
    extern __shared__ __half sm[];
    uint32_t sb = smem_u32(sm);
    const int m0 = blockIdx.y * 128;
    const int rr = blockIdx.x;
    if (rr < 3)
        gemm_tile128<false>(qa, wq, bqp, qp, m0, rr * 128, NQKP, DMODEL, sb);
    else if (rr < 6)
        gemm_tile128<false>(ka, wk, bkp, kp, m0, (rr - 3) * 128, NQKP, DMODEL, sb);
    else
        gemm_tile128<true>(va, wv, bv, vp, m0, (rr - 6) * 128, NV, DMODEL, sb);
}

// output projection: grid (8, 64)
__global__ __launch_bounds__(256, 2)
void gemm_out(const __half* __restrict__ A, const __half* __restrict__ B,
              const float* __restrict__ bias, float* __restrict__ C)
{
    extern __shared__ __half sm[];
    uint32_t sb = smem_u32(sm);
    gemm_tile128<false>(A, B, bias, C, blockIdx.y * 128, blockIdx.x * 128, DMODEL, NV, sb);
}

// ---------------- scores kernel: per (subhead, b, l-tile) ---------------------
template <int DILT, bool DYN>
__device__ __forceinline__ void scores_body(
    const float* __restrict__ qp, const float* __restrict__ kp,
    float* __restrict__ sc, int s, int dil_rt)
{
    const int DIL = DYN ? dil_rt : DILT;
    const int WIN = 31 * DIL + 32;
    extern __shared__ float sa[];
    float* swin = sa;                 // WIN*64
    float* sq   = swin + WIN * 64;    // 2048

    const int l0 = blockIdx.x * 32;
    const int b  = blockIdx.y;
    const int tid = threadIdx.x, lane = tid & 31;
    const int w0 = l0 - 16 * DIL;
    const long rowbase = (long)b * L_SZ + l0;

    {
        int idx = tid;
        #pragma unroll
        for (int p = 0; p < 2; p++, idx += 256) {
            int row = idx >> 4, q4 = (idx & 15) * 4;
            *(float4*)(sq + row * 64 + q4) =
                *(const float4*)(qp + (rowbase + row) * NQKP + s * 64 + q4);
        }
    }
    for (int r = tid >> 4; r < WIN; r += 16) {
        int g = w0 + r; g = g < 0 ? 0 : (g > L_SZ - 1 ? L_SZ - 1 : g);
        int q4 = (tid & 15) * 4;
        *(float4*)(swin + r * 64 + q4) =
            *(const float4*)(kp + ((long)b * L_SZ + g) * NQKP + s * 64 + q4);
    }
    __syncthreads();

    {
        const int li = tid >> 3;
        const int kb = (tid & 7) * 4;
        float acc0 = 0.f, acc1 = 0.f, acc2 = 0.f, acc3 = 0.f;
        const float* qrow = sq + li * 64;
        const float* wr0 = swin + (li + (kb + 0) * DIL) * 64;
        const float* wr1 = swin + (li + (kb + 1) * DIL) * 64;
        const float* wr2 = swin + (li + (kb + 2) * DIL) * 64;
        const float* wr3 = swin + (li + (kb + 3) * DIL) * 64;
        #pragma unroll
        for (int t4 = 0; t4 < 16; t4++) {
            int i = ((t4 + lane) & 15) * 4;
            float4 qv = *(const float4*)(qrow + i);
            float4 v0 = *(const float4*)(wr0 + i);
            float4 v1 = *(const float4*)(wr1 + i);
            float4 v2 = *(const float4*)(wr2 + i);
            float4 v3 = *(const float4*)(wr3 + i);
            acc0 += qv.x * v0.x + qv.y * v0.y + qv.z * v0.z + qv.w * v0.w;
            acc1 += qv.x * v1.x + qv.y * v1.y + qv.z * v1.z + qv.w * v1.w;
            acc2 += qv.x * v2.x + qv.y * v2.y + qv.z * v2.z + qv.w * v2.w;
            acc3 += qv.x * v3.x + qv.y * v3.y + qv.z * v3.z + qv.w * v3.w;
        }
        float4 o;
        o.x = acc0 * 0.125f; o.y = acc1 * 0.125f; o.z = acc2 * 0.125f; o.w = acc3 * 0.125f;
        *(float4*)(sc + (((size_t)s * B_SZ + b) * L_SZ + l0 + li) * KW + kb) = o;
    }
}

__global__ __launch_bounds__(256)
void scores_d1(const float* __restrict__ qp, const float* __restrict__ kp, float* __restrict__ sc)
{
    scores_body<1, false>(qp, kp, sc, blockIdx.z, 1);
}
__global__ __launch_bounds__(256)
void scores_dyn(const float* __restrict__ qp, const float* __restrict__ kp, float* __restrict__ sc)
{
    const int z = blockIdx.z;              // 0..2 -> s=2,3,4
    const int dil = (z == 0) ? 2 : (z == 1 ? 4 : 8);
    scores_body<0, true>(qp, kp, sc, 2 + z, dil);
}

// ---------------- head kernel: resample + softmax + AV (fp16 V) --------------
#define HEAD_FIXED (1024 + 1152 + 1056 + 1024 + 32)   // floats after swin

template <int DILT, bool DYN>
__device__ __forceinline__ void head_body(
    const __half* __restrict__ vp, const float* __restrict__ sc_g,
    const float* __restrict__ Ws, const float* __restrict__ bsg,
    __half* __restrict__ oa, int h, int s, int dil_rt)
{
    const int DIL = DYN ? dil_rt : DILT;
    const int WIN = 31 * DIL + 32;
    extern __shared__ char sab[];
    __half* swin = (__half*)sab;                       // WIN*64 halfs
    float* sws  = (float*)(sab + (size_t)WIN * 128);   // 1024
    float* ssc  = sws + 1024;                          // 1152
    float* ssm  = ssc + 1152;                          // 1056
    float* satt = ssm + 1056;                          // 1024
    float* sbs  = satt + 1024;                         // 32

    const int l0 = blockIdx.x * 32;
    const int b  = blockIdx.y;
    const int tid = threadIdx.x, lane = tid & 31;
    const int w0 = l0 - 16 * DIL;
    const long rowbase = (long)b * L_SZ + l0;

    // loads: Ws, bs, sc tile, V window (fp16)
    *(float4*)(sws + tid * 4) = *(const float4*)(Ws + (size_t)h * 1024 + tid * 4);
    if (tid < 32) sbs[tid] = bsg[h * KW + tid];
    {
        int li = tid >> 3, kb = (tid & 7) * 4;
        *(float4*)(ssc + li * 36 + kb) =
            *(const float4*)(sc_g + (((size_t)s * B_SZ + b) * L_SZ + l0 + li) * KW + kb);
    }
    for (int r = tid >> 3; r < WIN; r += 32) {
        int g = w0 + r; g = g < 0 ? 0 : (g > L_SZ - 1 ? L_SZ - 1 : g);
        int c8 = (tid & 7) * 8;
        *(uint4*)(swin + r * 64 + c8) =
            *(const uint4*)(vp + ((long)b * L_SZ + g) * NV + h * 64 + c8);
    }
    __syncthreads();

    // resample
    {
        const int li = tid >> 3;
        const int m4 = (tid & 7) * 4;
        float a0 = sbs[m4], a1 = sbs[m4 + 1], a2 = sbs[m4 + 2], a3 = sbs[m4 + 3];
        #pragma unroll 8
        for (int k = 0; k < 32; k++) {
            float scv = ssc[li * 36 + k];
            float4 wv = *(const float4*)(sws + k * 32 + m4);
            a0 += scv * wv.x; a1 += scv * wv.y; a2 += scv * wv.z; a3 += scv * wv.w;
        }
        ssm[li * 33 + m4 + 0] = a0;
        ssm[li * 33 + m4 + 1] = a1;
        ssm[li * 33 + m4 + 2] = a2;
        ssm[li * 33 + m4 + 3] = a3;
    }
    __syncthreads();

    // softmax
    {
        const int w = tid >> 5;
        #pragma unroll
        for (int rr = 0; rr < 4; rr++) {
            int li = w * 4 + rr;
            float v = ssm[li * 33 + lane];
            float mx = v;
            #pragma unroll
            for (int o = 16; o; o >>= 1) mx = fmaxf(mx, __shfl_xor_sync(0xffffffffu, mx, o));
            float e = __expf(v - mx);
            float ss = e;
            #pragma unroll
            for (int o = 16; o; o >>= 1) ss += __shfl_xor_sync(0xffffffffu, ss, o);
            satt[li * 32 + lane] = e / ss;
        }
    }
    __syncthreads();

    // AV (fp16 V window)
    {
        const int li = tid >> 3;
        const int io = (tid & 7) * 8;
        float4 a0 = make_float4(0.f, 0.f, 0.f, 0.f);
        float4 a1 = make_float4(0.f, 0.f, 0.f, 0.f);
        #pragma unroll 8
        for (int k = 0; k < 32; k++) {
            float wv = satt[li * 32 + k];
            const __half* vr = swin + (li + k * DIL) * 64 + io;
            uint4 raw = *(const uint4*)vr;
            const __half2* hp = (const __half2*)&raw;
            float2 f0 = __half22float2(hp[0]);
            float2 f1 = __half22float2(hp[1]);
            float2 f2 = __half22float2(hp[2]);
            float2 f3 = __half22float2(hp[3]);
            a0.x += wv * f0.x; a0.y += wv * f0.y; a0.z += wv * f1.x; a0.w += wv * f1.y;
            a1.x += wv * f2.x; a1.y += wv * f2.y; a1.z += wv * f3.x; a1.w += wv * f3.y;
        }
        uint4 hv;
        hv.x = pack2(a0.x, a0.y);
        hv.y = pack2(a0.z, a0.w);
        hv.z = pack2(a1.x, a1.y);
        hv.w = pack2(a1.z, a1.w);
        *(uint4*)(oa + (rowbase + li) * NV + h * 64 + io) = hv;
    }
}

__global__ __launch_bounds__(256)
void head_d1(const __half* __restrict__ vp, const float* __restrict__ sc,
             const float* __restrict__ Ws, const float* __restrict__ bsg,
             __half* __restrict__ oa)
{
    const int h = blockIdx.z;
    head_body<1, false>(vp, sc, Ws, bsg, oa, h, (h < 5) ? 0 : 1, 1);
}
__global__ __launch_bounds__(256)
void head_dyn(const __half* __restrict__ vp, const float* __restrict__ sc,
              const float* __restrict__ Ws, const float* __restrict__ bsg,
              __half* __restrict__ oa)
{
    const int z = blockIdx.z;              // 0..3 -> heads 10..13
    const int h = 10 + z;
    const int s = (h < 12) ? 2 : (h == 12 ? 3 : 4);
    const int dil = (h < 12) ? 2 : (h == 12 ? 4 : 8);
    head_body<0, true>(vp, sc, Ws, bsg, oa, h, s, dil);
}

// ---------------- launcher ---------------------------------------------------
extern "C" void kernel_launch(void* const* d_in, const int* in_sizes, int n_in,
                              void* d_out, int out_size)
{
    const float* query = (const float*)d_in[0];
    const float* key   = (const float*)d_in[1];
    const float* value = (const float*)d_in[2];
    const float* Wq    = (const float*)d_in[3];
    const float* bq    = (const float*)d_in[4];
    const float* Wk    = (const float*)d_in[5];
    const float* bk    = (const float*)d_in[6];
    const float* Wv    = (const float*)d_in[7];
    const float* bv    = (const float*)d_in[8];
    const float* Ws    = (const float*)d_in[9];
    const float* bs    = (const float*)d_in[10];
    const float* Wc    = (const float*)d_in[11];
    const float* bc    = (const float*)d_in[12];
    float* out = (float*)d_out;

    float *qp, *kp, *sc, *bqp, *bkp;
    __half *vp, *qa, *ka, *va, *oa, *wq, *wk, *wv, *wc;
    cudaGetSymbolAddress((void**)&qp, g_qp);
    cudaGetSymbolAddress((void**)&kp, g_kp);
    cudaGetSymbolAddress((void**)&vp, g_vp);
    cudaGetSymbolAddress((void**)&sc, g_sc);
    cudaGetSymbolAddress((void**)&bqp, g_bqp);
    cudaGetSymbolAddress((void**)&bkp, g_bkp);
    cudaGetSymbolAddress((void**)&qa, g_qa);
    cudaGetSymbolAddress((void**)&ka, g_ka);
    cudaGetSymbolAddress((void**)&va, g_va);
    cudaGetSymbolAddress((void**)&oa, g_oa);
    cudaGetSymbolAddress((void**)&wq, g_wq);
    cudaGetSymbolAddress((void**)&wk, g_wk);
    cudaGetSymbolAddress((void**)&wv, g_wv);
    cudaGetSymbolAddress((void**)&wc, g_wc);

    cudaFuncSetAttribute(gemm_qkv, cudaFuncAttributeMaxDynamicSharedMemorySize, GEMM_SMEM);
    cudaFuncSetAttribute(gemm_out, cudaFuncAttributeMaxDynamicSharedMemorySize, GEMM_SMEM);

    auto ssz = [](int dil) { return (size_t)((31 * dil + 32) * 64 + 2048) * 4; };
    auto hsz = [](int dil) { return (size_t)(31 * dil + 32) * 128 + (size_t)HEAD_FIXED * 4; };
    cudaFuncSetAttribute(scores_d1,  cudaFuncAttributeMaxDynamicSharedMemorySize, (int)ssz(1));
    cudaFuncSetAttribute(scores_dyn, cudaFuncAttributeMaxDynamicSharedMemorySize, (int)ssz(8));
    cudaFuncSetAttribute(head_d1,    cudaFuncAttributeMaxDynamicSharedMemorySize, (int)hsz(1));
    cudaFuncSetAttribute(head_dyn,   cudaFuncAttributeMaxDynamicSharedMemorySize, (int)hsz(8));

    const int nact8 = ML * DMODEL / 8;

    // ---- conversions ----
    conv_act3<<<dim3((nact8 + 511) / 512, 3), 256>>>(
        (const float4*)query, (const float4*)key, (const float4*)value,
        (uint4*)qa, (uint4*)ka, (uint4*)va, nact8);
    conv_w_all<<<2690, 256>>>(Wq, Wk, Wv, Wc, bq, bk, wq, wk, wv, wc, bqp, bkp);

    // ---- fused Q/K/V projection ----
    gemm_qkv<<<dim3(13, 64), 256, GEMM_SMEM>>>(qa, ka, va, wq, wk, wv,
                                               bqp, bkp, bv, qp, kp, vp);

    // ---- per-subhead scores ----
    scores_d1<<<dim3(L_SZ / 32, B_SZ, 2),  256, ssz(1)>>>(qp, kp, sc);
    scores_dyn<<<dim3(L_SZ / 32, B_SZ, 3), 256, ssz(8)>>>(qp, kp, sc);

    // ---- per-head resample + softmax + AV ----
    head_d1<<<dim3(L_SZ / 32, B_SZ, 10), 256, hsz(1)>>>(vp, sc, Ws, bs, oa);
    head_dyn<<<dim3(L_SZ / 32, B_SZ, 4), 256, hsz(8)>>>(vp, sc, Ws, bs, oa);

    // ---- output projection ----
    gemm_out<<<dim3(8, 64), 256, GEMM_SMEM>>>(oa, wc, bc, out);
}

// round 13
// speedup vs baseline: 6.9384x; 1.0241x over previous
#include <cuda_runtime.h>
#include <cuda_fp16.h>
#include <cstdint>

// Problem constants
#define B_SZ   2
#define L_SZ   4096
#define DMODEL 1024
#define DINT   64
#define KW     32
#define SUBH   5
#define HEADS  14
#define ML     (B_SZ * L_SZ)          // 8192 rows
#define NQK    320
#define NQKP   384                    // padded to 3*128
#define NV     896

// ---------------- scratch (static device globals; no allocation) -------------
__device__ __half g_qp[ML * NQKP];
__device__ __half g_kp[ML * NQKP];
__device__ __half g_vp[ML * NV];
__device__ __half g_sc[SUBH * B_SZ * L_SZ * KW];  // per-subhead scores (fp16)
__device__ __half g_qa[ML * DMODEL];
__device__ __half g_ka[ML * DMODEL];
__device__ __half g_va[ML * DMODEL];
__device__ __half g_oa[ML * NV];
__device__ __half g_wq[NQKP * DMODEL];
__device__ __half g_wk[NQKP * DMODEL];
__device__ __half g_wv[NV * DMODEL];
__device__ __half g_wc[DMODEL * NV];
__device__ float g_bqp[NQKP], g_bkp[NQKP];

// ---------------- helpers ------------------------------------------------
__device__ __forceinline__ uint32_t smem_u32(const void* p) {
    uint32_t a;
    asm("{ .reg .u64 t; cvta.to.shared.u64 t, %1; cvt.u32.u64 %0, t; }" : "=r"(a) : "l"(p));
    return a;
}
__device__ __forceinline__ void cpa16(uint32_t s, const void* g) {
    asm volatile("cp.async.cg.shared.global [%0], [%1], 16;" :: "r"(s), "l"(g));
}
#define CPA_COMMIT() asm volatile("cp.async.commit_group;" ::: "memory")
#define CPA_WAIT(n)  asm volatile("cp.async.wait_group %0;" :: "n"(n) : "memory")

#define LDSM4(r0, r1, r2, r3, a) \
    asm volatile("ldmatrix.sync.aligned.m8n8.x4.shared.b16 {%0,%1,%2,%3}, [%4];" \
        : "=r"(r0), "=r"(r1), "=r"(r2), "=r"(r3) : "r"(a))

#define MMAF16(c, a, b0, b1) \
    asm volatile("mma.sync.aligned.m16n8k16.row.col.f32.f16.f16.f32 " \
        "{%0,%1,%2,%3},{%4,%5,%6,%7},{%8,%9},{%0,%1,%2,%3};" \
        : "+f"((c)[0]), "+f"((c)[1]), "+f"((c)[2]), "+f"((c)[3]) \
        : "r"((a)[0]), "r"((a)[1]), "r"((a)[2]), "r"((a)[3]), "r"(b0), "r"(b1))

__device__ __forceinline__ uint32_t pack2(float a, float b) {
    __half2 h;
    h.x = __float2half_rn(a); h.y = __float2half_rn(b);
    return *(uint32_t*)&h;
}

// ---------------- conversion kernels -----------------------------------------
__global__ __launch_bounds__(256)
void conv_act3(const float4* __restrict__ q, const float4* __restrict__ k,
               const float4* __restrict__ v,
               uint4* __restrict__ qo, uint4* __restrict__ ko, uint4* __restrict__ vo, int n8)
{
    const float4* in; uint4* o;
    if (blockIdx.y == 0)      { in = q; o = qo; }
    else if (blockIdx.y == 1) { in = k; o = ko; }
    else                      { in = v; o = vo; }
    int i = blockIdx.x * 512 + threadIdx.x;
    #pragma unroll
    for (int p = 0; p < 2; p++, i += 256) {
        if (i < n8) {
            float4 a = in[2 * i], b = in[2 * i + 1];
            uint4 h;
            h.x = pack2(a.x, a.y);
            h.y = pack2(a.z, a.w);
            h.z = pack2(b.x, b.y);
            h.w = pack2(b.z, b.w);
            o[i] = h;
        }
    }
}

// fused weight conversions + bias padding; grid = 2690 blocks
__global__ __launch_bounds__(256)
void conv_w_all(const float* __restrict__ Wq, const float* __restrict__ Wk,
                const float* __restrict__ Wv, const float* __restrict__ Wc,
                const float* __restrict__ bq, const float* __restrict__ bk,
                __half* __restrict__ wq, __half* __restrict__ wk,
                __half* __restrict__ wv, __half* __restrict__ wc,
                float* __restrict__ bqp, float* __restrict__ bkp)
{
    const int bidx = blockIdx.x, tid = threadIdx.x;
    if (bidx >= 2688) {
        const float* src = (bidx == 2688) ? bq : bk;
        float* dst = (bidx == 2688) ? bqp : bkp;
        for (int i = tid; i < NQKP; i += 256) dst[i] = (i < NQK) ? src[i] : 0.f;
        return;
    }
    if (bidx < 768) {
        const bool isq = (bidx < 384);
        const float* W = isq ? Wq : Wk;
        __half* dst = isq ? wq : wk;
        int n = isq ? bidx : (bidx - 384);
        if (n >= NQK) {
            for (int kk = tid; kk < DMODEL; kk += 256) dst[(size_t)n * DMODEL + kk] = __float2half(0.f);
            return;
        }
        int head = n >> 6, i = n & 63;
        for (int kk = tid; kk < DMODEL; kk += 256)
            dst[(size_t)n * DMODEL + kk] = __float2half_rn(W[((size_t)head * DMODEL + kk) * 64 + i]);
    } else if (bidx < 1664) {
        int n = bidx - 768;
        int head = n >> 6, i = n & 63;
        for (int kk = tid; kk < DMODEL; kk += 256)
            wv[(size_t)n * DMODEL + kk] = __float2half_rn(Wv[((size_t)head * DMODEL + kk) * 64 + i]);
    } else {
        int n = bidx - 1664;
        for (int kk = tid; kk < NV; kk += 256)
            wc[(size_t)n * NV + kk] = __float2half_rn(Wc[(size_t)kk * DMODEL + n]);
    }
}

// ---------------- fp16 HMMA GEMM, 128x128 tile, K-chunk 64 -------------------
#define APAD 72
#define A_OFF 0
#define B_OFF 9216                    // 128 * 72
#define STE   18432
#define GEMM_SMEM (2 * STE * 2)       // 73728 bytes

template <bool OUT_HALF>
__device__ __forceinline__ void gemm_tile128(
    const __half* __restrict__ A, const __half* __restrict__ B,
    const float* __restrict__ bias, void* __restrict__ Cv,
    int m0, int n0, int N, int K, uint32_t sb)
{
    const int tid = threadIdx.x, lane = tid & 31, wid = tid >> 5;
    const int wm = wid >> 1, wn = wid & 1;

    float c[2][8][4];
    #pragma unroll
    for (int i = 0; i < 2; i++)
        #pragma unroll
        for (int j = 0; j < 8; j++)
            #pragma unroll
            for (int q = 0; q < 4; q++) c[i][j][q] = 0.f;

    const int ld_row0 = tid >> 3;
    const int ld_col  = (tid & 7) * 8;

    const int r = lane & 7, g = lane >> 3;
    const int a_ld_row = (g & 1) * 8 + r;
    const int a_ld_k   = (g >> 1) * 8;
    const int b_ld_row = (g >> 1) * 8 + r;
    const int b_ld_k   = (g & 1) * 8;

    const int nit = K >> 6;

    {
        uint32_t base = sb;
        #pragma unroll
        for (int i = 0; i < 4; i++) {
            int row = ld_row0 + i * 32;
            uint32_t so = base + (uint32_t)(row * APAD + ld_col) * 2;
            cpa16(so + A_OFF * 2, A + (size_t)(m0 + row) * K + ld_col);
            cpa16(so + B_OFF * 2, B + (size_t)(n0 + row) * K + ld_col);
        }
        CPA_COMMIT();
    }

    for (int it = 0; it < nit; ++it) {
        if (it + 1 < nit) {
            uint32_t base = sb + (uint32_t)(((it + 1) & 1) * STE) * 2;
            int k0 = (it + 1) << 6;
            #pragma unroll
            for (int i = 0; i < 4; i++) {
                int row = ld_row0 + i * 32;
                uint32_t so = base + (uint32_t)(row * APAD + ld_col) * 2;
                cpa16(so + A_OFF * 2, A + (size_t)(m0 + row) * K + k0 + ld_col);
                cpa16(so + B_OFF * 2, B + (size_t)(n0 + row) * K + k0 + ld_col);
            }
            CPA_COMMIT();
            CPA_WAIT(1);
        } else {
            CPA_WAIT(0);
        }
        __syncthreads();

        uint32_t base = sb + (uint32_t)((it & 1) * STE) * 2;
        #pragma unroll
        for (int kk = 0; kk < 64; kk += 16) {
            uint32_t ah[2][4];
            #pragma unroll
            for (int mt = 0; mt < 2; mt++) {
                uint32_t ad = base + (uint32_t)((wm * 32 + mt * 16 + a_ld_row) * APAD + kk + a_ld_k) * 2;
                LDSM4(ah[mt][0], ah[mt][1], ah[mt][2], ah[mt][3], ad + A_OFF * 2);
            }
            #pragma unroll
            for (int np = 0; np < 4; np++) {
                uint32_t bh[4];
                uint32_t bd = base + (uint32_t)((wn * 64 + np * 16 + b_ld_row) * APAD + kk + b_ld_k) * 2;
                LDSM4(bh[0], bh[1], bh[2], bh[3], bd + B_OFF * 2);
                #pragma unroll
                for (int mt = 0; mt < 2; mt++) {
                    MMAF16(c[mt][np * 2 + 0], ah[mt], bh[0], bh[1]);
                    MMAF16(c[mt][np * 2 + 1], ah[mt], bh[2], bh[3]);
                }
            }
        }
        __syncthreads();
    }

    #pragma unroll
    for (int mt = 0; mt < 2; mt++) {
        int row = m0 + wm * 32 + mt * 16 + (lane >> 2);
        #pragma unroll
        for (int nt = 0; nt < 8; nt++) {
            int col = n0 + wn * 64 + nt * 8 + (lane & 3) * 2;
            float2 bv = *(const float2*)(bias + col);
            float x0 = c[mt][nt][0] + bv.x, y0 = c[mt][nt][1] + bv.y;
            float x1 = c[mt][nt][2] + bv.x, y1 = c[mt][nt][3] + bv.y;
            if (OUT_HALF) {
                __half* C = (__half*)Cv;
                *(uint32_t*)(C + (size_t)row * N + col) = pack2(x0, y0);
                *(uint32_t*)(C + (size_t)(row + 8) * N + col) = pack2(x1, y1);
            } else {
                float* C = (float*)Cv;
                float2 v0; v0.x = x0; v0.y = y0;
                float2 v1; v1.x = x1; v1.y = y1;
                *(float2*)(C + (size_t)row * N + col) = v0;
                *(float2*)(C + (size_t)(row + 8) * N + col) = v1;
            }
        }
    }
}

// fused Q/K/V projection: grid (13, 64) — all outputs fp16
__global__ __launch_bounds__(256, 2)
void gemm_qkv(const __half* __restrict__ qa, const __half* __restrict__ ka,
              const __half* __restrict__ va,
              const __half* __restrict__ wq, const __half* __restrict__ wk,
              const __half* __restrict__ wv,
              const float* __restrict__ bqp, const float* __restrict__ bkp, const float* __restrict__ bv,
              __half* __restrict__ qp, __half* __restrict__ kp, __half* __restrict__ vp)
{
    extern __shared__ __half sm[];
    uint32_t sb = smem_u32(sm);
    const int m0 = blockIdx.y * 128;
    const int rr = blockIdx.x;
    if (rr < 3)
        gemm_tile128<true>(qa, wq, bqp, qp, m0, rr * 128, NQKP, DMODEL, sb);
    else if (rr < 6)
        gemm_tile128<true>(ka, wk, bkp, kp, m0, (rr - 3) * 128, NQKP, DMODEL, sb);
    else
        gemm_tile128<true>(va, wv, bv, vp, m0, (rr - 6) * 128, NV, DMODEL, sb);
}

// output projection: grid (8, 64)
__global__ __launch_bounds__(256, 2)
void gemm_out(const __half* __restrict__ A, const __half* __restrict__ B,
              const float* __restrict__ bias, float* __restrict__ C)
{
    extern __shared__ __half sm[];
    uint32_t sb = smem_u32(sm);
    gemm_tile128<false>(A, B, bias, C, blockIdx.y * 128, blockIdx.x * 128, DMODEL, NV, sb);
}

// ---------------- scores kernel: per (subhead, b, l-tile), fp16 ---------------
template <int DILT, bool DYN>
__device__ __forceinline__ void scores_body(
    const __half* __restrict__ qp, const __half* __restrict__ kp,
    __half* __restrict__ sc, int s, int dil_rt)
{
    const int DIL = DYN ? dil_rt : DILT;
    const int WIN = 31 * DIL + 32;
    extern __shared__ __half sh[];
    __half* swin = sh;                 // WIN*64
    __half* sq   = swin + WIN * 64;    // 2048

    const int l0 = blockIdx.x * 32;
    const int b  = blockIdx.y;
    const int tid = threadIdx.x, lane = tid & 31;
    const int w0 = l0 - 16 * DIL;
    const long rowbase = (long)b * L_SZ + l0;
    const int c8 = (tid & 7) * 8;

    // load Q tile: 32 rows x 64 halfs = 256 uint4, 1 per thread
    {
        int row = tid >> 3;
        *(uint4*)(sq + row * 64 + c8) =
            *(const uint4*)(qp + (rowbase + row) * NQKP + s * 64 + c8);
    }
    // load K window
    for (int r = tid >> 3; r < WIN; r += 32) {
        int g = w0 + r; g = g < 0 ? 0 : (g > L_SZ - 1 ? L_SZ - 1 : g);
        *(uint4*)(swin + r * 64 + c8) =
            *(const uint4*)(kp + ((long)b * L_SZ + g) * NQKP + s * 64 + c8);
    }
    __syncthreads();

    {
        const int li = tid >> 3;
        const int kb = (tid & 7) * 4;
        float acc0 = 0.f, acc1 = 0.f, acc2 = 0.f, acc3 = 0.f;
        const __half* qrow = sq + li * 64;
        const __half* wr0 = swin + (li + (kb + 0) * DIL) * 64;
        const __half* wr1 = swin + (li + (kb + 1) * DIL) * 64;
        const __half* wr2 = swin + (li + (kb + 2) * DIL) * 64;
        const __half* wr3 = swin + (li + (kb + 3) * DIL) * 64;
        #pragma unroll
        for (int t8 = 0; t8 < 8; t8++) {
            int i = ((t8 + lane) & 7) * 8;
            uint4 qr = *(const uint4*)(qrow + i);
            uint4 r0 = *(const uint4*)(wr0 + i);
            uint4 r1 = *(const uint4*)(wr1 + i);
            uint4 r2 = *(const uint4*)(wr2 + i);
            uint4 r3 = *(const uint4*)(wr3 + i);
            const __half2* qh = (const __half2*)&qr;
            const __half2* h0 = (const __half2*)&r0;
            const __half2* h1 = (const __half2*)&r1;
            const __half2* h2 = (const __half2*)&r2;
            const __half2* h3 = (const __half2*)&r3;
            #pragma unroll
            for (int u = 0; u < 4; u++) {
                float2 qf = __half22float2(qh[u]);
                float2 f0 = __half22float2(h0[u]);
                float2 f1 = __half22float2(h1[u]);
                float2 f2 = __half22float2(h2[u]);
                float2 f3 = __half22float2(h3[u]);
                acc0 += qf.x * f0.x + qf.y * f0.y;
                acc1 += qf.x * f1.x + qf.y * f1.y;
                acc2 += qf.x * f2.x + qf.y * f2.y;
                acc3 += qf.x * f3.x + qf.y * f3.y;
            }
        }
        uint2 o;
        o.x = pack2(acc0 * 0.125f, acc1 * 0.125f);
        o.y = pack2(acc2 * 0.125f, acc3 * 0.125f);
        *(uint2*)(sc + (((size_t)s * B_SZ + b) * L_SZ + l0 + li) * KW + kb) = o;
    }
}

__global__ __launch_bounds__(256)
void scores_d1(const __half* __restrict__ qp, const __half* __restrict__ kp, __half* __restrict__ sc)
{
    scores_body<1, false>(qp, kp, sc, blockIdx.z, 1);
}
__global__ __launch_bounds__(256)
void scores_dyn(const __half* __restrict__ qp, const __half* __restrict__ kp, __half* __restrict__ sc)
{
    const int z = blockIdx.z;              // 0..2 -> s=2,3,4
    const int dil = (z == 0) ? 2 : (z == 1 ? 4 : 8);
    scores_body<0, true>(qp, kp, sc, 2 + z, dil);
}

// ---------------- head kernel: resample + softmax + AV (fp16 V, fp16 sc) -----
#define HEAD_FIXED (1024 + 1152 + 1056 + 1024 + 32)   // floats after swin

template <int DILT, bool DYN>
__device__ __forceinline__ void head_body(
    const __half* __restrict__ vp, const __half* __restrict__ sc_g,
    const float* __restrict__ Ws, const float* __restrict__ bsg,
    __half* __restrict__ oa, int h, int s, int dil_rt)
{
    const int DIL = DYN ? dil_rt : DILT;
    const int WIN = 31 * DIL + 32;
    extern __shared__ char sab[];
    __half* swin = (__half*)sab;                       // WIN*64 halfs
    float* sws  = (float*)(sab + (size_t)WIN * 128);   // 1024
    float* ssc  = sws + 1024;                          // 1152
    float* ssm  = ssc + 1152;                          // 1056
    float* satt = ssm + 1056;                          // 1024
    float* sbs  = satt + 1024;                         // 32

    const int l0 = blockIdx.x * 32;
    const int b  = blockIdx.y;
    const int tid = threadIdx.x, lane = tid & 31;
    const int w0 = l0 - 16 * DIL;
    const long rowbase = (long)b * L_SZ + l0;

    *(float4*)(sws + tid * 4) = *(const float4*)(Ws + (size_t)h * 1024 + tid * 4);
    if (tid < 32) sbs[tid] = bsg[h * KW + tid];
    {
        int li = tid >> 3, kb = (tid & 7) * 4;
        uint2 raw = *(const uint2*)(sc_g + (((size_t)s * B_SZ + b) * L_SZ + l0 + li) * KW + kb);
        float2 f0 = __half22float2(*(__half2*)&raw.x);
        float2 f1 = __half22float2(*(__half2*)&raw.y);
        ssc[li * 36 + kb + 0] = f0.x;
        ssc[li * 36 + kb + 1] = f0.y;
        ssc[li * 36 + kb + 2] = f1.x;
        ssc[li * 36 + kb + 3] = f1.y;
    }
    for (int r = tid >> 3; r < WIN; r += 32) {
        int g = w0 + r; g = g < 0 ? 0 : (g > L_SZ - 1 ? L_SZ - 1 : g);
        int c8 = (tid & 7) * 8;
        *(uint4*)(swin + r * 64 + c8) =
            *(const uint4*)(vp + ((long)b * L_SZ + g) * NV + h * 64 + c8);
    }
    __syncthreads();

    // resample
    {
        const int li = tid >> 3;
        const int m4 = (tid & 7) * 4;
        float a0 = sbs[m4], a1 = sbs[m4 + 1], a2 = sbs[m4 + 2], a3 = sbs[m4 + 3];
        #pragma unroll 8
        for (int k = 0; k < 32; k++) {
            float scv = ssc[li * 36 + k];
            float4 wv = *(const float4*)(sws + k * 32 + m4);
            a0 += scv * wv.x; a1 += scv * wv.y; a2 += scv * wv.z; a3 += scv * wv.w;
        }
        ssm[li * 33 + m4 + 0] = a0;
        ssm[li * 33 + m4 + 1] = a1;
        ssm[li * 33 + m4 + 2] = a2;
        ssm[li * 33 + m4 + 3] = a3;
    }
    __syncthreads();

    // softmax
    {
        const int w = tid >> 5;
        #pragma unroll
        for (int rr = 0; rr < 4; rr++) {
            int li = w * 4 + rr;
            float v = ssm[li * 33 + lane];
            float mx = v;
            #pragma unroll
            for (int o = 16; o; o >>= 1) mx = fmaxf(mx, __shfl_xor_sync(0xffffffffu, mx, o));
            float e = __expf(v - mx);
            float ss = e;
            #pragma unroll
            for (int o = 16; o; o >>= 1) ss += __shfl_xor_sync(0xffffffffu, ss, o);
            satt[li * 32 + lane] = e / ss;
        }
    }
    __syncthreads();

    // AV (fp16 V window)
    {
        const int li = tid >> 3;
        const int io = (tid & 7) * 8;
        float4 a0 = make_float4(0.f, 0.f, 0.f, 0.f);
        float4 a1 = make_float4(0.f, 0.f, 0.f, 0.f);
        #pragma unroll 8
        for (int k = 0; k < 32; k++) {
            float wv = satt[li * 32 + k];
            const __half* vr = swin + (li + k * DIL) * 64 + io;
            uint4 raw = *(const uint4*)vr;
            const __half2* hp = (const __half2*)&raw;
            float2 f0 = __half22float2(hp[0]);
            float2 f1 = __half22float2(hp[1]);
            float2 f2 = __half22float2(hp[2]);
            float2 f3 = __half22float2(hp[3]);
            a0.x += wv * f0.x; a0.y += wv * f0.y; a0.z += wv * f1.x; a0.w += wv * f1.y;
            a1.x += wv * f2.x; a1.y += wv * f2.y; a1.z += wv * f3.x; a1.w += wv * f3.y;
        }
        uint4 hv;
        hv.x = pack2(a0.x, a0.y);
        hv.y = pack2(a0.z, a0.w);
        hv.z = pack2(a1.x, a1.y);
        hv.w = pack2(a1.z, a1.w);
        *(uint4*)(oa + (rowbase + li) * NV + h * 64 + io) = hv;
    }
}

__global__ __launch_bounds__(256)
void head_d1(const __half* __restrict__ vp, const __half* __restrict__ sc,
             const float* __restrict__ Ws, const float* __restrict__ bsg,
             __half* __restrict__ oa)
{
    const int h = blockIdx.z;
    head_body<1, false>(vp, sc, Ws, bsg, oa, h, (h < 5) ? 0 : 1, 1);
}
__global__ __launch_bounds__(256)
void head_dyn(const __half* __restrict__ vp, const __half* __restrict__ sc,
              const float* __restrict__ Ws, const float* __restrict__ bsg,
              __half* __restrict__ oa)
{
    const int z = blockIdx.z;              // 0..3 -> heads 10..13
    const int h = 10 + z;
    const int s = (h < 12) ? 2 : (h == 12 ? 3 : 4);
    const int dil = (h < 12) ? 2 : (h == 12 ? 4 : 8);
    head_body<0, true>(vp, sc, Ws, bsg, oa, h, s, dil);
}

// ---------------- launcher ---------------------------------------------------
extern "C" void kernel_launch(void* const* d_in, const int* in_sizes, int n_in,
                              void* d_out, int out_size)
{
    const float* query = (const float*)d_in[0];
    const float* key   = (const float*)d_in[1];
    const float* value = (const float*)d_in[2];
    const float* Wq    = (const float*)d_in[3];
    const float* bq    = (const float*)d_in[4];
    const float* Wk    = (const float*)d_in[5];
    const float* bk    = (const float*)d_in[6];
    const float* Wv    = (const float*)d_in[7];
    const float* bv    = (const float*)d_in[8];
    const float* Ws    = (const float*)d_in[9];
    const float* bs    = (const float*)d_in[10];
    const float* Wc    = (const float*)d_in[11];
    const float* bc    = (const float*)d_in[12];
    float* out = (float*)d_out;

    float *bqp, *bkp;
    __half *qp, *kp, *vp, *sc, *qa, *ka, *va, *oa, *wq, *wk, *wv, *wc;
    cudaGetSymbolAddress((void**)&qp, g_qp);
    cudaGetSymbolAddress((void**)&kp, g_kp);
    cudaGetSymbolAddress((void**)&vp, g_vp);
    cudaGetSymbolAddress((void**)&sc, g_sc);
    cudaGetSymbolAddress((void**)&bqp, g_bqp);
    cudaGetSymbolAddress((void**)&bkp, g_bkp);
    cudaGetSymbolAddress((void**)&qa, g_qa);
    cudaGetSymbolAddress((void**)&ka, g_ka);
    cudaGetSymbolAddress((void**)&va, g_va);
    cudaGetSymbolAddress((void**)&oa, g_oa);
    cudaGetSymbolAddress((void**)&wq, g_wq);
    cudaGetSymbolAddress((void**)&wk, g_wk);
    cudaGetSymbolAddress((void**)&wv, g_wv);
    cudaGetSymbolAddress((void**)&wc, g_wc);

    cudaFuncSetAttribute(gemm_qkv, cudaFuncAttributeMaxDynamicSharedMemorySize, GEMM_SMEM);
    cudaFuncSetAttribute(gemm_out, cudaFuncAttributeMaxDynamicSharedMemorySize, GEMM_SMEM);

    auto ssz = [](int dil) { return (size_t)((31 * dil + 32) * 64 + 2048) * 2; };
    auto hsz = [](int dil) { return (size_t)(31 * dil + 32) * 128 + (size_t)HEAD_FIXED * 4; };
    cudaFuncSetAttribute(scores_d1,  cudaFuncAttributeMaxDynamicSharedMemorySize, (int)ssz(1));
    cudaFuncSetAttribute(scores_dyn, cudaFuncAttributeMaxDynamicSharedMemorySize, (int)ssz(8));
    cudaFuncSetAttribute(head_d1,    cudaFuncAttributeMaxDynamicSharedMemorySize, (int)hsz(1));
    cudaFuncSetAttribute(head_dyn,   cudaFuncAttributeMaxDynamicSharedMemorySize, (int)hsz(8));

    const int nact8 = ML * DMODEL / 8;

    // ---- conversions ----
    conv_act3<<<dim3((nact8 + 511) / 512, 3), 256>>>(
        (const float4*)query, (const float4*)key, (const float4*)value,
        (uint4*)qa, (uint4*)ka, (uint4*)va, nact8);
    conv_w_all<<<2690, 256>>>(Wq, Wk, Wv, Wc, bq, bk, wq, wk, wv, wc, bqp, bkp);

    // ---- fused Q/K/V projection ----
    gemm_qkv<<<dim3(13, 64), 256, GEMM_SMEM>>>(qa, ka, va, wq, wk, wv,
                                               bqp, bkp, bv, qp, kp, vp);

    // ---- per-subhead scores ----
    scores_d1<<<dim3(L_SZ / 32, B_SZ, 2),  256, ssz(1)>>>(qp, kp, sc);
    scores_dyn<<<dim3(L_SZ / 32, B_SZ, 3), 256, ssz(8)>>>(qp, kp, sc);

    // ---- per-head resample + softmax + AV ----
    head_d1<<<dim3(L_SZ / 32, B_SZ, 10), 256, hsz(1)>>>(vp, sc, Ws, bs, oa);
    head_dyn<<<dim3(L_SZ / 32, B_SZ, 4), 256, hsz(8)>>>(vp, sc, Ws, bs, oa);

    // ---- output projection ----
    gemm_out<<<dim3(8, 64), 256, GEMM_SMEM>>>(oa, wc, bc, out);
}

// round 14
// speedup vs baseline: 7.0788x; 1.0202x over previous
#include <cuda_runtime.h>
#include <cuda_fp16.h>
#include <cstdint>

// Problem constants
#define B_SZ   2
#define L_SZ   4096
#define DMODEL 1024
#define DINT   64
#define KW     32
#define SUBH   5
#define HEADS  14
#define ML     (B_SZ * L_SZ)          // 8192 rows
#define NQK    320
#define NQKP   384                    // padded to 3*128
#define NV     896

// ---------------- scratch (static device globals; no allocation) -------------
__device__ __half g_qp[ML * NQKP];
__device__ __half g_kp[ML * NQKP];
__device__ __half g_vp[ML * NV];
__device__ __half g_sc[SUBH * B_SZ * L_SZ * KW];  // per-subhead scores (fp16)
__device__ __half g_qa[ML * DMODEL];
__device__ __half g_ka[ML * DMODEL];
__device__ __half g_va[ML * DMODEL];
__device__ __half g_oa[ML * NV];
__device__ __half g_wq[NQKP * DMODEL];
__device__ __half g_wk[NQKP * DMODEL];
__device__ __half g_wv[NV * DMODEL];
__device__ __half g_wc[DMODEL * NV];
__device__ float g_bqp[NQKP], g_bkp[NQKP];

// ---------------- helpers ------------------------------------------------
__device__ __forceinline__ uint32_t smem_u32(const void* p) {
    uint32_t a;
    asm("{ .reg .u64 t; cvta.to.shared.u64 t, %1; cvt.u32.u64 %0, t; }" : "=r"(a) : "l"(p));
    return a;
}
__device__ __forceinline__ void cpa16(uint32_t s, const void* g) {
    asm volatile("cp.async.cg.shared.global [%0], [%1], 16;" :: "r"(s), "l"(g));
}
#define CPA_COMMIT() asm volatile("cp.async.commit_group;" ::: "memory")
#define CPA_WAIT(n)  asm volatile("cp.async.wait_group %0;" :: "n"(n) : "memory")

#define LDSM4(r0, r1, r2, r3, a) \
    asm volatile("ldmatrix.sync.aligned.m8n8.x4.shared.b16 {%0,%1,%2,%3}, [%4];" \
        : "=r"(r0), "=r"(r1), "=r"(r2), "=r"(r3) : "r"(a))

#define MMAF16(c, a, b0, b1) \
    asm volatile("mma.sync.aligned.m16n8k16.row.col.f32.f16.f16.f32 " \
        "{%0,%1,%2,%3},{%4,%5,%6,%7},{%8,%9},{%0,%1,%2,%3};" \
        : "+f"((c)[0]), "+f"((c)[1]), "+f"((c)[2]), "+f"((c)[3]) \
        : "r"((a)[0]), "r"((a)[1]), "r"((a)[2]), "r"((a)[3]), "r"(b0), "r"(b1))

__device__ __forceinline__ uint32_t pack2(float a, float b) {
    __half2 h;
    h.x = __float2half_rn(a); h.y = __float2half_rn(b);
    return *(uint32_t*)&h;
}

// ---------------- fused conversion kernel -------------------------------------
// blocks [0, 3072): activations (1024 blocks/tensor, 32 elems/thread, MLP=8)
// blocks [3072, 5760): weights; [5760, 5762): bias padding
#define ACT_BLKS_PER 1024
#define CONV_BLOCKS (3 * ACT_BLKS_PER + 2688 + 2)

__global__ __launch_bounds__(256)
void conv_all(const float4* __restrict__ q, const float4* __restrict__ k,
              const float4* __restrict__ v,
              uint4* __restrict__ qo, uint4* __restrict__ ko, uint4* __restrict__ vo,
              const float* __restrict__ Wq, const float* __restrict__ Wk,
              const float* __restrict__ Wv, const float* __restrict__ Wc,
              const float* __restrict__ bq, const float* __restrict__ bk,
              __half* __restrict__ wq, __half* __restrict__ wk,
              __half* __restrict__ wv, __half* __restrict__ wc,
              float* __restrict__ bqp, float* __restrict__ bkp)
{
    const int bidx = blockIdx.x, tid = threadIdx.x;

    if (bidx < 3 * ACT_BLKS_PER) {
        const int t = bidx / ACT_BLKS_PER;
        const int blk = bidx - t * ACT_BLKS_PER;
        const float4* in = (t == 0) ? q : (t == 1) ? k : v;
        uint4* o = (t == 0) ? qo : (t == 1) ? ko : vo;
        const int base = blk * 1024 + tid;      // uint4 output index, +256 per p
        float4 a[4], b[4];
        #pragma unroll
        for (int p = 0; p < 4; p++) {
            int i = base + p * 256;
            a[p] = in[2 * i];
            b[p] = in[2 * i + 1];
        }
        #pragma unroll
        for (int p = 0; p < 4; p++) {
            uint4 h;
            h.x = pack2(a[p].x, a[p].y);
            h.y = pack2(a[p].z, a[p].w);
            h.z = pack2(b[p].x, b[p].y);
            h.w = pack2(b[p].z, b[p].w);
            o[base + p * 256] = h;
        }
        return;
    }

    const int wb = bidx - 3 * ACT_BLKS_PER;     // 0..2689
    if (wb >= 2688) {
        const float* src = (wb == 2688) ? bq : bk;
        float* dst = (wb == 2688) ? bqp : bkp;
        for (int i = tid; i < NQKP; i += 256) dst[i] = (i < NQK) ? src[i] : 0.f;
        return;
    }
    if (wb < 768) {
        const bool isq = (wb < 384);
        const float* W = isq ? Wq : Wk;
        __half* dst = isq ? wq : wk;
        int n = isq ? wb : (wb - 384);
        if (n >= NQK) {
            for (int kk = tid; kk < DMODEL; kk += 256) dst[(size_t)n * DMODEL + kk] = __float2half(0.f);
            return;
        }
        int head = n >> 6, i = n & 63;
        for (int kk = tid; kk < DMODEL; kk += 256)
            dst[(size_t)n * DMODEL + kk] = __float2half_rn(W[((size_t)head * DMODEL + kk) * 64 + i]);
    } else if (wb < 1664) {
        int n = wb - 768;
        int head = n >> 6, i = n & 63;
        for (int kk = tid; kk < DMODEL; kk += 256)
            wv[(size_t)n * DMODEL + kk] = __float2half_rn(Wv[((size_t)head * DMODEL + kk) * 64 + i]);
    } else {
        int n = wb - 1664;
        for (int kk = tid; kk < NV; kk += 256)
            wc[(size_t)n * NV + kk] = __float2half_rn(Wc[(size_t)kk * DMODEL + n]);
    }
}

// ---------------- fp16 HMMA GEMM, 128x128 tile, K-chunk 64 -------------------
#define APAD 72
#define A_OFF 0
#define B_OFF 9216                    // 128 * 72
#define STE   18432
#define GEMM_SMEM (2 * STE * 2)       // 73728 bytes

template <bool OUT_HALF>
__device__ __forceinline__ void gemm_tile128(
    const __half* __restrict__ A, const __half* __restrict__ B,
    const float* __restrict__ bias, void* __restrict__ Cv,
    int m0, int n0, int N, int K, uint32_t sb)
{
    const int tid = threadIdx.x, lane = tid & 31, wid = tid >> 5;
    const int wm = wid >> 1, wn = wid & 1;

    float c[2][8][4];
    #pragma unroll
    for (int i = 0; i < 2; i++)
        #pragma unroll
        for (int j = 0; j < 8; j++)
            #pragma unroll
            for (int q = 0; q < 4; q++) c[i][j][q] = 0.f;

    const int ld_row0 = tid >> 3;
    const int ld_col  = (tid & 7) * 8;

    const int r = lane & 7, g = lane >> 3;
    const int a_ld_row = (g & 1) * 8 + r;
    const int a_ld_k   = (g >> 1) * 8;
    const int b_ld_row = (g >> 1) * 8 + r;
    const int b_ld_k   = (g & 1) * 8;

    const int nit = K >> 6;

    {
        uint32_t base = sb;
        #pragma unroll
        for (int i = 0; i < 4; i++) {
            int row = ld_row0 + i * 32;
            uint32_t so = base + (uint32_t)(row * APAD + ld_col) * 2;
            cpa16(so + A_OFF * 2, A + (size_t)(m0 + row) * K + ld_col);
            cpa16(so + B_OFF * 2, B + (size_t)(n0 + row) * K + ld_col);
        }
        CPA_COMMIT();
    }

    for (int it = 0; it < nit; ++it) {
        if (it + 1 < nit) {
            uint32_t base = sb + (uint32_t)(((it + 1) & 1) * STE) * 2;
            int k0 = (it + 1) << 6;
            #pragma unroll
            for (int i = 0; i < 4; i++) {
                int row = ld_row0 + i * 32;
                uint32_t so = base + (uint32_t)(row * APAD + ld_col) * 2;
                cpa16(so + A_OFF * 2, A + (size_t)(m0 + row) * K + k0 + ld_col);
                cpa16(so + B_OFF * 2, B + (size_t)(n0 + row) * K + k0 + ld_col);
            }
            CPA_COMMIT();
            CPA_WAIT(1);
        } else {
            CPA_WAIT(0);
        }
        __syncthreads();

        uint32_t base = sb + (uint32_t)((it & 1) * STE) * 2;
        #pragma unroll
        for (int kk = 0; kk < 64; kk += 16) {
            uint32_t ah[2][4];
            #pragma unroll
            for (int mt = 0; mt < 2; mt++) {
                uint32_t ad = base + (uint32_t)((wm * 32 + mt * 16 + a_ld_row) * APAD + kk + a_ld_k) * 2;
                LDSM4(ah[mt][0], ah[mt][1], ah[mt][2], ah[mt][3], ad + A_OFF * 2);
            }
            #pragma unroll
            for (int np = 0; np < 4; np++) {
                uint32_t bh[4];
                uint32_t bd = base + (uint32_t)((wn * 64 + np * 16 + b_ld_row) * APAD + kk + b_ld_k) * 2;
                LDSM4(bh[0], bh[1], bh[2], bh[3], bd + B_OFF * 2);
                #pragma unroll
                for (int mt = 0; mt < 2; mt++) {
                    MMAF16(c[mt][np * 2 + 0], ah[mt], bh[0], bh[1]);
                    MMAF16(c[mt][np * 2 + 1], ah[mt], bh[2], bh[3]);
                }
            }
        }
        __syncthreads();
    }

    #pragma unroll
    for (int mt = 0; mt < 2; mt++) {
        int row = m0 + wm * 32 + mt * 16 + (lane >> 2);
        #pragma unroll
        for (int nt = 0; nt < 8; nt++) {
            int col = n0 + wn * 64 + nt * 8 + (lane & 3) * 2;
            float2 bv = *(const float2*)(bias + col);
            float x0 = c[mt][nt][0] + bv.x, y0 = c[mt][nt][1] + bv.y;
            float x1 = c[mt][nt][2] + bv.x, y1 = c[mt][nt][3] + bv.y;
            if (OUT_HALF) {
                __half* C = (__half*)Cv;
                *(uint32_t*)(C + (size_t)row * N + col) = pack2(x0, y0);
                *(uint32_t*)(C + (size_t)(row + 8) * N + col) = pack2(x1, y1);
            } else {
                float* C = (float*)Cv;
                float2 v0; v0.x = x0; v0.y = y0;
                float2 v1; v1.x = x1; v1.y = y1;
                *(float2*)(C + (size_t)row * N + col) = v0;
                *(float2*)(C + (size_t)(row + 8) * N + col) = v1;
            }
        }
    }
}

// fused Q/K/V projection: grid (13, 64)
__global__ __launch_bounds__(256, 2)
void gemm_qkv(const __half* __restrict__ qa, const __half* __restrict__ ka,
              const __half* __restrict__ va,
              const __half* __restrict__ wq, const __half* __restrict__ wk,
              const __half* __restrict__ wv,
              const float* __restrict__ bqp, const float* __restrict__ bkp, const float* __restrict__ bv,
              __half* __restrict__ qp, __half* __restrict__ kp, __half* __restrict__ vp)
{
    extern __shared__ __half sm[];
    uint32_t sb = smem_u32(sm);
    const int m0 = blockIdx.y * 128;
    const int rr = blockIdx.x;
    if (rr < 3)
        gemm_tile128<true>(qa, wq, bqp, qp, m0, rr * 128, NQKP, DMODEL, sb);
    else if (rr < 6)
        gemm_tile128<true>(ka, wk, bkp, kp, m0, (rr - 3) * 128, NQKP, DMODEL, sb);
    else
        gemm_tile128<true>(va, wv, bv, vp, m0, (rr - 6) * 128, NV, DMODEL, sb);
}

// output projection: grid (8, 64)
__global__ __launch_bounds__(256, 2)
void gemm_out(const __half* __restrict__ A, const __half* __restrict__ B,
              const float* __restrict__ bias, float* __restrict__ C)
{
    extern __shared__ __half sm[];
    uint32_t sb = smem_u32(sm);
    gemm_tile128<false>(A, B, bias, C, blockIdx.y * 128, blockIdx.x * 128, DMODEL, NV, sb);
}

// ---------------- scores: merged all-subhead launch ---------------------------
template <int DILT, bool DYN>
__device__ __forceinline__ void scores_body(
    const __half* __restrict__ qp, const __half* __restrict__ kp,
    __half* __restrict__ sc, int s, int dil_rt)
{
    const int DIL = DYN ? dil_rt : DILT;
    const int WIN = 31 * DIL + 32;
    extern __shared__ __half sh[];
    __half* swin = sh;                 // WIN*64
    __half* sq   = swin + WIN * 64;    // 2048

    const int l0 = blockIdx.x * 32;
    const int b  = blockIdx.y;
    const int tid = threadIdx.x, lane = tid & 31;
    const int w0 = l0 - 16 * DIL;
    const long rowbase = (long)b * L_SZ + l0;
    const int c8 = (tid & 7) * 8;

    {
        int row = tid >> 3;
        *(uint4*)(sq + row * 64 + c8) =
            *(const uint4*)(qp + (rowbase + row) * NQKP + s * 64 + c8);
    }
    for (int r = tid >> 3; r < WIN; r += 32) {
        int g = w0 + r; g = g < 0 ? 0 : (g > L_SZ - 1 ? L_SZ - 1 : g);
        *(uint4*)(swin + r * 64 + c8) =
            *(const uint4*)(kp + ((long)b * L_SZ + g) * NQKP + s * 64 + c8);
    }
    __syncthreads();

    {
        const int li = tid >> 3;
        const int kb = (tid & 7) * 4;
        float acc0 = 0.f, acc1 = 0.f, acc2 = 0.f, acc3 = 0.f;
        const __half* qrow = sq + li * 64;
        const __half* wr0 = swin + (li + (kb + 0) * DIL) * 64;
        const __half* wr1 = swin + (li + (kb + 1) * DIL) * 64;
        const __half* wr2 = swin + (li + (kb + 2) * DIL) * 64;
        const __half* wr3 = swin + (li + (kb + 3) * DIL) * 64;
        #pragma unroll
        for (int t8 = 0; t8 < 8; t8++) {
            int i = ((t8 + lane) & 7) * 8;
            uint4 qr = *(const uint4*)(qrow + i);
            uint4 r0 = *(const uint4*)(wr0 + i);
            uint4 r1 = *(const uint4*)(wr1 + i);
            uint4 r2 = *(const uint4*)(wr2 + i);
            uint4 r3 = *(const uint4*)(wr3 + i);
            const __half2* qh = (const __half2*)&qr;
            const __half2* h0 = (const __half2*)&r0;
            const __half2* h1 = (const __half2*)&r1;
            const __half2* h2 = (const __half2*)&r2;
            const __half2* h3 = (const __half2*)&r3;
            #pragma unroll
            for (int u = 0; u < 4; u++) {
                float2 qf = __half22float2(qh[u]);
                float2 f0 = __half22float2(h0[u]);
                float2 f1 = __half22float2(h1[u]);
                float2 f2 = __half22float2(h2[u]);
                float2 f3 = __half22float2(h3[u]);
                acc0 += qf.x * f0.x + qf.y * f0.y;
                acc1 += qf.x * f1.x + qf.y * f1.y;
                acc2 += qf.x * f2.x + qf.y * f2.y;
                acc3 += qf.x * f3.x + qf.y * f3.y;
            }
        }
        uint2 o;
        o.x = pack2(acc0 * 0.125f, acc1 * 0.125f);
        o.y = pack2(acc2 * 0.125f, acc3 * 0.125f);
        *(uint2*)(sc + (((size_t)s * B_SZ + b) * L_SZ + l0 + li) * KW + kb) = o;
    }
}

__global__ __launch_bounds__(256)
void scores_all(const __half* __restrict__ qp, const __half* __restrict__ kp, __half* __restrict__ sc)
{
    const int z = blockIdx.z;     // 0..4 = subhead
    if (z < 2) {
        scores_body<1, false>(qp, kp, sc, z, 1);
    } else {
        const int dil = (z == 2) ? 2 : (z == 3 ? 4 : 8);
        scores_body<0, true>(qp, kp, sc, z, dil);
    }
}

// ---------------- head kernel: resample + softmax + AV (fp16 V, fp16 sc) -----
#define HEAD_FIXED (1024 + 1152 + 1056 + 1024 + 32)

template <int DILT, bool DYN>
__device__ __forceinline__ void head_body(
    const __half* __restrict__ vp, const __half* __restrict__ sc_g,
    const float* __restrict__ Ws, const float* __restrict__ bsg,
    __half* __restrict__ oa, int h, int s, int dil_rt)
{
    const int DIL = DYN ? dil_rt : DILT;
    const int WIN = 31 * DIL + 32;
    extern __shared__ char sab[];
    __half* swin = (__half*)sab;
    float* sws  = (float*)(sab + (size_t)WIN * 128);
    float* ssc  = sws + 1024;
    float* ssm  = ssc + 1152;
    float* satt = ssm + 1056;
    float* sbs  = satt + 1024;

    const int l0 = blockIdx.x * 32;
    const int b  = blockIdx.y;
    const int tid = threadIdx.x, lane = tid & 31;
    const int w0 = l0 - 16 * DIL;
    const long rowbase = (long)b * L_SZ + l0;

    *(float4*)(sws + tid * 4) = *(const float4*)(Ws + (size_t)h * 1024 + tid * 4);
    if (tid < 32) sbs[tid] = bsg[h * KW + tid];
    {
        int li = tid >> 3, kb = (tid & 7) * 4;
        uint2 raw = *(const uint2*)(sc_g + (((size_t)s * B_SZ + b) * L_SZ + l0 + li) * KW + kb);
        float2 f0 = __half22float2(*(__half2*)&raw.x);
        float2 f1 = __half22float2(*(__half2*)&raw.y);
        ssc[li * 36 + kb + 0] = f0.x;
        ssc[li * 36 + kb + 1] = f0.y;
        ssc[li * 36 + kb + 2] = f1.x;
        ssc[li * 36 + kb + 3] = f1.y;
    }
    for (int r = tid >> 3; r < WIN; r += 32) {
        int g = w0 + r; g = g < 0 ? 0 : (g > L_SZ - 1 ? L_SZ - 1 : g);
        int c8 = (tid & 7) * 8;
        *(uint4*)(swin + r * 64 + c8) =
            *(const uint4*)(vp + ((long)b * L_SZ + g) * NV + h * 64 + c8);
    }
    __syncthreads();

    {
        const int li = tid >> 3;
        const int m4 = (tid & 7) * 4;
        float a0 = sbs[m4], a1 = sbs[m4 + 1], a2 = sbs[m4 + 2], a3 = sbs[m4 + 3];
        #pragma unroll 8
        for (int k = 0; k < 32; k++) {
            float scv = ssc[li * 36 + k];
            float4 wv = *(const float4*)(sws + k * 32 + m4);
            a0 += scv * wv.x; a1 += scv * wv.y; a2 += scv * wv.z; a3 += scv * wv.w;
        }
        ssm[li * 33 + m4 + 0] = a0;
        ssm[li * 33 + m4 + 1] = a1;
        ssm[li * 33 + m4 + 2] = a2;
        ssm[li * 33 + m4 + 3] = a3;
    }
    __syncthreads();

    {
        const int w = tid >> 5;
        #pragma unroll
        for (int rr = 0; rr < 4; rr++) {
            int li = w * 4 + rr;
            float v = ssm[li * 33 + lane];
            float mx = v;
            #pragma unroll
            for (int o = 16; o; o >>= 1) mx = fmaxf(mx, __shfl_xor_sync(0xffffffffu, mx, o));
            float e = __expf(v - mx);
            float ss = e;
            #pragma unroll
            for (int o = 16; o; o >>= 1) ss += __shfl_xor_sync(0xffffffffu, ss, o);
            satt[li * 32 + lane] = e / ss;
        }
    }
    __syncthreads();

    {
        const int li = tid >> 3;
        const int io = (tid & 7) * 8;
        float4 a0 = make_float4(0.f, 0.f, 0.f, 0.f);
        float4 a1 = make_float4(0.f, 0.f, 0.f, 0.f);
        #pragma unroll 8
        for (int k = 0; k < 32; k++) {
            float wv = satt[li * 32 + k];
            const __half* vr = swin + (li + k * DIL) * 64 + io;
            uint4 raw = *(const uint4*)vr;
            const __half2* hp = (const __half2*)&raw;
            float2 f0 = __half22float2(hp[0]);
            float2 f1 = __half22float2(hp[1]);
            float2 f2 = __half22float2(hp[2]);
            float2 f3 = __half22float2(hp[3]);
            a0.x += wv * f0.x; a0.y += wv * f0.y; a0.z += wv * f1.x; a0.w += wv * f1.y;
            a1.x += wv * f2.x; a1.y += wv * f2.y; a1.z += wv * f3.x; a1.w += wv * f3.y;
        }
        uint4 hv;
        hv.x = pack2(a0.x, a0.y);
        hv.y = pack2(a0.z, a0.w);
        hv.z = pack2(a1.x, a1.y);
        hv.w = pack2(a1.z, a1.w);
        *(uint4*)(oa + (rowbase + li) * NV + h * 64 + io) = hv;
    }
}

__global__ __launch_bounds__(256)
void head_d1(const __half* __restrict__ vp, const __half* __restrict__ sc,
             const float* __restrict__ Ws, const float* __restrict__ bsg,
             __half* __restrict__ oa)
{
    const int h = blockIdx.z;
    head_body<1, false>(vp, sc, Ws, bsg, oa, h, (h < 5) ? 0 : 1, 1);
}
__global__ __launch_bounds__(256)
void head_dyn(const __half* __restrict__ vp, const __half* __restrict__ sc,
              const float* __restrict__ Ws, const float* __restrict__ bsg,
              __half* __restrict__ oa)
{
    const int z = blockIdx.z;              // 0..3 -> heads 10..13
    const int h = 10 + z;
    const int s = (h < 12) ? 2 : (h == 12 ? 3 : 4);
    const int dil = (h < 12) ? 2 : (h == 12 ? 4 : 8);
    head_body<0, true>(vp, sc, Ws, bsg, oa, h, s, dil);
}

// ---------------- launcher ---------------------------------------------------
extern "C" void kernel_launch(void* const* d_in, const int* in_sizes, int n_in,
                              void* d_out, int out_size)
{
    const float* query = (const float*)d_in[0];
    const float* key   = (const float*)d_in[1];
    const float* value = (const float*)d_in[2];
    const float* Wq    = (const float*)d_in[3];
    const float* bq    = (const float*)d_in[4];
    const float* Wk    = (const float*)d_in[5];
    const float* bk    = (const float*)d_in[6];
    const float* Wv    = (const float*)d_in[7];
    const float* bv    = (const float*)d_in[8];
    const float* Ws    = (const float*)d_in[9];
    const float* bs    = (const float*)d_in[10];
    const float* Wc    = (const float*)d_in[11];
    const float* bc    = (const float*)d_in[12];
    float* out = (float*)d_out;

    float *bqp, *bkp;
    __half *qp, *kp, *vp, *sc, *qa, *ka, *va, *oa, *wq, *wk, *wv, *wc;
    cudaGetSymbolAddress((void**)&qp, g_qp);
    cudaGetSymbolAddress((void**)&kp, g_kp);
    cudaGetSymbolAddress((void**)&vp, g_vp);
    cudaGetSymbolAddress((void**)&sc, g_sc);
    cudaGetSymbolAddress((void**)&bqp, g_bqp);
    cudaGetSymbolAddress((void**)&bkp, g_bkp);
    cudaGetSymbolAddress((void**)&qa, g_qa);
    cudaGetSymbolAddress((void**)&ka, g_ka);
    cudaGetSymbolAddress((void**)&va, g_va);
    cudaGetSymbolAddress((void**)&oa, g_oa);
    cudaGetSymbolAddress((void**)&wq, g_wq);
    cudaGetSymbolAddress((void**)&wk, g_wk);
    cudaGetSymbolAddress((void**)&wv, g_wv);
    cudaGetSymbolAddress((void**)&wc, g_wc);

    cudaFuncSetAttribute(gemm_qkv, cudaFuncAttributeMaxDynamicSharedMemorySize, GEMM_SMEM);
    cudaFuncSetAttribute(gemm_out, cudaFuncAttributeMaxDynamicSharedMemorySize, GEMM_SMEM);

    auto ssz = [](int dil) { return (size_t)((31 * dil + 32) * 64 + 2048) * 2; };
    auto hsz = [](int dil) { return (size_t)(31 * dil + 32) * 128 + (size_t)HEAD_FIXED * 4; };
    cudaFuncSetAttribute(scores_all, cudaFuncAttributeMaxDynamicSharedMemorySize, (int)ssz(8));
    cudaFuncSetAttribute(head_d1,    cudaFuncAttributeMaxDynamicSharedMemorySize, (int)hsz(1));
    cudaFuncSetAttribute(head_dyn,   cudaFuncAttributeMaxDynamicSharedMemorySize, (int)hsz(8));

    // ---- conversions (one launch) ----
    conv_all<<<CONV_BLOCKS, 256>>>(
        (const float4*)query, (const float4*)key, (const float4*)value,
        (uint4*)qa, (uint4*)ka, (uint4*)va,
        Wq, Wk, Wv, Wc, bq, bk, wq, wk, wv, wc, bqp, bkp);

    // ---- fused Q/K/V projection ----
    gemm_qkv<<<dim3(13, 64), 256, GEMM_SMEM>>>(qa, ka, va, wq, wk, wv,
                                               bqp, bkp, bv, qp, kp, vp);

    // ---- per-subhead scores (one launch, all 5 subheads) ----
    scores_all<<<dim3(L_SZ / 32, B_SZ, SUBH), 256, ssz(8)>>>(qp, kp, sc);

    // ---- per-head resample + softmax + AV ----
    head_d1<<<dim3(L_SZ / 32, B_SZ, 10), 256, hsz(1)>>>(vp, sc, Ws, bs, oa);
    head_dyn<<<dim3(L_SZ / 32, B_SZ, 4), 256, hsz(8)>>>(vp, sc, Ws, bs, oa);

    // ---- output projection ----
    gemm_out<<<dim3(8, 64), 256, GEMM_SMEM>>>(oa, wc, bc, out);
}

// round 15
// speedup vs baseline: 7.2564x; 1.0251x over previous
#include <cuda_runtime.h>
#include <cuda_fp16.h>
#include <cstdint>

// Problem constants
#define B_SZ   2
#define L_SZ   4096
#define DMODEL 1024
#define DINT   64
#define KW     32
#define SUBH   5
#define HEADS  14
#define ML     (B_SZ * L_SZ)          // 8192 rows
#define NQK    320
#define NQKP   384                    // padded to 3*128
#define NV     896

// ---------------- scratch (static device globals; no allocation) -------------
__device__ __half g_qp[ML * NQKP];
__device__ __half g_kp[ML * NQKP];
__device__ __half g_vp[ML * NV];
__device__ __half g_sc[SUBH * B_SZ * L_SZ * KW];
__device__ __half g_qa[ML * DMODEL];
__device__ __half g_ka[ML * DMODEL];
__device__ __half g_va[ML * DMODEL];
__device__ __half g_oa[ML * NV];
__device__ __half g_wq[NQKP * DMODEL];
__device__ __half g_wk[NQKP * DMODEL];
__device__ __half g_wv[NV * DMODEL];
__device__ __half g_wc[DMODEL * NV];
__device__ float g_bqp[NQKP], g_bkp[NQKP];

// ---------------- helpers ------------------------------------------------
__device__ __forceinline__ uint32_t smem_u32(const void* p) {
    uint32_t a;
    asm("{ .reg .u64 t; cvta.to.shared.u64 t, %1; cvt.u32.u64 %0, t; }" : "=r"(a) : "l"(p));
    return a;
}
__device__ __forceinline__ void cpa16(uint32_t s, const void* g) {
    asm volatile("cp.async.cg.shared.global [%0], [%1], 16;" :: "r"(s), "l"(g));
}
#define CPA_COMMIT() asm volatile("cp.async.commit_group;" ::: "memory")
#define CPA_WAIT(n)  asm volatile("cp.async.wait_group %0;" :: "n"(n) : "memory")

#define LDSM4(r0, r1, r2, r3, a) \
    asm volatile("ldmatrix.sync.aligned.m8n8.x4.shared.b16 {%0,%1,%2,%3}, [%4];" \
        : "=r"(r0), "=r"(r1), "=r"(r2), "=r"(r3) : "r"(a))

#define MMAF16(c, a, b0, b1) \
    asm volatile("mma.sync.aligned.m16n8k16.row.col.f32.f16.f16.f32 " \
        "{%0,%1,%2,%3},{%4,%5,%6,%7},{%8,%9},{%0,%1,%2,%3};" \
        : "+f"((c)[0]), "+f"((c)[1]), "+f"((c)[2]), "+f"((c)[3]) \
        : "r"((a)[0]), "r"((a)[1]), "r"((a)[2]), "r"((a)[3]), "r"(b0), "r"(b1))

__device__ __forceinline__ uint32_t pack2(float a, float b) {
    __half2 h;
    h.x = __float2half_rn(a); h.y = __float2half_rn(b);
    return *(uint32_t*)&h;
}

// ---------------- fused conversion kernel -------------------------------------
#define ACT_BLKS_PER 1024
#define CONV_BLOCKS (3 * ACT_BLKS_PER + 2688 + 2)

__global__ __launch_bounds__(256)
void conv_all(const float4* __restrict__ q, const float4* __restrict__ k,
              const float4* __restrict__ v,
              uint4* __restrict__ qo, uint4* __restrict__ ko, uint4* __restrict__ vo,
              const float* __restrict__ Wq, const float* __restrict__ Wk,
              const float* __restrict__ Wv, const float* __restrict__ Wc,
              const float* __restrict__ bq, const float* __restrict__ bk,
              __half* __restrict__ wq, __half* __restrict__ wk,
              __half* __restrict__ wv, __half* __restrict__ wc,
              float* __restrict__ bqp, float* __restrict__ bkp)
{
    const int bidx = blockIdx.x, tid = threadIdx.x;

    if (bidx < 3 * ACT_BLKS_PER) {
        const int t = bidx / ACT_BLKS_PER;
        const int blk = bidx - t * ACT_BLKS_PER;
        const float4* in = (t == 0) ? q : (t == 1) ? k : v;
        uint4* o = (t == 0) ? qo : (t == 1) ? ko : vo;
        const int base = blk * 1024 + tid;
        float4 a[4], b[4];
        #pragma unroll
        for (int p = 0; p < 4; p++) {
            int i = base + p * 256;
            a[p] = in[2 * i];
            b[p] = in[2 * i + 1];
        }
        #pragma unroll
        for (int p = 0; p < 4; p++) {
            uint4 h;
            h.x = pack2(a[p].x, a[p].y);
            h.y = pack2(a[p].z, a[p].w);
            h.z = pack2(b[p].x, b[p].y);
            h.w = pack2(b[p].z, b[p].w);
            o[base + p * 256] = h;
        }
        return;
    }

    const int wb = bidx - 3 * ACT_BLKS_PER;
    if (wb >= 2688) {
        const float* src = (wb == 2688) ? bq : bk;
        float* dst = (wb == 2688) ? bqp : bkp;
        for (int i = tid; i < NQKP; i += 256) dst[i] = (i < NQK) ? src[i] : 0.f;
        return;
    }
    if (wb < 768) {
        const bool isq = (wb < 384);
        const float* W = isq ? Wq : Wk;
        __half* dst = isq ? wq : wk;
        int n = isq ? wb : (wb - 384);
        if (n >= NQK) {
            for (int kk = tid; kk < DMODEL; kk += 256) dst[(size_t)n * DMODEL + kk] = __float2half(0.f);
            return;
        }
        int head = n >> 6, i = n & 63;
        for (int kk = tid; kk < DMODEL; kk += 256)
            dst[(size_t)n * DMODEL + kk] = __float2half_rn(W[((size_t)head * DMODEL + kk) * 64 + i]);
    } else if (wb < 1664) {
        int n = wb - 768;
        int head = n >> 6, i = n & 63;
        for (int kk = tid; kk < DMODEL; kk += 256)
            wv[(size_t)n * DMODEL + kk] = __float2half_rn(Wv[((size_t)head * DMODEL + kk) * 64 + i]);
    } else {
        int n = wb - 1664;
        for (int kk = tid; kk < NV; kk += 256)
            wc[(size_t)n * NV + kk] = __float2half_rn(Wc[(size_t)kk * DMODEL + n]);
    }
}

// ---------------- fp16 HMMA GEMM, 128x128 tile, K-chunk 64 -------------------
#define APAD 72
#define A_OFF 0
#define B_OFF 9216
#define STE   18432
#define GEMM_SMEM (2 * STE * 2)

template <bool OUT_HALF>
__device__ __forceinline__ void gemm_tile128(
    const __half* __restrict__ A, const __half* __restrict__ B,
    const float* __restrict__ bias, void* __restrict__ Cv,
    int m0, int n0, int N, int K, uint32_t sb)
{
    const int tid = threadIdx.x, lane = tid & 31, wid = tid >> 5;
    const int wm = wid >> 1, wn = wid & 1;

    float c[2][8][4];
    #pragma unroll
    for (int i = 0; i < 2; i++)
        #pragma unroll
        for (int j = 0; j < 8; j++)
            #pragma unroll
            for (int q = 0; q < 4; q++) c[i][j][q] = 0.f;

    const int ld_row0 = tid >> 3;
    const int ld_col  = (tid & 7) * 8;

    const int r = lane & 7, g = lane >> 3;
    const int a_ld_row = (g & 1) * 8 + r;
    const int a_ld_k   = (g >> 1) * 8;
    const int b_ld_row = (g >> 1) * 8 + r;
    const int b_ld_k   = (g & 1) * 8;

    const int nit = K >> 6;

    {
        uint32_t base = sb;
        #pragma unroll
        for (int i = 0; i < 4; i++) {
            int row = ld_row0 + i * 32;
            uint32_t so = base + (uint32_t)(row * APAD + ld_col) * 2;
            cpa16(so + A_OFF * 2, A + (size_t)(m0 + row) * K + ld_col);
            cpa16(so + B_OFF * 2, B + (size_t)(n0 + row) * K + ld_col);
        }
        CPA_COMMIT();
    }

    for (int it = 0; it < nit; ++it) {
        if (it + 1 < nit) {
            uint32_t base = sb + (uint32_t)(((it + 1) & 1) * STE) * 2;
            int k0 = (it + 1) << 6;
            #pragma unroll
            for (int i = 0; i < 4; i++) {
                int row = ld_row0 + i * 32;
                uint32_t so = base + (uint32_t)(row * APAD + ld_col) * 2;
                cpa16(so + A_OFF * 2, A + (size_t)(m0 + row) * K + k0 + ld_col);
                cpa16(so + B_OFF * 2, B + (size_t)(n0 + row) * K + k0 + ld_col);
            }
            CPA_COMMIT();
            CPA_WAIT(1);
        } else {
            CPA_WAIT(0);
        }
        __syncthreads();

        uint32_t base = sb + (uint32_t)((it & 1) * STE) * 2;
        #pragma unroll
        for (int kk = 0; kk < 64; kk += 16) {
            uint32_t ah[2][4];
            #pragma unroll
            for (int mt = 0; mt < 2; mt++) {
                uint32_t ad = base + (uint32_t)((wm * 32 + mt * 16 + a_ld_row) * APAD + kk + a_ld_k) * 2;
                LDSM4(ah[mt][0], ah[mt][1], ah[mt][2], ah[mt][3], ad + A_OFF * 2);
            }
            #pragma unroll
            for (int np = 0; np < 4; np++) {
                uint32_t bh[4];
                uint32_t bd = base + (uint32_t)((wn * 64 + np * 16 + b_ld_row) * APAD + kk + b_ld_k) * 2;
                LDSM4(bh[0], bh[1], bh[2], bh[3], bd + B_OFF * 2);
                #pragma unroll
                for (int mt = 0; mt < 2; mt++) {
                    MMAF16(c[mt][np * 2 + 0], ah[mt], bh[0], bh[1]);
                    MMAF16(c[mt][np * 2 + 1], ah[mt], bh[2], bh[3]);
                }
            }
        }
        __syncthreads();
    }

    #pragma unroll
    for (int mt = 0; mt < 2; mt++) {
        int row = m0 + wm * 32 + mt * 16 + (lane >> 2);
        #pragma unroll
        for (int nt = 0; nt < 8; nt++) {
            int col = n0 + wn * 64 + nt * 8 + (lane & 3) * 2;
            float2 bv = *(const float2*)(bias + col);
            float x0 = c[mt][nt][0] + bv.x, y0 = c[mt][nt][1] + bv.y;
            float x1 = c[mt][nt][2] + bv.x, y1 = c[mt][nt][3] + bv.y;
            if (OUT_HALF) {
                __half* C = (__half*)Cv;
                *(uint32_t*)(C + (size_t)row * N + col) = pack2(x0, y0);
                *(uint32_t*)(C + (size_t)(row + 8) * N + col) = pack2(x1, y1);
            } else {
                float* C = (float*)Cv;
                float2 v0; v0.x = x0; v0.y = y0;
                float2 v1; v1.x = x1; v1.y = y1;
                *(float2*)(C + (size_t)row * N + col) = v0;
                *(float2*)(C + (size_t)(row + 8) * N + col) = v1;
            }
        }
    }
}

__global__ __launch_bounds__(256, 2)
void gemm_qkv(const __half* __restrict__ qa, const __half* __restrict__ ka,
              const __half* __restrict__ va,
              const __half* __restrict__ wq, const __half* __restrict__ wk,
              const __half* __restrict__ wv,
              const float* __restrict__ bqp, const float* __restrict__ bkp, const float* __restrict__ bv,
              __half* __restrict__ qp, __half* __restrict__ kp, __half* __restrict__ vp)
{
    extern __shared__ __half sm[];
    uint32_t sb = smem_u32(sm);
    const int m0 = blockIdx.y * 128;
    const int rr = blockIdx.x;
    if (rr < 3)
        gemm_tile128<true>(qa, wq, bqp, qp, m0, rr * 128, NQKP, DMODEL, sb);
    else if (rr < 6)
        gemm_tile128<true>(ka, wk, bkp, kp, m0, (rr - 3) * 128, NQKP, DMODEL, sb);
    else
        gemm_tile128<true>(va, wv, bv, vp, m0, (rr - 6) * 128, NV, DMODEL, sb);
}

__global__ __launch_bounds__(256, 2)
void gemm_out(const __half* __restrict__ A, const __half* __restrict__ B,
              const float* __restrict__ bias, float* __restrict__ C)
{
    extern __shared__ __half sm[];
    uint32_t sb = smem_u32(sm);
    gemm_tile128<false>(A, B, bias, C, blockIdx.y * 128, blockIdx.x * 128, DMODEL, NV, sb);
}

// ---------------- scores: merged all-subhead launch ---------------------------
template <int DILT, bool DYN>
__device__ __forceinline__ void scores_body(
    const __half* __restrict__ qp, const __half* __restrict__ kp,
    __half* __restrict__ sc, int s, int dil_rt)
{
    const int DIL = DYN ? dil_rt : DILT;
    const int WIN = 31 * DIL + 32;
    extern __shared__ __half sh[];
    __half* swin = sh;
    __half* sq   = swin + WIN * 64;

    const int l0 = blockIdx.x * 32;
    const int b  = blockIdx.y;
    const int tid = threadIdx.x, lane = tid & 31;
    const int w0 = l0 - 16 * DIL;
    const long rowbase = (long)b * L_SZ + l0;
    const int c8 = (tid & 7) * 8;

    {
        int row = tid >> 3;
        *(uint4*)(sq + row * 64 + c8) =
            *(const uint4*)(qp + (rowbase + row) * NQKP + s * 64 + c8);
    }
    for (int r = tid >> 3; r < WIN; r += 32) {
        int g = w0 + r; g = g < 0 ? 0 : (g > L_SZ - 1 ? L_SZ - 1 : g);
        *(uint4*)(swin + r * 64 + c8) =
            *(const uint4*)(kp + ((long)b * L_SZ + g) * NQKP + s * 64 + c8);
    }
    __syncthreads();

    {
        const int li = tid >> 3;
        const int kb = (tid & 7) * 4;
        float acc0 = 0.f, acc1 = 0.f, acc2 = 0.f, acc3 = 0.f;
        const __half* qrow = sq + li * 64;
        const __half* wr0 = swin + (li + (kb + 0) * DIL) * 64;
        const __half* wr1 = swin + (li + (kb + 1) * DIL) * 64;
        const __half* wr2 = swin + (li + (kb + 2) * DIL) * 64;
        const __half* wr3 = swin + (li + (kb + 3) * DIL) * 64;
        #pragma unroll
        for (int t8 = 0; t8 < 8; t8++) {
            int i = ((t8 + lane) & 7) * 8;
            uint4 qr = *(const uint4*)(qrow + i);
            uint4 r0 = *(const uint4*)(wr0 + i);
            uint4 r1 = *(const uint4*)(wr1 + i);
            uint4 r2 = *(const uint4*)(wr2 + i);
            uint4 r3 = *(const uint4*)(wr3 + i);
            const __half2* qh = (const __half2*)&qr;
            const __half2* h0 = (const __half2*)&r0;
            const __half2* h1 = (const __half2*)&r1;
            const __half2* h2 = (const __half2*)&r2;
            const __half2* h3 = (const __half2*)&r3;
            #pragma unroll
            for (int u = 0; u < 4; u++) {
                float2 qf = __half22float2(qh[u]);
                float2 f0 = __half22float2(h0[u]);
                float2 f1 = __half22float2(h1[u]);
                float2 f2 = __half22float2(h2[u]);
                float2 f3 = __half22float2(h3[u]);
                acc0 += qf.x * f0.x + qf.y * f0.y;
                acc1 += qf.x * f1.x + qf.y * f1.y;
                acc2 += qf.x * f2.x + qf.y * f2.y;
                acc3 += qf.x * f3.x + qf.y * f3.y;
            }
        }
        uint2 o;
        o.x = pack2(acc0 * 0.125f, acc1 * 0.125f);
        o.y = pack2(acc2 * 0.125f, acc3 * 0.125f);
        *(uint2*)(sc + (((size_t)s * B_SZ + b) * L_SZ + l0 + li) * KW + kb) = o;
    }
}

__global__ __launch_bounds__(256)
void scores_all(const __half* __restrict__ qp, const __half* __restrict__ kp, __half* __restrict__ sc)
{
    const int z = blockIdx.z;
    if (z < 2) {
        scores_body<1, false>(qp, kp, sc, z, 1);
    } else {
        const int dil = (z == 2) ? 2 : (z == 3 ? 4 : 8);
        scores_body<0, true>(qp, kp, sc, z, dil);
    }
}

// ---------------- head kernel: resample + softmax + AV ------------------------
// smem: swin[WIN*64 half] | sws_h[1024 half] | ssc[1152 f] | ssm[1056 f] | satt[1024 f] | sbs[32 f]
#define HEAD_FIXED_B (1024 * 2 + (1152 + 1056 + 1024 + 32) * 4)

template <int DILT, bool DYN>
__device__ __forceinline__ void head_body(
    const __half* __restrict__ vp, const __half* __restrict__ sc_g,
    const float* __restrict__ Ws, const float* __restrict__ bsg,
    __half* __restrict__ oa, int h, int s, int dil_rt)
{
    const int DIL = DYN ? dil_rt : DILT;
    const int WIN = 31 * DIL + 32;
    extern __shared__ char sab[];
    __half* swin  = (__half*)sab;
    __half* sws_h = (__half*)(sab + (size_t)WIN * 128);
    float* ssc  = (float*)(sws_h + 1024);
    float* ssm  = ssc + 1152;
    float* satt = ssm + 1056;
    float* sbs  = satt + 1024;

    const int l0 = blockIdx.x * 32;
    const int b  = blockIdx.y;
    const int tid = threadIdx.x, lane = tid & 31;
    const int w0 = l0 - 16 * DIL;
    const long rowbase = (long)b * L_SZ + l0;

    // loads: Ws (fp32->fp16), bs, sc tile, V window
    {
        float4 wv4 = *(const float4*)(Ws + (size_t)h * 1024 + tid * 4);
        uint2 wp;
        wp.x = pack2(wv4.x, wv4.y);
        wp.y = pack2(wv4.z, wv4.w);
        *(uint2*)(sws_h + tid * 4) = wp;
    }
    if (tid < 32) sbs[tid] = bsg[h * KW + tid];
    {
        int li = tid >> 3, kb = (tid & 7) * 4;
        uint2 raw = *(const uint2*)(sc_g + (((size_t)s * B_SZ + b) * L_SZ + l0 + li) * KW + kb);
        float2 f0 = __half22float2(*(__half2*)&raw.x);
        float2 f1 = __half22float2(*(__half2*)&raw.y);
        ssc[li * 36 + kb + 0] = f0.x;
        ssc[li * 36 + kb + 1] = f0.y;
        ssc[li * 36 + kb + 2] = f1.x;
        ssc[li * 36 + kb + 3] = f1.y;
    }
    for (int r = tid >> 3; r < WIN; r += 32) {
        int g = w0 + r; g = g < 0 ? 0 : (g > L_SZ - 1 ? L_SZ - 1 : g);
        int c8 = (tid & 7) * 8;
        *(uint4*)(swin + r * 64 + c8) =
            *(const uint4*)(vp + ((long)b * L_SZ + g) * NV + h * 64 + c8);
    }
    __syncthreads();

    // resample (fp16 Ws)
    {
        const int li = tid >> 3;
        const int m4 = (tid & 7) * 4;
        float a0 = sbs[m4], a1 = sbs[m4 + 1], a2 = sbs[m4 + 2], a3 = sbs[m4 + 3];
        #pragma unroll 8
        for (int k = 0; k < 32; k++) {
            float scv = ssc[li * 36 + k];
            uint2 raw = *(const uint2*)(sws_h + k * 32 + m4);
            float2 w0f = __half22float2(*(__half2*)&raw.x);
            float2 w1f = __half22float2(*(__half2*)&raw.y);
            a0 += scv * w0f.x; a1 += scv * w0f.y; a2 += scv * w1f.x; a3 += scv * w1f.y;
        }
        ssm[li * 33 + m4 + 0] = a0;
        ssm[li * 33 + m4 + 1] = a1;
        ssm[li * 33 + m4 + 2] = a2;
        ssm[li * 33 + m4 + 3] = a3;
    }
    __syncthreads();

    // softmax
    {
        const int w = tid >> 5;
        #pragma unroll
        for (int rr = 0; rr < 4; rr++) {
            int li = w * 4 + rr;
            float v = ssm[li * 33 + lane];
            float mx = v;
            #pragma unroll
            for (int o = 16; o; o >>= 1) mx = fmaxf(mx, __shfl_xor_sync(0xffffffffu, mx, o));
            float e = __expf(v - mx);
            float ss = e;
            #pragma unroll
            for (int o = 16; o; o >>= 1) ss += __shfl_xor_sync(0xffffffffu, ss, o);
            satt[li * 32 + lane] = e / ss;
        }
    }
    __syncthreads();

    if (!DYN && DILT == 1) {
        // ---- row-centric AV (d=1): warp owns 4 li rows, lane owns 2 cols ----
        const int w = tid >> 5;
        const int li0 = w * 4;
        float2 acc[4];
        #pragma unroll
        for (int q = 0; q < 4; q++) { acc[q].x = 0.f; acc[q].y = 0.f; }
        #pragma unroll 5
        for (int rr = 0; rr < 35; rr++) {
            int row = li0 + rr;
            __half2 vh = *(const __half2*)(swin + row * 64 + lane * 2);
            float2 vf = __half22float2(vh);
            #pragma unroll
            for (int q = 0; q < 4; q++) {
                int k = rr - q;
                if (k >= 0 && k < 32) {
                    float a = satt[(li0 + q) * 32 + k];
                    acc[q].x += a * vf.x;
                    acc[q].y += a * vf.y;
                }
            }
        }
        #pragma unroll
        for (int q = 0; q < 4; q++)
            *(uint32_t*)(oa + (rowbase + li0 + q) * NV + h * 64 + lane * 2) =
                pack2(acc[q].x, acc[q].y);
    } else {
        // ---- original AV (dilated heads) ----
        const int li = tid >> 3;
        const int io = (tid & 7) * 8;
        float4 a0 = make_float4(0.f, 0.f, 0.f, 0.f);
        float4 a1 = make_float4(0.f, 0.f, 0.f, 0.f);
        #pragma unroll 8
        for (int k = 0; k < 32; k++) {
            float wv = satt[li * 32 + k];
            const __half* vr = swin + (li + k * DIL) * 64 + io;
            uint4 raw = *(const uint4*)vr;
            const __half2* hp = (const __half2*)&raw;
            float2 f0 = __half22float2(hp[0]);
            float2 f1 = __half22float2(hp[1]);
            float2 f2 = __half22float2(hp[2]);
            float2 f3 = __half22float2(hp[3]);
            a0.x += wv * f0.x; a0.y += wv * f0.y; a0.z += wv * f1.x; a0.w += wv * f1.y;
            a1.x += wv * f2.x; a1.y += wv * f2.y; a1.z += wv * f3.x; a1.w += wv * f3.y;
        }
        uint4 hv;
        hv.x = pack2(a0.x, a0.y);
        hv.y = pack2(a0.z, a0.w);
        hv.z = pack2(a1.x, a1.y);
        hv.w = pack2(a1.z, a1.w);
        *(uint4*)(oa + (rowbase + li) * NV + h * 64 + io) = hv;
    }
}

__global__ __launch_bounds__(256)
void head_d1(const __half* __restrict__ vp, const __half* __restrict__ sc,
             const float* __restrict__ Ws, const float* __restrict__ bsg,
             __half* __restrict__ oa)
{
    const int h = blockIdx.z;
    head_body<1, false>(vp, sc, Ws, bsg, oa, h, (h < 5) ? 0 : 1, 1);
}
__global__ __launch_bounds__(256)
void head_dyn(const __half* __restrict__ vp, const __half* __restrict__ sc,
              const float* __restrict__ Ws, const float* __restrict__ bsg,
              __half* __restrict__ oa)
{
    const int z = blockIdx.z;
    const int h = 10 + z;
    const int s = (h < 12) ? 2 : (h == 12 ? 3 : 4);
    const int dil = (h < 12) ? 2 : (h == 12 ? 4 : 8);
    head_body<0, true>(vp, sc, Ws, bsg, oa, h, s, dil);
}

// ---------------- launcher ---------------------------------------------------
extern "C" void kernel_launch(void* const* d_in, const int* in_sizes, int n_in,
                              void* d_out, int out_size)
{
    const float* query = (const float*)d_in[0];
    const float* key   = (const float*)d_in[1];
    const float* value = (const float*)d_in[2];
    const float* Wq    = (const float*)d_in[3];
    const float* bq    = (const float*)d_in[4];
    const float* Wk    = (const float*)d_in[5];
    const float* bk    = (const float*)d_in[6];
    const float* Wv    = (const float*)d_in[7];
    const float* bv    = (const float*)d_in[8];
    const float* Ws    = (const float*)d_in[9];
    const float* bs    = (const float*)d_in[10];
    const float* Wc    = (const float*)d_in[11];
    const float* bc    = (const float*)d_in[12];
    float* out = (float*)d_out;

    float *bqp, *bkp;
    __half *qp, *kp, *vp, *sc, *qa, *ka, *va, *oa, *wq, *wk, *wv, *wc;
    cudaGetSymbolAddress((void**)&qp, g_qp);
    cudaGetSymbolAddress((void**)&kp, g_kp);
    cudaGetSymbolAddress((void**)&vp, g_vp);
    cudaGetSymbolAddress((void**)&sc, g_sc);
    cudaGetSymbolAddress((void**)&bqp, g_bqp);
    cudaGetSymbolAddress((void**)&bkp, g_bkp);
    cudaGetSymbolAddress((void**)&qa, g_qa);
    cudaGetSymbolAddress((void**)&ka, g_ka);
    cudaGetSymbolAddress((void**)&va, g_va);
    cudaGetSymbolAddress((void**)&oa, g_oa);
    cudaGetSymbolAddress((void**)&wq, g_wq);
    cudaGetSymbolAddress((void**)&wk, g_wk);
    cudaGetSymbolAddress((void**)&wv, g_wv);
    cudaGetSymbolAddress((void**)&wc, g_wc);

    cudaFuncSetAttribute(gemm_qkv, cudaFuncAttributeMaxDynamicSharedMemorySize, GEMM_SMEM);
    cudaFuncSetAttribute(gemm_out, cudaFuncAttributeMaxDynamicSharedMemorySize, GEMM_SMEM);

    auto ssz = [](int dil) { return (size_t)((31 * dil + 32) * 64 + 2048) * 2; };
    auto hsz = [](int dil) { return (size_t)(31 * dil + 32) * 128 + (size_t)HEAD_FIXED_B; };
    cudaFuncSetAttribute(scores_all, cudaFuncAttributeMaxDynamicSharedMemorySize, (int)ssz(8));
    cudaFuncSetAttribute(head_d1,    cudaFuncAttributeMaxDynamicSharedMemorySize, (int)hsz(1));
    cudaFuncSetAttribute(head_dyn,   cudaFuncAttributeMaxDynamicSharedMemorySize, (int)hsz(8));

    // ---- conversions (one launch) ----
    conv_all<<<CONV_BLOCKS, 256>>>(
        (const float4*)query, (const float4*)key, (const float4*)value,
        (uint4*)qa, (uint4*)ka, (uint4*)va,
        Wq, Wk, Wv, Wc, bq, bk, wq, wk, wv, wc, bqp, bkp);

    // ---- fused Q/K/V projection ----
    gemm_qkv<<<dim3(13, 64), 256, GEMM_SMEM>>>(qa, ka, va, wq, wk, wv,
                                               bqp, bkp, bv, qp, kp, vp);

    // ---- per-subhead scores (one launch, all 5 subheads) ----
    scores_all<<<dim3(L_SZ / 32, B_SZ, SUBH), 256, ssz(8)>>>(qp, kp, sc);

    // ---- per-head resample + softmax + AV ----
    head_d1<<<dim3(L_SZ / 32, B_SZ, 10), 256, hsz(1)>>>(vp, sc, Ws, bs, oa);
    head_dyn<<<dim3(L_SZ / 32, B_SZ, 4), 256, hsz(8)>>>(vp, sc, Ws, bs, oa);

    // ---- output projection ----
    gemm_out<<<dim3(8, 64), 256, GEMM_SMEM>>>(oa, wc, bc, out);
}

// round 16
// speedup vs baseline: 7.5037x; 1.0341x over previous
#include <cuda_runtime.h>
#include <cuda_fp16.h>
#include <cstdint>

// Problem constants
#define B_SZ   2
#define L_SZ   4096
#define DMODEL 1024
#define DINT   64
#define KW     32
#define SUBH   5
#define HEADS  14
#define ML     (B_SZ * L_SZ)          // 8192 rows
#define NQK    320
#define NQKP   384                    // padded to 3*128
#define NV     896

// ---------------- scratch (static device globals; no allocation) -------------
__device__ __half g_qp[ML * NQKP];
__device__ __half g_kp[ML * NQKP];
__device__ __half g_vp[ML * NV];
__device__ __half g_sc[SUBH * B_SZ * L_SZ * KW];
__device__ __half g_oa[ML * NV];
__device__ __half g_wq[NQKP * DMODEL];
__device__ __half g_wk[NQKP * DMODEL];
__device__ __half g_wv[NV * DMODEL];
__device__ __half g_wc[DMODEL * NV];
__device__ float g_bqp[NQKP], g_bkp[NQKP];

// ---------------- helpers ------------------------------------------------
__device__ __forceinline__ uint32_t smem_u32(const void* p) {
    uint32_t a;
    asm("{ .reg .u64 t; cvta.to.shared.u64 t, %1; cvt.u32.u64 %0, t; }" : "=r"(a) : "l"(p));
    return a;
}
__device__ __forceinline__ void cpa16(uint32_t s, const void* g) {
    asm volatile("cp.async.cg.shared.global [%0], [%1], 16;" :: "r"(s), "l"(g));
}
#define CPA_COMMIT() asm volatile("cp.async.commit_group;" ::: "memory")
#define CPA_WAIT(n)  asm volatile("cp.async.wait_group %0;" :: "n"(n) : "memory")

#define LDSM4(r0, r1, r2, r3, a) \
    asm volatile("ldmatrix.sync.aligned.m8n8.x4.shared.b16 {%0,%1,%2,%3}, [%4];" \
        : "=r"(r0), "=r"(r1), "=r"(r2), "=r"(r3) : "r"(a))

#define MMAF16(c, a, b0, b1) \
    asm volatile("mma.sync.aligned.m16n8k16.row.col.f32.f16.f16.f32 " \
        "{%0,%1,%2,%3},{%4,%5,%6,%7},{%8,%9},{%0,%1,%2,%3};" \
        : "+f"((c)[0]), "+f"((c)[1]), "+f"((c)[2]), "+f"((c)[3]) \
        : "r"((a)[0]), "r"((a)[1]), "r"((a)[2]), "r"((a)[3]), "r"(b0), "r"(b1))

__device__ __forceinline__ uint32_t pack2(float a, float b) {
    __half2 h;
    h.x = __float2half_rn(a); h.y = __float2half_rn(b);
    return *(uint32_t*)&h;
}
#define STS128(so, h) \
    asm volatile("st.shared.v4.b32 [%0], {%1,%2,%3,%4};" \
        :: "r"(so), "r"((h).x), "r"((h).y), "r"((h).z), "r"((h).w) : "memory")

// ---------------- weight conversion kernel ------------------------------------
#define CONV_BLOCKS (2688 + 2)

__global__ __launch_bounds__(256)
void conv_w_all(const float* __restrict__ Wq, const float* __restrict__ Wk,
                const float* __restrict__ Wv, const float* __restrict__ Wc,
                const float* __restrict__ bq, const float* __restrict__ bk,
                __half* __restrict__ wq, __half* __restrict__ wk,
                __half* __restrict__ wv, __half* __restrict__ wc,
                float* __restrict__ bqp, float* __restrict__ bkp)
{
    const int wb = blockIdx.x, tid = threadIdx.x;
    if (wb >= 2688) {
        const float* src = (wb == 2688) ? bq : bk;
        float* dst = (wb == 2688) ? bqp : bkp;
        for (int i = tid; i < NQKP; i += 256) dst[i] = (i < NQK) ? src[i] : 0.f;
        return;
    }
    if (wb < 768) {
        const bool isq = (wb < 384);
        const float* W = isq ? Wq : Wk;
        __half* dst = isq ? wq : wk;
        int n = isq ? wb : (wb - 384);
        if (n >= NQK) {
            for (int kk = tid; kk < DMODEL; kk += 256) dst[(size_t)n * DMODEL + kk] = __float2half(0.f);
            return;
        }
        int head = n >> 6, i = n & 63;
        for (int kk = tid; kk < DMODEL; kk += 256)
            dst[(size_t)n * DMODEL + kk] = __float2half_rn(W[((size_t)head * DMODEL + kk) * 64 + i]);
    } else if (wb < 1664) {
        int n = wb - 768;
        int head = n >> 6, i = n & 63;
        for (int kk = tid; kk < DMODEL; kk += 256)
            wv[(size_t)n * DMODEL + kk] = __float2half_rn(Wv[((size_t)head * DMODEL + kk) * 64 + i]);
    } else {
        int n = wb - 1664;
        for (int kk = tid; kk < NV; kk += 256)
            wc[(size_t)n * NV + kk] = __float2half_rn(Wc[(size_t)kk * DMODEL + n]);
    }
}

// ---------------- fp16 HMMA GEMM, 128x128 tile, K-chunk 64 -------------------
#define APAD 72
#define A_OFF 0
#define B_OFF 9216
#define STE   18432
#define GEMM_SMEM (2 * STE * 2)

template <bool A32, bool OUT_HALF>
__device__ __forceinline__ void gemm_tile128(
    const void* __restrict__ Av, const __half* __restrict__ B,
    const float* __restrict__ bias, void* __restrict__ Cv,
    int m0, int n0, int N, int K, uint32_t sb)
{
    const int tid = threadIdx.x, lane = tid & 31, wid = tid >> 5;
    const int wm = wid >> 1, wn = wid & 1;

    float c[2][8][4];
    #pragma unroll
    for (int i = 0; i < 2; i++)
        #pragma unroll
        for (int j = 0; j < 8; j++)
            #pragma unroll
            for (int q = 0; q < 4; q++) c[i][j][q] = 0.f;

    const int ld_row0 = tid >> 3;
    const int ld_col  = (tid & 7) * 8;

    const int r = lane & 7, g = lane >> 3;
    const int a_ld_row = (g & 1) * 8 + r;
    const int a_ld_k   = (g >> 1) * 8;
    const int b_ld_row = (g >> 1) * 8 + r;
    const int b_ld_k   = (g & 1) * 8;

    const int nit = K >> 6;
    const __half* A16 = (const __half*)Av;
    const float*  Af  = (const float*)Av;

    float4 av[8];

    // ---- prologue: stage 0 ----
    if (A32) {
        #pragma unroll
        for (int i = 0; i < 4; i++) {
            int row = ld_row0 + i * 32;
            const float* ap = Af + (size_t)(m0 + row) * K + ld_col;
            av[2 * i]     = *(const float4*)ap;
            av[2 * i + 1] = *(const float4*)(ap + 4);
        }
    }
    {
        uint32_t base = sb;
        #pragma unroll
        for (int i = 0; i < 4; i++) {
            int row = ld_row0 + i * 32;
            uint32_t so = base + (uint32_t)(row * APAD + ld_col) * 2;
            if (!A32)
                cpa16(so + A_OFF * 2, A16 + (size_t)(m0 + row) * K + ld_col);
            cpa16(so + B_OFF * 2, B + (size_t)(n0 + row) * K + ld_col);
        }
        CPA_COMMIT();
    }
    if (A32) {
        #pragma unroll
        for (int i = 0; i < 4; i++) {
            int row = ld_row0 + i * 32;
            uint32_t so = sb + (uint32_t)(row * APAD + ld_col) * 2 + A_OFF * 2;
            uint4 h;
            h.x = pack2(av[2 * i].x,     av[2 * i].y);
            h.y = pack2(av[2 * i].z,     av[2 * i].w);
            h.z = pack2(av[2 * i + 1].x, av[2 * i + 1].y);
            h.w = pack2(av[2 * i + 1].z, av[2 * i + 1].w);
            STS128(so, h);
        }
    }

    for (int it = 0; it < nit; ++it) {
        if (it + 1 < nit) {
            uint32_t base = sb + (uint32_t)(((it + 1) & 1) * STE) * 2;
            int k0 = (it + 1) << 6;
            if (A32) {
                #pragma unroll
                for (int i = 0; i < 4; i++) {
                    int row = ld_row0 + i * 32;
                    const float* ap = Af + (size_t)(m0 + row) * K + k0 + ld_col;
                    av[2 * i]     = *(const float4*)ap;
                    av[2 * i + 1] = *(const float4*)(ap + 4);
                }
            }
            #pragma unroll
            for (int i = 0; i < 4; i++) {
                int row = ld_row0 + i * 32;
                uint32_t so = base + (uint32_t)(row * APAD + ld_col) * 2;
                if (!A32)
                    cpa16(so + A_OFF * 2, A16 + (size_t)(m0 + row) * K + k0 + ld_col);
                cpa16(so + B_OFF * 2, B + (size_t)(n0 + row) * K + k0 + ld_col);
            }
            CPA_COMMIT();
            CPA_WAIT(1);
        } else {
            CPA_WAIT(0);
        }
        __syncthreads();

        uint32_t base = sb + (uint32_t)((it & 1) * STE) * 2;
        #pragma unroll
        for (int kk = 0; kk < 64; kk += 16) {
            uint32_t ah[2][4];
            #pragma unroll
            for (int mt = 0; mt < 2; mt++) {
                uint32_t ad = base + (uint32_t)((wm * 32 + mt * 16 + a_ld_row) * APAD + kk + a_ld_k) * 2;
                LDSM4(ah[mt][0], ah[mt][1], ah[mt][2], ah[mt][3], ad + A_OFF * 2);
            }
            #pragma unroll
            for (int np = 0; np < 4; np++) {
                uint32_t bh[4];
                uint32_t bd = base + (uint32_t)((wn * 64 + np * 16 + b_ld_row) * APAD + kk + b_ld_k) * 2;
                LDSM4(bh[0], bh[1], bh[2], bh[3], bd + B_OFF * 2);
                #pragma unroll
                for (int mt = 0; mt < 2; mt++) {
                    MMAF16(c[mt][np * 2 + 0], ah[mt], bh[0], bh[1]);
                    MMAF16(c[mt][np * 2 + 1], ah[mt], bh[2], bh[3]);
                }
            }
        }

        if (A32 && it + 1 < nit) {
            uint32_t base2 = sb + (uint32_t)(((it + 1) & 1) * STE) * 2;
            #pragma unroll
            for (int i = 0; i < 4; i++) {
                int row = ld_row0 + i * 32;
                uint32_t so = base2 + (uint32_t)(row * APAD + ld_col) * 2 + A_OFF * 2;
                uint4 h;
                h.x = pack2(av[2 * i].x,     av[2 * i].y);
                h.y = pack2(av[2 * i].z,     av[2 * i].w);
                h.z = pack2(av[2 * i + 1].x, av[2 * i + 1].y);
                h.w = pack2(av[2 * i + 1].z, av[2 * i + 1].w);
                STS128(so, h);
            }
        }
        __syncthreads();
    }

    #pragma unroll
    for (int mt = 0; mt < 2; mt++) {
        int row = m0 + wm * 32 + mt * 16 + (lane >> 2);
        #pragma unroll
        for (int nt = 0; nt < 8; nt++) {
            int col = n0 + wn * 64 + nt * 8 + (lane & 3) * 2;
            float2 bv = *(const float2*)(bias + col);
            float x0 = c[mt][nt][0] + bv.x, y0 = c[mt][nt][1] + bv.y;
            float x1 = c[mt][nt][2] + bv.x, y1 = c[mt][nt][3] + bv.y;
            if (OUT_HALF) {
                __half* C = (__half*)Cv;
                *(uint32_t*)(C + (size_t)row * N + col) = pack2(x0, y0);
                *(uint32_t*)(C + (size_t)(row + 8) * N + col) = pack2(x1, y1);
            } else {
                float* C = (float*)Cv;
                float2 v0; v0.x = x0; v0.y = y0;
                float2 v1; v1.x = x1; v1.y = y1;
                *(float2*)(C + (size_t)row * N + col) = v0;
                *(float2*)(C + (size_t)(row + 8) * N + col) = v1;
            }
        }
    }
}

__global__ __launch_bounds__(256, 2)
void gemm_qkv(const float* __restrict__ query, const float* __restrict__ key,
              const float* __restrict__ value,
              const __half* __restrict__ wq, const __half* __restrict__ wk,
              const __half* __restrict__ wv,
              const float* __restrict__ bqp, const float* __restrict__ bkp, const float* __restrict__ bv,
              __half* __restrict__ qp, __half* __restrict__ kp, __half* __restrict__ vp)
{
    extern __shared__ __half sm[];
    uint32_t sb = smem_u32(sm);
    const int m0 = blockIdx.y * 128;
    const int rr = blockIdx.x;
    if (rr < 3)
        gemm_tile128<true, true>(query, wq, bqp, qp, m0, rr * 128, NQKP, DMODEL, sb);
    else if (rr < 6)
        gemm_tile128<true, true>(key, wk, bkp, kp, m0, (rr - 3) * 128, NQKP, DMODEL, sb);
    else
        gemm_tile128<true, true>(value, wv, bv, vp, m0, (rr - 6) * 128, NV, DMODEL, sb);
}

__global__ __launch_bounds__(256, 2)
void gemm_out(const __half* __restrict__ A, const __half* __restrict__ B,
              const float* __restrict__ bias, float* __restrict__ C)
{
    extern __shared__ __half sm[];
    uint32_t sb = smem_u32(sm);
    gemm_tile128<false, false>(A, B, bias, C, blockIdx.y * 128, blockIdx.x * 128, DMODEL, NV, sb);
}

// ---------------- scores: merged all-subhead launch ---------------------------
template <int DILT, bool DYN>
__device__ __forceinline__ void scores_body(
    const __half* __restrict__ qp, const __half* __restrict__ kp,
    __half* __restrict__ sc, int s, int dil_rt)
{
    const int DIL = DYN ? dil_rt : DILT;
    const int WIN = 31 * DIL + 32;
    extern __shared__ __half sh[];
    __half* swin = sh;
    __half* sq   = swin + WIN * 64;

    const int l0 = blockIdx.x * 32;
    const int b  = blockIdx.y;
    const int tid = threadIdx.x, lane = tid & 31;
    const int w0 = l0 - 16 * DIL;
    const long rowbase = (long)b * L_SZ + l0;
    const int c8 = (tid & 7) * 8;

    {
        int row = tid >> 3;
        *(uint4*)(sq + row * 64 + c8) =
            *(const uint4*)(qp + (rowbase + row) * NQKP + s * 64 + c8);
    }
    for (int r = tid >> 3; r < WIN; r += 32) {
        int g = w0 + r; g = g < 0 ? 0 : (g > L_SZ - 1 ? L_SZ - 1 : g);
        *(uint4*)(swin + r * 64 + c8) =
            *(const uint4*)(kp + ((long)b * L_SZ + g) * NQKP + s * 64 + c8);
    }
    __syncthreads();

    {
        const int li = tid >> 3;
        const int kb = (tid & 7) * 4;
        float acc0 = 0.f, acc1 = 0.f, acc2 = 0.f, acc3 = 0.f;
        const __half* qrow = sq + li * 64;
        const __half* wr0 = swin + (li + (kb + 0) * DIL) * 64;
        const __half* wr1 = swin + (li + (kb + 1) * DIL) * 64;
        const __half* wr2 = swin + (li + (kb + 2) * DIL) * 64;
        const __half* wr3 = swin + (li + (kb + 3) * DIL) * 64;
        #pragma unroll
        for (int t8 = 0; t8 < 8; t8++) {
            int i = ((t8 + lane) & 7) * 8;
            uint4 qr = *(const uint4*)(qrow + i);
            uint4 r0 = *(const uint4*)(wr0 + i);
            uint4 r1 = *(const uint4*)(wr1 + i);
            uint4 r2 = *(const uint4*)(wr2 + i);
            uint4 r3 = *(const uint4*)(wr3 + i);
            const __half2* qh = (const __half2*)&qr;
            const __half2* h0 = (const __half2*)&r0;
            const __half2* h1 = (const __half2*)&r1;
            const __half2* h2 = (const __half2*)&r2;
            const __half2* h3 = (const __half2*)&r3;
            #pragma unroll
            for (int u = 0; u < 4; u++) {
                float2 qf = __half22float2(qh[u]);
                float2 f0 = __half22float2(h0[u]);
                float2 f1 = __half22float2(h1[u]);
                float2 f2 = __half22float2(h2[u]);
                float2 f3 = __half22float2(h3[u]);
                acc0 += qf.x * f0.x + qf.y * f0.y;
                acc1 += qf.x * f1.x + qf.y * f1.y;
                acc2 += qf.x * f2.x + qf.y * f2.y;
                acc3 += qf.x * f3.x + qf.y * f3.y;
            }
        }
        uint2 o;
        o.x = pack2(acc0 * 0.125f, acc1 * 0.125f);
        o.y = pack2(acc2 * 0.125f, acc3 * 0.125f);
        *(uint2*)(sc + (((size_t)s * B_SZ + b) * L_SZ + l0 + li) * KW + kb) = o;
    }
}

__global__ __launch_bounds__(256)
void scores_all(const __half* __restrict__ qp, const __half* __restrict__ kp, __half* __restrict__ sc)
{
    const int z = blockIdx.z;
    if (z < 2) {
        scores_body<1, false>(qp, kp, sc, z, 1);
    } else {
        const int dil = (z == 2) ? 2 : (z == 3 ? 4 : 8);
        scores_body<0, true>(qp, kp, sc, z, dil);
    }
}

// ---------------- head kernel: resample + softmax + AV ------------------------
#define HEAD_FIXED_B (1024 * 2 + (1152 + 1056 + 1024 + 32) * 4)

template <int DILT, bool DYN>
__device__ __forceinline__ void head_body(
    const __half* __restrict__ vp, const __half* __restrict__ sc_g,
    const float* __restrict__ Ws, const float* __restrict__ bsg,
    __half* __restrict__ oa, int h, int s, int dil_rt)
{
    const int DIL = DYN ? dil_rt : DILT;
    const int WIN = 31 * DIL + 32;
    extern __shared__ char sab[];
    __half* swin  = (__half*)sab;
    __half* sws_h = (__half*)(sab + (size_t)WIN * 128);
    float* ssc  = (float*)(sws_h + 1024);
    float* ssm  = ssc + 1152;
    float* satt = ssm + 1056;
    float* sbs  = satt + 1024;

    const int l0 = blockIdx.x * 32;
    const int b  = blockIdx.y;
    const int tid = threadIdx.x, lane = tid & 31;
    const int w0 = l0 - 16 * DIL;
    const long rowbase = (long)b * L_SZ + l0;

    {
        float4 wv4 = *(const float4*)(Ws + (size_t)h * 1024 + tid * 4);
        uint2 wp;
        wp.x = pack2(wv4.x, wv4.y);
        wp.y = pack2(wv4.z, wv4.w);
        *(uint2*)(sws_h + tid * 4) = wp;
    }
    if (tid < 32) sbs[tid] = bsg[h * KW + tid];
    {
        int li = tid >> 3, kb = (tid & 7) * 4;
        uint2 raw = *(const uint2*)(sc_g + (((size_t)s * B_SZ + b) * L_SZ + l0 + li) * KW + kb);
        float2 f0 = __half22float2(*(__half2*)&raw.x);
        float2 f1 = __half22float2(*(__half2*)&raw.y);
        ssc[li * 36 + kb + 0] = f0.x;
        ssc[li * 36 + kb + 1] = f0.y;
        ssc[li * 36 + kb + 2] = f1.x;
        ssc[li * 36 + kb + 3] = f1.y;
    }
    for (int r = tid >> 3; r < WIN; r += 32) {
        int g = w0 + r; g = g < 0 ? 0 : (g > L_SZ - 1 ? L_SZ - 1 : g);
        int c8 = (tid & 7) * 8;
        *(uint4*)(swin + r * 64 + c8) =
            *(const uint4*)(vp + ((long)b * L_SZ + g) * NV + h * 64 + c8);
    }
    __syncthreads();

    {
        const int li = tid >> 3;
        const int m4 = (tid & 7) * 4;
        float a0 = sbs[m4], a1 = sbs[m4 + 1], a2 = sbs[m4 + 2], a3 = sbs[m4 + 3];
        #pragma unroll 8
        for (int k = 0; k < 32; k++) {
            float scv = ssc[li * 36 + k];
            uint2 raw = *(const uint2*)(sws_h + k * 32 + m4);
            float2 w0f = __half22float2(*(__half2*)&raw.x);
            float2 w1f = __half22float2(*(__half2*)&raw.y);
            a0 += scv * w0f.x; a1 += scv * w0f.y; a2 += scv * w1f.x; a3 += scv * w1f.y;
        }
        ssm[li * 33 + m4 + 0] = a0;
        ssm[li * 33 + m4 + 1] = a1;
        ssm[li * 33 + m4 + 2] = a2;
        ssm[li * 33 + m4 + 3] = a3;
    }
    __syncthreads();

    {
        const int w = tid >> 5;
        #pragma unroll
        for (int rr = 0; rr < 4; rr++) {
            int li = w * 4 + rr;
            float v = ssm[li * 33 + lane];
            float mx = v;
            #pragma unroll
            for (int o = 16; o; o >>= 1) mx = fmaxf(mx, __shfl_xor_sync(0xffffffffu, mx, o));
            float e = __expf(v - mx);
            float ss = e;
            #pragma unroll
            for (int o = 16; o; o >>= 1) ss += __shfl_xor_sync(0xffffffffu, ss, o);
            satt[li * 32 + lane] = e / ss;
        }
    }
    __syncthreads();

    if (!DYN && DILT == 1) {
        const int w = tid >> 5;
        const int li0 = w * 4;
        float2 acc[4];
        #pragma unroll
        for (int q = 0; q < 4; q++) { acc[q].x = 0.f; acc[q].y = 0.f; }
        #pragma unroll
        for (int rr = 0; rr < 35; rr++) {
            int row = li0 + rr;
            __half2 vh = *(const __half2*)(swin + row * 64 + lane * 2);
            float2 vf = __half22float2(vh);
            #pragma unroll
            for (int q = 0; q < 4; q++) {
                int k = rr - q;
                if (k >= 0 && k < 32) {
                    float a = satt[(li0 + q) * 32 + k];
                    acc[q].x += a * vf.x;
                    acc[q].y += a * vf.y;
                }
            }
        }
        #pragma unroll
        for (int q = 0; q < 4; q++)
            *(uint32_t*)(oa + (rowbase + li0 + q) * NV + h * 64 + lane * 2) =
                pack2(acc[q].x, acc[q].y);
    } else {
        const int li = tid >> 3;
        const int io = (tid & 7) * 8;
        float4 a0 = make_float4(0.f, 0.f, 0.f, 0.f);
        float4 a1 = make_float4(0.f, 0.f, 0.f, 0.f);
        #pragma unroll 8
        for (int k = 0; k < 32; k++) {
            float wv = satt[li * 32 + k];
            const __half* vr = swin + (li + k * DIL) * 64 + io;
            uint4 raw = *(const uint4*)vr;
            const __half2* hp = (const __half2*)&raw;
            float2 f0 = __half22float2(hp[0]);
            float2 f1 = __half22float2(hp[1]);
            float2 f2 = __half22float2(hp[2]);
            float2 f3 = __half22float2(hp[3]);
            a0.x += wv * f0.x; a0.y += wv * f0.y; a0.z += wv * f1.x; a0.w += wv * f1.y;
            a1.x += wv * f2.x; a1.y += wv * f2.y; a1.z += wv * f3.x; a1.w += wv * f3.y;
        }
        uint4 hv;
        hv.x = pack2(a0.x, a0.y);
        hv.y = pack2(a0.z, a0.w);
        hv.z = pack2(a1.x, a1.y);
        hv.w = pack2(a1.z, a1.w);
        *(uint4*)(oa + (rowbase + li) * NV + h * 64 + io) = hv;
    }
}

__global__ __launch_bounds__(256)
void head_d1(const __half* __restrict__ vp, const __half* __restrict__ sc,
             const float* __restrict__ Ws, const float* __restrict__ bsg,
             __half* __restrict__ oa)
{
    const int h = blockIdx.z;
    head_body<1, false>(vp, sc, Ws, bsg, oa, h, (h < 5) ? 0 : 1, 1);
}
__global__ __launch_bounds__(256)
void head_dyn(const __half* __restrict__ vp, const __half* __restrict__ sc,
              const float* __restrict__ Ws, const float* __restrict__ bsg,
              __half* __restrict__ oa)
{
    const int z = blockIdx.z;
    const int h = 10 + z;
    const int s = (h < 12) ? 2 : (h == 12 ? 3 : 4);
    const int dil = (h < 12) ? 2 : (h == 12 ? 4 : 8);
    head_body<0, true>(vp, sc, Ws, bsg, oa, h, s, dil);
}

// ---------------- launcher ---------------------------------------------------
extern "C" void kernel_launch(void* const* d_in, const int* in_sizes, int n_in,
                              void* d_out, int out_size)
{
    const float* query = (const float*)d_in[0];
    const float* key   = (const float*)d_in[1];
    const float* value = (const float*)d_in[2];
    const float* Wq    = (const float*)d_in[3];
    const float* bq    = (const float*)d_in[4];
    const float* Wk    = (const float*)d_in[5];
    const float* bk    = (const float*)d_in[6];
    const float* Wv    = (const float*)d_in[7];
    const float* bv    = (const float*)d_in[8];
    const float* Ws    = (const float*)d_in[9];
    const float* bs    = (const float*)d_in[10];
    const float* Wc    = (const float*)d_in[11];
    const float* bc    = (const float*)d_in[12];
    float* out = (float*)d_out;

    float *bqp, *bkp;
    __half *qp, *kp, *vp, *sc, *oa, *wq, *wk, *wv, *wc;
    cudaGetSymbolAddress((void**)&qp, g_qp);
    cudaGetSymbolAddress((void**)&kp, g_kp);
    cudaGetSymbolAddress((void**)&vp, g_vp);
    cudaGetSymbolAddress((void**)&sc, g_sc);
    cudaGetSymbolAddress((void**)&bqp, g_bqp);
    cudaGetSymbolAddress((void**)&bkp, g_bkp);
    cudaGetSymbolAddress((void**)&oa, g_oa);
    cudaGetSymbolAddress((void**)&wq, g_wq);
    cudaGetSymbolAddress((void**)&wk, g_wk);
    cudaGetSymbolAddress((void**)&wv, g_wv);
    cudaGetSymbolAddress((void**)&wc, g_wc);

    cudaFuncSetAttribute(gemm_qkv, cudaFuncAttributeMaxDynamicSharedMemorySize, GEMM_SMEM);
    cudaFuncSetAttribute(gemm_out, cudaFuncAttributeMaxDynamicSharedMemorySize, GEMM_SMEM);

    auto ssz = [](int dil) { return (size_t)((31 * dil + 32) * 64 + 2048) * 2; };
    auto hsz = [](int dil) { return (size_t)(31 * dil + 32) * 128 + (size_t)HEAD_FIXED_B; };
    cudaFuncSetAttribute(scores_all, cudaFuncAttributeMaxDynamicSharedMemorySize, (int)ssz(8));
    cudaFuncSetAttribute(head_d1,    cudaFuncAttributeMaxDynamicSharedMemorySize, (int)hsz(1));
    cudaFuncSetAttribute(head_dyn,   cudaFuncAttributeMaxDynamicSharedMemorySize, (int)hsz(8));

    // ---- weight conversions only (activation conversion fused into GEMM) ----
    conv_w_all<<<CONV_BLOCKS, 256>>>(Wq, Wk, Wv, Wc, bq, bk, wq, wk, wv, wc, bqp, bkp);

    // ---- fused Q/K/V projection (reads fp32 activations directly) ----
    gemm_qkv<<<dim3(13, 64), 256, GEMM_SMEM>>>(query, key, value, wq, wk, wv,
                                               bqp, bkp, bv, qp, kp, vp);

    // ---- per-subhead scores ----
    scores_all<<<dim3(L_SZ / 32, B_SZ, SUBH), 256, ssz(8)>>>(qp, kp, sc);

    // ---- per-head resample + softmax + AV ----
    head_d1<<<dim3(L_SZ / 32, B_SZ, 10), 256, hsz(1)>>>(vp, sc, Ws, bs, oa);
    head_dyn<<<dim3(L_SZ / 32, B_SZ, 4), 256, hsz(8)>>>(vp, sc, Ws, bs, oa);

    // ---- output projection ----
    gemm_out<<<dim3(8, 64), 256, GEMM_SMEM>>>(oa, wc, bc, out);
}